// round 13
// baseline (speedup 1.0000x reference)
#include <cuda_runtime.h>
#include <cuda_bf16.h>
#include <cstdint>
#include <math.h>

#define BATCH 8
#define LSEQ  1024
#define DIM   512
#define DI    1024
#define DS    16
#define HID   1024
#define ROWS  (BATCH*LSEQ)    // 8192
#define NCHUNK 32
#define CLEN   32
#define NCH    16384
#define XPLANE ((size_t)2*ROWS*DI)          // xc hi/lo plane stride
#define XZPLANE ((size_t)ROWS*4096)         // xz hi/lo plane stride
#define DSPLANE ((size_t)2*ROWS*DI)         // dsp hi/lo plane stride

typedef __nv_bfloat16 bf16;

// ---------------- fp32 scratch ----------------
__device__ float g_pos    [LSEQ*DIM];
__device__ float g_pos_mix[LSEQ*DIM];
__device__ float g_proj   [2*ROWS*64];
__device__ float g_dmix   [ROWS*DIM];
__device__ float g_dln    [ROWS*DIM];
__device__ float g_hend [NCHUNK*NCH*DS];
__device__ float g_prod [NCHUNK*NCH*DS];
__device__ float g_hinit[NCHUNK*NCH*DS];

// ---------------- bf16 hi/lo scratch ----------------
__device__ __align__(16) bf16 hl_scan_in[2*ROWS*DIM];
__device__ __align__(16) bf16 hl_pos_h  [2*LSEQ*DIM];
__device__ __align__(16) bf16 hl_pos    [2*LSEQ*DIM];
__device__ __align__(16) bf16 hl_w_pos2 [2*DIM*DIM];
__device__ __align__(16) bf16 hl_w_pmix [2*DIM*DIM];
__device__ __align__(16) bf16 hl_w_mixA [2*2*DIM*DIM];
__device__ __align__(16) bf16 hl_wT_out [2*2*DI*DIM];
__device__ __align__(16) bf16 hl_w_in   [2*4096*DIM];
__device__ __align__(16) bf16 hl_w_xp   [2*2*64*DI];
__device__ __align__(16) bf16 hl_w_dt   [2*2*DI*32];
__device__ __align__(16) bf16 hl_w_f1   [2*HID*DIM];
__device__ __align__(16) bf16 hl_w_f2   [2*DIM*HID];
__device__ __align__(16) bf16 hl_xz     [2*ROWS*4096];
__device__ __align__(16) bf16 hl_dsp    [2*2*ROWS*DI];
__device__ __align__(16) bf16 hl_xc     [2*2*ROWS*DI];
__device__ __align__(16) bf16 hl_proj   [2*2*ROWS*64];
__device__ __align__(16) bf16 hl_ycat   [2*ROWS*2048];
__device__ __align__(16) bf16 hl_wc     [2*DIM*2048];
__device__ __align__(16) bf16 hl_lnf    [2*ROWS*DIM];
__device__ __align__(16) bf16 hl_h1     [2*ROWS*HID];

// ---------------- math helpers ----------------
__device__ __forceinline__ float geluf(float x) {
    return 0.5f * x * (1.0f + erff(x * 0.70710678118654752440f));
}
__device__ __forceinline__ float siluf(float x) { return x / (1.0f + __expf(-x)); }
__device__ __forceinline__ float softplusf(float x) { return (x > 20.0f) ? x : log1pf(__expf(x)); }
__device__ __forceinline__ void splitf(float v, bf16& h, bf16& l) {
    h = __float2bfloat16(v);
    l = __float2bfloat16(v - __bfloat162float(h));
}
__device__ __forceinline__ float fcomp(float4 f, int k) {
    return k == 0 ? f.x : (k == 1 ? f.y : (k == 2 ? f.z : f.w));
}
__device__ __forceinline__ void split4_store(bf16* ph, bf16* pl, float4 v) {
    bf16 h0, l0, h1, l1, h2, l2, h3, l3;
    splitf(v.x, h0, l0); splitf(v.y, h1, l1);
    splitf(v.z, h2, l2); splitf(v.w, h3, l3);
    __nv_bfloat162 a; a.x = h0; a.y = h1;
    __nv_bfloat162 b; b.x = h2; b.y = h3;
    __nv_bfloat162 c; c.x = l0; c.y = l1;
    __nv_bfloat162 d; d.x = l2; d.y = l3;
    *(__nv_bfloat162*)ph = a; *(__nv_bfloat162*)(ph + 2) = b;
    *(__nv_bfloat162*)pl = c; *(__nv_bfloat162*)(pl + 2) = d;
}
__device__ __forceinline__ float hlval(const bf16* p, size_t plane, size_t i) {
    return __bfloat162float(p[i]) + __bfloat162float(p[plane + i]);
}
// reconstruct 4 consecutive values from hi/lo planes (vectorized 8B loads)
__device__ __forceinline__ float4 hl4(const bf16* p, size_t plane, size_t i) {
    __nv_bfloat162 h0 = *(const __nv_bfloat162*)(p + i);
    __nv_bfloat162 h1 = *(const __nv_bfloat162*)(p + i + 2);
    __nv_bfloat162 l0 = *(const __nv_bfloat162*)(p + plane + i);
    __nv_bfloat162 l1 = *(const __nv_bfloat162*)(p + plane + i + 2);
    float4 r;
    r.x = __bfloat162float(h0.x) + __bfloat162float(l0.x);
    r.y = __bfloat162float(h0.y) + __bfloat162float(l0.y);
    r.z = __bfloat162float(h1.x) + __bfloat162float(l1.x);
    r.w = __bfloat162float(h1.y) + __bfloat162float(l1.y);
    return r;
}

// ---------------- PTX helpers ----------------
__device__ __forceinline__ void mma16816(float* d, const uint32_t* a, uint32_t b0, uint32_t b1) {
    asm volatile(
        "mma.sync.aligned.m16n8k16.row.col.f32.bf16.bf16.f32 "
        "{%0,%1,%2,%3},{%4,%5,%6,%7},{%8,%9},{%0,%1,%2,%3};\n"
        : "+f"(d[0]), "+f"(d[1]), "+f"(d[2]), "+f"(d[3])
        : "r"(a[0]), "r"(a[1]), "r"(a[2]), "r"(a[3]), "r"(b0), "r"(b1));
}
__device__ __forceinline__ void ldsm4(uint32_t* r, uint32_t addr) {
    asm volatile("ldmatrix.sync.aligned.m8n8.x4.shared.b16 {%0,%1,%2,%3}, [%4];\n"
                 : "=r"(r[0]), "=r"(r[1]), "=r"(r[2]), "=r"(r[3]) : "r"(addr));
}
__device__ __forceinline__ void cp16(uint32_t dst, const void* src, bool pred) {
    int sz = pred ? 16 : 0;
    asm volatile("cp.async.cg.shared.global [%0], [%1], 16, %2;\n"
                 :: "r"(dst), "l"(src), "r"(sz) : "memory");
}
__device__ __forceinline__ void cp_commit() { asm volatile("cp.async.commit_group;\n" ::: "memory"); }
__device__ __forceinline__ void cp_wait1()  { asm volatile("cp.async.wait_group 1;\n" ::: "memory"); }

// ---------------- mma.sync GEMM 128x128 ----------------
#define BK_STAGES 3
#define SMEM_BYTES (BK_STAGES*32768)

template<int EPI, int OUT>
__global__ void __launch_bounds__(256, 2)
bgemm(const bf16* __restrict__ Ah, const bf16* __restrict__ Al, int lda, long long sA,
      const bf16* __restrict__ Bh, const bf16* __restrict__ Bl, int ldb, long long sB,
      float* __restrict__ C, int ldc, long long sC,
      bf16* __restrict__ Ch, long long planeC, int ldch, long long sCh,
      const float* __restrict__ bias, long long sBias,
      const float* __restrict__ aux, int auxMod,
      int M, int N, int K)
{
    extern __shared__ char smd[];
    const int zi = blockIdx.z;
    Ah += (size_t)zi * sA; Al += (size_t)zi * sA;
    Bh += (size_t)zi * sB; Bl += (size_t)zi * sB;
    if (OUT != 2) C += (size_t)zi * sC;
    if (OUT != 0) Ch += (size_t)zi * sCh;
    const float* bp = bias ? (bias + (size_t)zi * sBias) : nullptr;

    const int bm = blockIdx.y * 128;
    const int bn = blockIdx.x * 128;
    const int tid = threadIdx.x, lane = tid & 31, warp = tid >> 5;
    const int wm = warp & 1, wn = warp >> 1;

    const uint32_t smem_base = (uint32_t)__cvta_generic_to_shared(smd);

    auto load_stage = [&](int s, int kt) {
        const int k0 = kt * 32;
        const uint32_t As = smem_base + s * 32768;
        const uint32_t Bs = As + 16384;
#pragma unroll
        for (int i = 0; i < 4; i++) {
            int lin = i * 256 + tid;
            int row = lin >> 3, ch = lin & 7;
            const bf16* srcA = ((ch & 4) ? Al : Ah) + (size_t)(bm + row) * lda + k0 + (ch & 3) * 8;
            cp16(As + row * 128 + ((ch ^ (row & 7)) * 16), srcA, true);
        }
#pragma unroll
        for (int i = 0; i < 4; i++) {
            int lin = i * 256 + tid;
            int row = lin >> 3, ch = lin & 7;
            bool ok = (bn + row) < N;
            const bf16* srcB = ((ch & 4) ? Bl : Bh) +
                               (ok ? ((size_t)(bn + row) * ldb + k0 + (ch & 3) * 8) : 0);
            cp16(Bs + row * 128 + ((ch ^ (row & 7)) * 16), srcB, ok);
        }
    };

    float acc[4][4][4];
#pragma unroll
    for (int i = 0; i < 4; i++)
#pragma unroll
        for (int j = 0; j < 4; j++)
#pragma unroll
            for (int q = 0; q < 4; q++) acc[i][j][q] = 0.0f;

    const int nk = K / 32;
    if (nk > 0) load_stage(0, 0);
    cp_commit();
    if (nk > 1) load_stage(1, 1);
    cp_commit();

    const int g  = lane >> 3;
    const int lr = lane & 7;
    const int aRow0 = wm * 64 + (g & 1) * 8 + lr;
    const int bRow0 = wn * 32 + (g & 1) * 8 + lr;
    const int chHi  = (g >> 1);

    for (int kt = 0; kt < nk; kt++) {
        cp_wait1();
        __syncthreads();
        const uint32_t As = smem_base + (kt % BK_STAGES) * 32768;
        const uint32_t Bs = As + 16384;

#pragma unroll
        for (int step = 0; step < 2; step++) {
            uint32_t ah[4][4], al[4][4], bh[2][4], bl[2][4];
            const int cH = ((step * 2 + chHi) ^ lr) * 16;
            const int cL = ((4 + step * 2 + chHi) ^ lr) * 16;
#pragma unroll
            for (int mt = 0; mt < 4; mt++) {
                uint32_t rb = As + (uint32_t)(aRow0 + mt * 16) * 128;
                ldsm4(ah[mt], rb + cH);
                ldsm4(al[mt], rb + cL);
            }
#pragma unroll
            for (int p = 0; p < 2; p++) {
                uint32_t rb = Bs + (uint32_t)(bRow0 + p * 16) * 128;
                ldsm4(bh[p], rb + cH);
                ldsm4(bl[p], rb + cL);
            }
#pragma unroll
            for (int nt = 0; nt < 4; nt++) {
                const int p = nt >> 1, o = nt & 1;
                const uint32_t b0h = bh[p][o], b1h = bh[p][o + 2];
                const uint32_t b0l = bl[p][o], b1l = bl[p][o + 2];
#pragma unroll
                for (int mt = 0; mt < 4; mt++) {
                    mma16816(acc[mt][nt], ah[mt], b0h, b1h);
                    mma16816(acc[mt][nt], ah[mt], b0l, b1l);
                    mma16816(acc[mt][nt], al[mt], b0h, b1h);
                }
            }
        }
        __syncthreads();
        if (kt + 2 < nk) load_stage((kt + 2) % BK_STAGES, kt + 2);
        cp_commit();
    }

    const int r_ep = lane >> 2, c_ep = lane & 3;
#pragma unroll
    for (int mt = 0; mt < 4; mt++) {
        const int m0 = bm + wm * 64 + mt * 16 + r_ep;
#pragma unroll
        for (int nt = 0; nt < 4; nt++) {
            const int n0 = bn + wn * 32 + nt * 8 + 2 * c_ep;
#pragma unroll
            for (int half = 0; half < 2; half++) {
                const int m = m0 + half * 8;
#pragma unroll
                for (int q = 0; q < 2; q++) {
                    const int n = n0 + q;
                    if (n < N) {
                        float v = acc[mt][nt][half * 2 + q];
                        if (bp) v += bp[n];
                        if (EPI == 1)      v = geluf(v);
                        else if (EPI == 3) v = softplusf(v);
                        else if (EPI == 4) v += aux[(size_t)(m % auxMod) * ldc + n];
                        else if (EPI == 5) v += aux[(size_t)m * ldc + n];
                        if (OUT != 2) C[(size_t)m * ldc + n] = v;
                        if (OUT != 0) {
                            bf16 h, l; splitf(v, h, l);
                            size_t o = (size_t)m * ldch + n;
                            Ch[o] = h; Ch[planeC + o] = l;
                        }
                    }
                }
            }
        }
    }
}

// ---------------- mma.sync GEMM 64x128 (small shapes) ----------------
#define SMEM64_BYTES (3*24576)

template<int EPI, int OUT>
__global__ void __launch_bounds__(256, 2)
bgemm64(const bf16* __restrict__ Ah, const bf16* __restrict__ Al, int lda, long long sA,
        const bf16* __restrict__ Bh, const bf16* __restrict__ Bl, int ldb, long long sB,
        float* __restrict__ C, int ldc, long long sC,
        bf16* __restrict__ Ch, long long planeC, int ldch, long long sCh,
        const float* __restrict__ bias, long long sBias,
        const float* __restrict__ aux, int auxMod,
        int M, int N, int K)
{
    extern __shared__ char smd[];
    const int zi = blockIdx.z;
    Ah += (size_t)zi * sA; Al += (size_t)zi * sA;
    Bh += (size_t)zi * sB; Bl += (size_t)zi * sB;
    if (OUT != 2) C += (size_t)zi * sC;
    if (OUT != 0) Ch += (size_t)zi * sCh;
    const float* bp = bias ? (bias + (size_t)zi * sBias) : nullptr;

    const int bm = blockIdx.y * 64;
    const int bn = blockIdx.x * 128;
    const int tid = threadIdx.x, lane = tid & 31, warp = tid >> 5;
    const int wm = warp & 1, wn = warp >> 1;

    const uint32_t smem_base = (uint32_t)__cvta_generic_to_shared(smd);

    auto load_stage = [&](int s, int kt) {
        const int k0 = kt * 32;
        const uint32_t As = smem_base + s * 24576;
        const uint32_t Bs = As + 8192;
#pragma unroll
        for (int i = 0; i < 2; i++) {
            int lin = i * 256 + tid;
            int row = lin >> 3, ch = lin & 7;
            const bf16* srcA = ((ch & 4) ? Al : Ah) + (size_t)(bm + row) * lda + k0 + (ch & 3) * 8;
            cp16(As + row * 128 + ((ch ^ (row & 7)) * 16), srcA, true);
        }
#pragma unroll
        for (int i = 0; i < 4; i++) {
            int lin = i * 256 + tid;
            int row = lin >> 3, ch = lin & 7;
            bool ok = (bn + row) < N;
            const bf16* srcB = ((ch & 4) ? Bl : Bh) +
                               (ok ? ((size_t)(bn + row) * ldb + k0 + (ch & 3) * 8) : 0);
            cp16(Bs + row * 128 + ((ch ^ (row & 7)) * 16), srcB, ok);
        }
    };

    float acc[2][4][4];
#pragma unroll
    for (int i = 0; i < 2; i++)
#pragma unroll
        for (int j = 0; j < 4; j++)
#pragma unroll
            for (int q = 0; q < 4; q++) acc[i][j][q] = 0.0f;

    const int nk = K / 32;
    if (nk > 0) load_stage(0, 0);
    cp_commit();
    if (nk > 1) load_stage(1, 1);
    cp_commit();

    const int g  = lane >> 3;
    const int lr = lane & 7;
    const int aRow0 = wm * 32 + (g & 1) * 8 + lr;
    const int bRow0 = wn * 32 + (g & 1) * 8 + lr;
    const int chHi  = (g >> 1);

    for (int kt = 0; kt < nk; kt++) {
        cp_wait1();
        __syncthreads();
        const uint32_t As = smem_base + (kt % 3) * 24576;
        const uint32_t Bs = As + 8192;

#pragma unroll
        for (int step = 0; step < 2; step++) {
            uint32_t ah[2][4], al[2][4], bh[2][4], bl[2][4];
            const int cH = ((step * 2 + chHi) ^ lr) * 16;
            const int cL = ((4 + step * 2 + chHi) ^ lr) * 16;
#pragma unroll
            for (int mt = 0; mt < 2; mt++) {
                uint32_t rb = As + (uint32_t)(aRow0 + mt * 16) * 128;
                ldsm4(ah[mt], rb + cH);
                ldsm4(al[mt], rb + cL);
            }
#pragma unroll
            for (int p = 0; p < 2; p++) {
                uint32_t rb = Bs + (uint32_t)(bRow0 + p * 16) * 128;
                ldsm4(bh[p], rb + cH);
                ldsm4(bl[p], rb + cL);
            }
#pragma unroll
            for (int nt = 0; nt < 4; nt++) {
                const int p = nt >> 1, o = nt & 1;
                const uint32_t b0h = bh[p][o], b1h = bh[p][o + 2];
                const uint32_t b0l = bl[p][o], b1l = bl[p][o + 2];
#pragma unroll
                for (int mt = 0; mt < 2; mt++) {
                    mma16816(acc[mt][nt], ah[mt], b0h, b1h);
                    mma16816(acc[mt][nt], ah[mt], b0l, b1l);
                    mma16816(acc[mt][nt], al[mt], b0h, b1h);
                }
            }
        }
        __syncthreads();
        if (kt + 2 < nk) load_stage((kt + 2) % 3, kt + 2);
        cp_commit();
    }

    const int r_ep = lane >> 2, c_ep = lane & 3;
#pragma unroll
    for (int mt = 0; mt < 2; mt++) {
        const int m0 = bm + wm * 32 + mt * 16 + r_ep;
#pragma unroll
        for (int nt = 0; nt < 4; nt++) {
            const int n0 = bn + wn * 32 + nt * 8 + 2 * c_ep;
#pragma unroll
            for (int half = 0; half < 2; half++) {
                const int m = m0 + half * 8;
#pragma unroll
                for (int q = 0; q < 2; q++) {
                    const int n = n0 + q;
                    if (n < N) {
                        float v = acc[mt][nt][half * 2 + q];
                        if (bp) v += bp[n];
                        if (EPI == 1)      v = geluf(v);
                        else if (EPI == 3) v = softplusf(v);
                        else if (EPI == 4) v += aux[(size_t)(m % auxMod) * ldc + n];
                        else if (EPI == 5) v += aux[(size_t)m * ldc + n];
                        if (OUT != 2) C[(size_t)m * ldc + n] = v;
                        if (OUT != 0) {
                            bf16 h, l; splitf(v, h, l);
                            size_t o = (size_t)m * ldch + n;
                            Ch[o] = h; Ch[planeC + o] = l;
                        }
                    }
                }
            }
        }
    }
}

// ---------------- fused prepass ----------------
#define PRE_BLOCKS 23296

__global__ void fused_pre_k(
    const float* __restrict__ pos_w1, const float* __restrict__ pos_b1,
    const float* __restrict__ pos_w2, const float* __restrict__ mix_w,
    const float* __restrict__ m_out_w, const float* __restrict__ m_in_w,
    const float* __restrict__ m_xproj_w, const float* __restrict__ m_dt_w,
    const float* __restrict__ ffn_w1, const float* __restrict__ ffn_w2,
    bf16* __restrict__ wpos2, bf16* __restrict__ wpmix, bf16* __restrict__ wmixA,
    bf16* __restrict__ wTout, bf16* __restrict__ win, bf16* __restrict__ wxp,
    bf16* __restrict__ wdt, bf16* __restrict__ wf1, bf16* __restrict__ wf2,
    bf16* __restrict__ posh)
{
    const int bid = blockIdx.x, tid = threadIdx.x;
    bf16 h, l;
    if (bid < 1024) {
        int i = bid * 256 + tid;
        splitf(pos_w2[i], h, l); wpos2[i] = h; wpos2[262144 + i] = l;
    } else if (bid < 2048) {
        int i = (bid - 1024) * 256 + tid;
        int r = i >> 9, c = i & 511;
        splitf(mix_w[1024 + r * 1536 + c], h, l); wpmix[i] = h; wpmix[262144 + i] = l;
    } else if (bid < 3072) {
        int i = (bid - 2048) * 256 + tid;
        int r = i >> 9, c = i & 511;
        splitf(mix_w[r * 1536 + c], h, l); wmixA[i] = h; wmixA[524288 + i] = l;
    } else if (bid < 4096) {
        int i = (bid - 3072) * 256 + tid;
        int r = i >> 9, c = i & 511;
        splitf(mix_w[512 + r * 1536 + c], h, l);
        wmixA[262144 + i] = h; wmixA[524288 + 262144 + i] = l;
    } else if (bid < 6144) {
        int i = (bid - 4096) * 256 + tid;
        int e = i >> 9, j = i & 511;
        splitf(m_out_w[(size_t)j * 1024 + e], h, l);
        wTout[i] = h; wTout[1048576 + i] = l;
    } else if (bid < 8192) {
        int i = (bid - 6144) * 256 + tid;
        int e = i >> 9, j = i & 511;
        splitf(m_out_w[524288 + (size_t)j * 1024 + e], h, l);
        wTout[524288 + i] = h; wTout[1048576 + 524288 + i] = l;
    } else if (bid < 16384) {
        int i = (bid - 8192) * 256 + tid;
        splitf(m_in_w[i], h, l); win[i] = h; win[2097152 + i] = l;
    } else if (bid < 16896) {
        int i = (bid - 16384) * 256 + tid;
        splitf(m_xproj_w[i], h, l); wxp[i] = h; wxp[131072 + i] = l;
    } else if (bid < 17152) {
        int i = (bid - 16896) * 256 + tid;
        splitf(m_dt_w[i], h, l); wdt[i] = h; wdt[65536 + i] = l;
    } else if (bid < 19200) {
        int i = (bid - 17152) * 256 + tid;
        splitf(ffn_w1[i], h, l); wf1[i] = h; wf1[524288 + i] = l;
    } else if (bid < 21248) {
        int i = (bid - 19200) * 256 + tid;
        splitf(ffn_w2[i], h, l); wf2[i] = h; wf2[524288 + i] = l;
    } else {
        int i = (bid - 21248) * 256 + tid;
        int t = i >> 9, c = i & 511;
        int y = t >> 5, x = t & 31;
        const float PI = 3.14159265358979323846f;
        float yy = ((y + 0.5f) / 32.0f) * 2.0f - 1.0f;
        float xx = ((x + 0.5f) / 32.0f) * 2.0f - 1.0f;
        float f2 = sinf(PI * yy), f3 = cosf(PI * yy);
        float f4 = sinf(PI * xx), f5 = cosf(PI * xx);
        const float* w = pos_w1 + c * 6;
        float v = pos_b1[c] + yy * w[0] + xx * w[1] + f2 * w[2] + f3 * w[3] + f4 * w[4] + f5 * w[5];
        v = geluf(v);
        splitf(v, h, l); posh[i] = h; posh[524288 + i] = l;
    }
}

// ---------------- LN(tokens) + pos -> hi/lo ----------------
__global__ void ln_add_pos_k(const float* __restrict__ x,
                             const float* __restrict__ g, const float* __restrict__ b,
                             const float* __restrict__ pos, bf16* __restrict__ out)
{
    __shared__ float sh[16];
    const int row = blockIdx.x;
    const int tid = threadIdx.x;
    float4 v = ((const float4*)(x + (size_t)row * DIM))[tid];
    float s = v.x + v.y + v.z + v.w;
    float q = v.x * v.x + v.y * v.y + v.z * v.z + v.w * v.w;
#pragma unroll
    for (int o = 16; o; o >>= 1) {
        s += __shfl_xor_sync(0xffffffffu, s, o);
        q += __shfl_xor_sync(0xffffffffu, q, o);
    }
    if ((tid & 31) == 0) { sh[tid >> 5] = s; sh[4 + (tid >> 5)] = q; }
    __syncthreads();
    if (tid == 0) {
        float S = sh[0] + sh[1] + sh[2] + sh[3];
        float Q = sh[4] + sh[5] + sh[6] + sh[7];
        float mu = S * (1.0f / DIM);
        float var = Q * (1.0f / DIM) - mu * mu;
        sh[8] = mu; sh[9] = rsqrtf(var + 1e-5f);
    }
    __syncthreads();
    const float mu = sh[8], rs = sh[9];
    const int t = row & (LSEQ - 1);
    float4 g4 = ((const float4*)g)[tid];
    float4 b4 = ((const float4*)b)[tid];
    float4 p4 = ((const float4*)(pos + (size_t)t * DIM))[tid];
    float4 r;
    r.x = (v.x - mu) * rs * g4.x + b4.x + p4.x;
    r.y = (v.y - mu) * rs * g4.y + b4.y + p4.y;
    r.z = (v.z - mu) * rs * g4.z + b4.z + p4.z;
    r.w = (v.w - mu) * rs * g4.w + b4.w + p4.w;
    bf16* ph = out + (size_t)row * DIM + tid * 4;
    split4_store(ph, ph + (long long)ROWS * DIM, r);
}

// ---------------- causal conv + SiLU (reads hi/lo xz) ----------------
__global__ void conv_silu_k(const bf16* __restrict__ xzh,
                            const float* __restrict__ cw, const float* __restrict__ cb,
                            bf16* __restrict__ xch)
{
    size_t gidx = (size_t)blockIdx.x * 256 + threadIdx.x;
    int dq  = (int)(gidx & 255);
    int row = (int)((gidx >> 8) & (ROWS - 1));
    int dir = (int)(gidx >> 21);
    int d = dq * 4;
    int t = row & (LSEQ - 1);
    int b = row >> 10;

    float4 acc = *(const float4*)&cb[dir * DI + d];
    const float4* wrow = (const float4*)&cw[(size_t)(dir * DI + d) * 4];
    float4 w0 = wrow[0], w1 = wrow[1], w2 = wrow[2], w3 = wrow[3];

#pragma unroll
    for (int k = 0; k < 4; k++) {
        int off = dir ? (3 - k) : (k - 3);
        int tt = t + off;
        if (tt >= 0 && tt < LSEQ) {
            float4 v = hl4(xzh, XZPLANE, ((size_t)(b * LSEQ + tt)) * 4096 + dir * 2048 + d);
            acc.x = fmaf(fcomp(w0, k), v.x, acc.x);
            acc.y = fmaf(fcomp(w1, k), v.y, acc.y);
            acc.z = fmaf(fcomp(w2, k), v.z, acc.z);
            acc.w = fmaf(fcomp(w3, k), v.w, acc.w);
        }
    }
    float4 r;
    r.x = siluf(acc.x); r.y = siluf(acc.y); r.z = siluf(acc.z); r.w = siluf(acc.w);
    bf16* ph = xch + gidx * 4;
    split4_store(ph, ph + XPLANE, r);
}

// ================= chunked selective scan =================
__global__ void scan_part1_k(const bf16* __restrict__ dsph, const bf16* __restrict__ xch,
                             const float* __restrict__ proj, const float* __restrict__ A_log,
                             float* __restrict__ hend, float* __restrict__ prodv)
{
    const int chunk = blockIdx.x >> 3;
    const int dblk  = blockIdx.x & 7;
    const int b = blockIdx.y, dir = blockIdx.z;
    const int d = dblk * 128 + threadIdx.x;

    float a[DS];
    bool fast = true;
#pragma unroll
    for (int s = 0; s < DS; s++) {
        a[s] = -expf(A_log[((size_t)dir * DI + d) * DS + s]);
        fast = fast && (fabsf(a[s] + (float)(s + 1)) < 1e-4f * (float)(s + 1));
    }

    const size_t base_row = (size_t)dir * ROWS + (size_t)b * LSEQ;
    __shared__ float sB[CLEN][DS];
    for (int i = threadIdx.x; i < CLEN * DS; i += 128) {
        int st = chunk * CLEN + (i >> 4);
        int c = i & 15;
        int r = dir ? (LSEQ - 1 - st) : st;
        sB[i >> 4][c] = proj[(base_row + r) * 64 + 32 + c];
    }
    __syncthreads();

    float h[DS], p[DS];
#pragma unroll
    for (int s = 0; s < DS; s++) h[s] = 0.0f;

    if (fast) {
        float prodE1 = 1.0f;
        for (int i = 0; i < CLEN; i++) {
            int st = chunk * CLEN + i;
            int r = dir ? (LSEQ - 1 - st) : st;
            size_t ro = (base_row + r) * (size_t)DI + d;
            float delta = hlval(dsph, DSPLANE, ro);
            float x     = hlval(xch, XPLANE, ro);
            float dx    = delta * x;
            float e1 = __expf(-delta);
            prodE1 *= e1;
            float ep = e1;
#pragma unroll
            for (int s = 0; s < DS; s++) {
                h[s] = fmaf(h[s], ep, dx * sB[i][s]);
                ep *= e1;
            }
        }
        float ep = prodE1;
#pragma unroll
        for (int s = 0; s < DS; s++) { p[s] = ep; ep *= prodE1; }
    } else {
#pragma unroll
        for (int s = 0; s < DS; s++) p[s] = 1.0f;
        for (int i = 0; i < CLEN; i++) {
            int st = chunk * CLEN + i;
            int r = dir ? (LSEQ - 1 - st) : st;
            size_t ro = (base_row + r) * (size_t)DI + d;
            float delta = hlval(dsph, DSPLANE, ro);
            float x     = hlval(xch, XPLANE, ro);
            float dx    = delta * x;
#pragma unroll
            for (int s = 0; s < DS; s++) {
                float e = __expf(delta * a[s]);
                h[s] = fmaf(h[s], e, dx * sB[i][s]);
                p[s] *= e;
            }
        }
    }

    const int CH = (dir * BATCH + b) * DI + d;
    size_t o = ((size_t)chunk * NCH + CH) * DS;
#pragma unroll
    for (int s = 0; s < DS; s++) { hend[o + s] = h[s]; prodv[o + s] = p[s]; }
}

__global__ void scan_part2_k(const float* __restrict__ hend, const float* __restrict__ prodv,
                             float* __restrict__ hinit)
{
    int idx = blockIdx.x * 256 + threadIdx.x;
    if (idx >= NCH * DS) return;
    float H = 0.0f;
#pragma unroll 4
    for (int c = 0; c < NCHUNK; c++) {
        size_t o = (size_t)c * (NCH * DS) + idx;
        hinit[o] = H;
        H = fmaf(prodv[o], H, hend[o]);
    }
}

__global__ void scan_part3_k(const bf16* __restrict__ dsph, const bf16* __restrict__ xch,
                             const float* __restrict__ proj, const bf16* __restrict__ xzh,
                             const float* __restrict__ A_log, const float* __restrict__ Dp,
                             const float* __restrict__ hinit, bf16* __restrict__ ycat)
{
    const int chunk = blockIdx.x >> 3;
    const int dblk  = blockIdx.x & 7;
    const int b = blockIdx.y, dir = blockIdx.z;
    const int d = dblk * 128 + threadIdx.x;

    float a[DS];
    bool fast = true;
#pragma unroll
    for (int s = 0; s < DS; s++) {
        a[s] = -expf(A_log[((size_t)dir * DI + d) * DS + s]);
        fast = fast && (fabsf(a[s] + (float)(s + 1)) < 1e-4f * (float)(s + 1));
    }
    const float Dv = Dp[dir * DI + d];

    const size_t base_row = (size_t)dir * ROWS + (size_t)b * LSEQ;
    const long long plane = (long long)ROWS * 2048;
    __shared__ float sBC[CLEN][32];
    for (int i = threadIdx.x; i < CLEN * 32; i += 128) {
        int st = chunk * CLEN + (i >> 5);
        int c = i & 31;
        int r = dir ? (LSEQ - 1 - st) : st;
        sBC[i >> 5][c] = proj[(base_row + r) * 64 + 32 + c];
    }
    __syncthreads();

    const int CH = (dir * BATCH + b) * DI + d;
    size_t ho = ((size_t)chunk * NCH + CH) * DS;
    float h[DS];
#pragma unroll
    for (int s = 0; s < DS; s++) h[s] = hinit[ho + s];

    if (fast) {
        for (int i = 0; i < CLEN; i++) {
            int st = chunk * CLEN + i;
            int r = dir ? (LSEQ - 1 - st) : st;
            size_t ro = (base_row + r) * (size_t)DI + d;
            float delta = hlval(dsph, DSPLANE, ro);
            float x     = hlval(xch, XPLANE, ro);
            float dx    = delta * x;
            float y = 0.0f;
            float e1 = __expf(-delta);
            float ep = e1;
#pragma unroll
            for (int s = 0; s < DS; s++) {
                h[s] = fmaf(h[s], ep, dx * sBC[i][s]);
                y = fmaf(h[s], sBC[i][16 + s], y);
                ep *= e1;
            }
            float z = hlval(xzh, XZPLANE, ((size_t)(b * LSEQ + r)) * 4096 + dir * 2048 + DI + d);
            float outv = (y + x * Dv) * siluf(z);
            bf16 hh, ll; splitf(outv, hh, ll);
            size_t oo = ((size_t)(b * LSEQ + r)) * 2048 + dir * DI + d;
            ycat[oo] = hh; ycat[plane + oo] = ll;
        }
    } else {
        for (int i = 0; i < CLEN; i++) {
            int st = chunk * CLEN + i;
            int r = dir ? (LSEQ - 1 - st) : st;
            size_t ro = (base_row + r) * (size_t)DI + d;
            float delta = hlval(dsph, DSPLANE, ro);
            float x     = hlval(xch, XPLANE, ro);
            float dx    = delta * x;
            float y = 0.0f;
#pragma unroll
            for (int s = 0; s < DS; s++) {
                float e = __expf(delta * a[s]);
                h[s] = fmaf(h[s], e, dx * sBC[i][s]);
                y = fmaf(h[s], sBC[i][16 + s], y);
            }
            float z = hlval(xzh, XZPLANE, ((size_t)(b * LSEQ + r)) * 4096 + dir * 2048 + DI + d);
            float outv = (y + x * Dv) * siluf(z);
            bf16 hh, ll; splitf(outv, hh, ll);
            size_t oo = ((size_t)(b * LSEQ + r)) * 2048 + dir * DI + d;
            ycat[oo] = hh; ycat[plane + oo] = ll;
        }
    }
}

// ---------------- dual LayerNorm ----------------
__global__ void ln_dual_k(const float* __restrict__ in,
                          const float* __restrict__ g1, const float* __restrict__ b1,
                          const float* __restrict__ g2, const float* __restrict__ b2,
                          float* __restrict__ out1, bf16* __restrict__ out2)
{
    __shared__ float sh[16];
    const int row = blockIdx.x;
    const int tid = threadIdx.x;
    float4 v = ((const float4*)(in + (size_t)row * DIM))[tid];
    float s = v.x + v.y + v.z + v.w;
    float q = v.x * v.x + v.y * v.y + v.z * v.z + v.w * v.w;
#pragma unroll
    for (int o = 16; o; o >>= 1) {
        s += __shfl_xor_sync(0xffffffffu, s, o);
        q += __shfl_xor_sync(0xffffffffu, q, o);
    }
    if ((tid & 31) == 0) { sh[tid >> 5] = s; sh[4 + (tid >> 5)] = q; }
    __syncthreads();
    if (tid == 0) {
        float S = sh[0] + sh[1] + sh[2] + sh[3];
        float Q = sh[4] + sh[5] + sh[6] + sh[7];
        float mu = S * (1.0f / DIM);
        float var = Q * (1.0f / DIM) - mu * mu;
        sh[8] = mu; sh[9] = rsqrtf(var + 1e-5f);
    }
    __syncthreads();
    float mu = sh[8], rs = sh[9];
    float4 g4 = ((const float4*)g1)[tid];
    float4 b4 = ((const float4*)b1)[tid];
    float4 x4;
    x4.x = (v.x - mu) * rs * g4.x + b4.x;
    x4.y = (v.y - mu) * rs * g4.y + b4.y;
    x4.z = (v.z - mu) * rs * g4.z + b4.z;
    x4.w = (v.w - mu) * rs * g4.w + b4.w;
    ((float4*)(out1 + (size_t)row * DIM))[tid] = x4;

    __syncthreads();
    s = x4.x + x4.y + x4.z + x4.w;
    q = x4.x * x4.x + x4.y * x4.y + x4.z * x4.z + x4.w * x4.w;
#pragma unroll
    for (int o = 16; o; o >>= 1) {
        s += __shfl_xor_sync(0xffffffffu, s, o);
        q += __shfl_xor_sync(0xffffffffu, q, o);
    }
    if ((tid & 31) == 0) { sh[tid >> 5] = s; sh[4 + (tid >> 5)] = q; }
    __syncthreads();
    if (tid == 0) {
        float S = sh[0] + sh[1] + sh[2] + sh[3];
        float Q = sh[4] + sh[5] + sh[6] + sh[7];
        float mu2 = S * (1.0f / DIM);
        float var2 = Q * (1.0f / DIM) - mu2 * mu2;
        sh[8] = mu2; sh[9] = rsqrtf(var2 + 1e-5f);
    }
    __syncthreads();
    float mu2 = sh[8], rs2 = sh[9];
    float4 G = ((const float4*)g2)[tid];
    float4 B = ((const float4*)b2)[tid];
    float4 r;
    r.x = (x4.x - mu2) * rs2 * G.x + B.x;
    r.y = (x4.y - mu2) * rs2 * G.y + B.y;
    r.z = (x4.z - mu2) * rs2 * G.z + B.z;
    r.w = (x4.w - mu2) * rs2 * G.w + B.w;
    bf16* ph = out2 + (size_t)row * DIM + tid * 4;
    split4_store(ph, ph + (long long)ROWS * DIM, r);
}

// ---------------- host launcher ----------------
extern "C" void kernel_launch(void* const* d_in, const int* in_sizes, int n_in,
                              void* d_out, int out_size)
{
    const float* tokens    = (const float*)d_in[0];
    const float* in_g      = (const float*)d_in[3];
    const float* in_b      = (const float*)d_in[4];
    const float* pos_w1    = (const float*)d_in[5];
    const float* pos_b1    = (const float*)d_in[6];
    const float* pos_w2    = (const float*)d_in[7];
    const float* pos_b2    = (const float*)d_in[8];
    const float* m_in_w    = (const float*)d_in[9];
    const float* m_conv_w  = (const float*)d_in[10];
    const float* m_conv_b  = (const float*)d_in[11];
    const float* m_xproj_w = (const float*)d_in[12];
    const float* m_dt_w    = (const float*)d_in[13];
    const float* m_dt_b    = (const float*)d_in[14];
    const float* m_A_log   = (const float*)d_in[15];
    const float* m_D       = (const float*)d_in[16];
    const float* m_out_w   = (const float*)d_in[17];
    const float* mix_w     = (const float*)d_in[18];
    const float* mix_b     = (const float*)d_in[19];
    const float* dn_g      = (const float*)d_in[20];
    const float* dn_b      = (const float*)d_in[21];
    const float* fn_g      = (const float*)d_in[22];
    const float* fn_b      = (const float*)d_in[23];
    const float* ffn_w1    = (const float*)d_in[24];
    const float* ffn_b1    = (const float*)d_in[25];
    const float* ffn_w2    = (const float*)d_in[26];
    const float* ffn_b2    = (const float*)d_in[27];
    float* out = (float*)d_out;

    float *pos, *pos_mix, *proj, *dmix, *dln, *hend, *prodv, *hinit;
    bf16 *sin_hl, *posh_hl, *pos_hl, *wpos2, *wpmix, *wmixA, *wTout, *win, *wxp, *wdt, *wf1, *wf2;
    bf16 *xzh, *dsph, *xc_hl, *proj_hl, *ycat_hl, *wc_hl, *lnf_hl, *h1_hl;
    cudaGetSymbolAddress((void**)&pos,     g_pos);
    cudaGetSymbolAddress((void**)&pos_mix, g_pos_mix);
    cudaGetSymbolAddress((void**)&proj,    g_proj);
    cudaGetSymbolAddress((void**)&dmix,    g_dmix);
    cudaGetSymbolAddress((void**)&dln,     g_dln);
    cudaGetSymbolAddress((void**)&hend,    g_hend);
    cudaGetSymbolAddress((void**)&prodv,   g_prod);
    cudaGetSymbolAddress((void**)&hinit,   g_hinit);
    cudaGetSymbolAddress((void**)&sin_hl,  hl_scan_in);
    cudaGetSymbolAddress((void**)&posh_hl, hl_pos_h);
    cudaGetSymbolAddress((void**)&pos_hl,  hl_pos);
    cudaGetSymbolAddress((void**)&wpos2,   hl_w_pos2);
    cudaGetSymbolAddress((void**)&wpmix,   hl_w_pmix);
    cudaGetSymbolAddress((void**)&wmixA,   hl_w_mixA);
    cudaGetSymbolAddress((void**)&wTout,   hl_wT_out);
    cudaGetSymbolAddress((void**)&win,     hl_w_in);
    cudaGetSymbolAddress((void**)&wxp,     hl_w_xp);
    cudaGetSymbolAddress((void**)&wdt,     hl_w_dt);
    cudaGetSymbolAddress((void**)&wf1,     hl_w_f1);
    cudaGetSymbolAddress((void**)&wf2,     hl_w_f2);
    cudaGetSymbolAddress((void**)&xzh,     hl_xz);
    cudaGetSymbolAddress((void**)&dsph,    hl_dsp);
    cudaGetSymbolAddress((void**)&xc_hl,   hl_xc);
    cudaGetSymbolAddress((void**)&proj_hl, hl_proj);
    cudaGetSymbolAddress((void**)&ycat_hl, hl_ycat);
    cudaGetSymbolAddress((void**)&wc_hl,   hl_wc);
    cudaGetSymbolAddress((void**)&lnf_hl,  hl_lnf);
    cudaGetSymbolAddress((void**)&h1_hl,   hl_h1);

    cudaFuncSetAttribute(bgemm<0,2>, cudaFuncAttributeMaxDynamicSharedMemorySize, SMEM_BYTES);
    cudaFuncSetAttribute(bgemm<4,0>, cudaFuncAttributeMaxDynamicSharedMemorySize, SMEM_BYTES);
    cudaFuncSetAttribute(bgemm<1,2>, cudaFuncAttributeMaxDynamicSharedMemorySize, SMEM_BYTES);
    cudaFuncSetAttribute(bgemm<5,0>, cudaFuncAttributeMaxDynamicSharedMemorySize, SMEM_BYTES);
    cudaFuncSetAttribute(bgemm64<0,0>, cudaFuncAttributeMaxDynamicSharedMemorySize, SMEM64_BYTES);
    cudaFuncSetAttribute(bgemm64<0,1>, cudaFuncAttributeMaxDynamicSharedMemorySize, SMEM64_BYTES);
    cudaFuncSetAttribute(bgemm64<0,2>, cudaFuncAttributeMaxDynamicSharedMemorySize, SMEM64_BYTES);
    cudaFuncSetAttribute(bgemm64<3,2>, cudaFuncAttributeMaxDynamicSharedMemorySize, SMEM64_BYTES);

    // 1: fused converts + pos_hidden
    fused_pre_k<<<PRE_BLOCKS, 256>>>(pos_w1, pos_b1, pos_w2, mix_w, m_out_w, m_in_w,
                                     m_xproj_w, m_dt_w, ffn_w1, ffn_w2,
                                     wpos2, wpmix, wmixA, wTout, win, wxp, wdt, wf1, wf2,
                                     posh_hl);
    // 2: pos = gelu_h @ pos_w2^T + b2
    bgemm64<0,1><<<dim3(4,16,1), 256, SMEM64_BYTES>>>(
        posh_hl, posh_hl + LSEQ*DIM, 512, 0,  wpos2, wpos2 + 512*512, 512, 0,
        pos, 512, 0,  pos_hl, (long long)LSEQ*DIM, 512, 0,
        pos_b2, 0, nullptr, 1, LSEQ, 512, 512);
    // 3: scan_in = LN(tokens) + pos
    ln_add_pos_k<<<ROWS, 128>>>(tokens, in_g, in_b, pos, sin_hl);
    // 4: xz = scan_in @ in_w^T -> hi/lo bf16  <-- profiled slot
    bgemm<0,2><<<dim3(32,64,1), 256, SMEM_BYTES>>>(
        sin_hl, sin_hl + (long long)ROWS*DIM, 512, 0,
        win, win + (long long)4096*512, 512, 0,
        nullptr, 4096, 0,
        xzh, (long long)XZPLANE, 4096, 0,
        nullptr, 0, nullptr, 1, ROWS, 4096, 512);

    conv_silu_k<<<(2*ROWS*DI)/1024, 256>>>(xzh, m_conv_w, m_conv_b, xc_hl);
    // proj = xc @ xproj^T per dir
    bgemm64<0,1><<<dim3(1,128,2), 256, SMEM64_BYTES>>>(
        xc_hl, xc_hl + (long long)2*ROWS*DI, 1024, (long long)ROWS*DI,
        wxp, wxp + (long long)128*1024, 1024, (long long)64*1024,
        proj, 64, (long long)ROWS*64,
        proj_hl, (long long)2*ROWS*64, 64, (long long)ROWS*64,
        nullptr, 0, nullptr, 1, ROWS, 64, 1024);
    // dsp = softplus(dt @ dt_w^T + dt_b) -> hi/lo bf16
    bgemm64<3,2><<<dim3(8,128,2), 256, SMEM64_BYTES>>>(
        proj_hl, proj_hl + (long long)2*ROWS*64, 64, (long long)ROWS*64,
        wdt, wdt + (long long)2048*32, 32, (long long)1024*32,
        nullptr, 1024, 0,
        dsph, (long long)DSPLANE, 1024, (long long)ROWS*DI,
        m_dt_b, 1024, nullptr, 1, ROWS, 1024, 32);

    // chunked scan
    scan_part1_k<<<dim3(8*NCHUNK, BATCH, 2), 128>>>(dsph, xc_hl, proj, m_A_log, hend, prodv);
    scan_part2_k<<<(NCH*DS)/256, 256>>>(hend, prodv, hinit);
    scan_part3_k<<<dim3(8*NCHUNK, BATCH, 2), 128>>>(dsph, xc_hl, proj, xzh, m_A_log, m_D, hinit, ycat_hl);

    // pos_mix = pos @ mix_w[:,1024:1536]^T + mix_b
    bgemm64<0,0><<<dim3(4,16,1), 256, SMEM64_BYTES>>>(
        pos_hl, pos_hl + LSEQ*DIM, 512, 0,  wpmix, wpmix + 512*512, 512, 0,
        pos_mix, 512, 0,  nullptr, 0, 0, 0,
        mix_b, 0, nullptr, 1, LSEQ, 512, 512);
    // Wc[dir] = mix_w_slice @ out_w[dir]
    bgemm64<0,2><<<dim3(8,8,2), 256, SMEM64_BYTES>>>(
        wmixA, wmixA + (long long)2*512*512, 512, (long long)512*512,
        wTout, wTout + (long long)2*1024*512, 512, (long long)1024*512,
        nullptr, 0, 0,
        wc_hl, (long long)512*2048, 2048, 1024,
        nullptr, 0, nullptr, 1, 512, 1024, 512);
    // dmix = ycat @ Wc^T + pos_mix
    bgemm<4,0><<<dim3(4,64,1), 256, SMEM_BYTES>>>(
        ycat_hl, ycat_hl + (long long)ROWS*2048, 2048, 0,
        wc_hl, wc_hl + (long long)512*2048, 2048, 0,
        dmix, 512, 0, nullptr, 0, 0, 0,
        nullptr, 0, pos_mix, LSEQ, ROWS, 512, 2048);
    ln_dual_k<<<ROWS, 128>>>(dmix, dn_g, dn_b, fn_g, fn_b, dln, lnf_hl);
    bgemm<1,2><<<dim3(8,64,1), 256, SMEM_BYTES>>>(
        lnf_hl, lnf_hl + (long long)ROWS*DIM, 512, 0,
        wf1, wf1 + (long long)1024*512, 512, 0,
        nullptr, 1024, 0,
        h1_hl, (long long)ROWS*HID, 1024, 0,
        ffn_b1, 0, nullptr, 1, ROWS, 1024, 512);
    bgemm<5,0><<<dim3(4,64,1), 256, SMEM_BYTES>>>(
        h1_hl, h1_hl + (long long)ROWS*HID, 1024, 0,
        wf2, wf2 + (long long)512*1024, 1024, 0,
        out, 512, 0, nullptr, 0, 0, 0,
        ffn_b2, 0, dln, 1, ROWS, 512, 1024);

    (void)in_sizes; (void)n_in; (void)out_size;
}

// round 14
// speedup vs baseline: 1.0938x; 1.0938x over previous
#include <cuda_runtime.h>
#include <cuda_bf16.h>
#include <cstdint>
#include <math.h>

#define BATCH 8
#define LSEQ  1024
#define DIM   512
#define DI    1024
#define DS    16
#define HID   1024
#define ROWS  (BATCH*LSEQ)    // 8192
#define NCHUNK 32
#define CLEN   32
#define NCH    16384
#define XPLANE ((size_t)2*ROWS*DI)
#define XZPLANE ((size_t)ROWS*4096)
#define DSPLANE ((size_t)2*ROWS*DI)

typedef __nv_bfloat16 bf16;

// ---------------- fp32 scratch ----------------
__device__ float g_pos    [LSEQ*DIM];
__device__ float g_pos_mix[LSEQ*DIM];
__device__ float g_proj   [2*ROWS*64];
__device__ float g_dmix   [ROWS*DIM];
__device__ float g_dln    [ROWS*DIM];
__device__ float g_hend [NCHUNK*NCH*DS];
__device__ float g_prod [NCHUNK*NCH*DS];
__device__ float g_hinit[NCHUNK*NCH*DS];

// ---------------- bf16 hi/lo scratch ----------------
__device__ __align__(16) bf16 hl_scan_in[2*ROWS*DIM];
__device__ __align__(16) bf16 hl_pos_h  [2*LSEQ*DIM];
__device__ __align__(16) bf16 hl_pos    [2*LSEQ*DIM];
__device__ __align__(16) bf16 hl_w_pos2 [2*DIM*DIM];
__device__ __align__(16) bf16 hl_w_pmix [2*DIM*DIM];
__device__ __align__(16) bf16 hl_w_mixA [2*2*DIM*DIM];
__device__ __align__(16) bf16 hl_wT_out [2*2*DI*DIM];
__device__ __align__(16) bf16 hl_w_in   [2*4096*DIM];
__device__ __align__(16) bf16 hl_w_xp   [2*2*64*DI];
__device__ __align__(16) bf16 hl_w_dt   [2*2*DI*32];
__device__ __align__(16) bf16 hl_w_f1   [2*HID*DIM];
__device__ __align__(16) bf16 hl_w_f2   [2*DIM*HID];
__device__ __align__(16) bf16 hl_xz     [2*ROWS*4096];
__device__ __align__(16) bf16 hl_dsp    [2*2*ROWS*DI];
__device__ __align__(16) bf16 hl_xc     [2*2*ROWS*DI];
__device__ __align__(16) bf16 hl_proj   [2*2*ROWS*64];
__device__ __align__(16) bf16 hl_ycat   [2*ROWS*2048];
__device__ __align__(16) bf16 hl_wc     [2*DIM*2048];
__device__ __align__(16) bf16 hl_lnf    [2*ROWS*DIM];
__device__ __align__(16) bf16 hl_h1     [2*ROWS*HID];

// ---------------- math helpers ----------------
__device__ __forceinline__ float geluf(float x) {
    return 0.5f * x * (1.0f + erff(x * 0.70710678118654752440f));
}
__device__ __forceinline__ float siluf(float x) { return x / (1.0f + __expf(-x)); }
__device__ __forceinline__ float softplusf(float x) { return (x > 20.0f) ? x : log1pf(__expf(x)); }
__device__ __forceinline__ void splitf(float v, bf16& h, bf16& l) {
    h = __float2bfloat16(v);
    l = __float2bfloat16(v - __bfloat162float(h));
}
__device__ __forceinline__ float fcomp(float4 f, int k) {
    return k == 0 ? f.x : (k == 1 ? f.y : (k == 2 ? f.z : f.w));
}
__device__ __forceinline__ void split4_store(bf16* ph, bf16* pl, float4 v) {
    bf16 h0, l0, h1, l1, h2, l2, h3, l3;
    splitf(v.x, h0, l0); splitf(v.y, h1, l1);
    splitf(v.z, h2, l2); splitf(v.w, h3, l3);
    __nv_bfloat162 a; a.x = h0; a.y = h1;
    __nv_bfloat162 b; b.x = h2; b.y = h3;
    __nv_bfloat162 c; c.x = l0; c.y = l1;
    __nv_bfloat162 d; d.x = l2; d.y = l3;
    *(__nv_bfloat162*)ph = a; *(__nv_bfloat162*)(ph + 2) = b;
    *(__nv_bfloat162*)pl = c; *(__nv_bfloat162*)(pl + 2) = d;
}
// packed pair hi/lo store (n must be 2-aligned)
__device__ __forceinline__ void split2_store(bf16* ph, bf16* pl, float v0, float v1) {
    bf16 h0, l0, h1, l1;
    splitf(v0, h0, l0); splitf(v1, h1, l1);
    __nv_bfloat162 hh; hh.x = h0; hh.y = h1;
    __nv_bfloat162 ll; ll.x = l0; ll.y = l1;
    *(__nv_bfloat162*)ph = hh;
    *(__nv_bfloat162*)pl = ll;
}
__device__ __forceinline__ float hlval(const bf16* p, size_t plane, size_t i) {
    return __bfloat162float(p[i]) + __bfloat162float(p[plane + i]);
}
__device__ __forceinline__ float4 hl4(const bf16* p, size_t plane, size_t i) {
    __nv_bfloat162 h0 = *(const __nv_bfloat162*)(p + i);
    __nv_bfloat162 h1 = *(const __nv_bfloat162*)(p + i + 2);
    __nv_bfloat162 l0 = *(const __nv_bfloat162*)(p + plane + i);
    __nv_bfloat162 l1 = *(const __nv_bfloat162*)(p + plane + i + 2);
    float4 r;
    r.x = __bfloat162float(h0.x) + __bfloat162float(l0.x);
    r.y = __bfloat162float(h0.y) + __bfloat162float(l0.y);
    r.z = __bfloat162float(h1.x) + __bfloat162float(l1.x);
    r.w = __bfloat162float(h1.y) + __bfloat162float(l1.y);
    return r;
}

// ---------------- PTX helpers ----------------
__device__ __forceinline__ void mma16816(float* d, const uint32_t* a, uint32_t b0, uint32_t b1) {
    asm volatile(
        "mma.sync.aligned.m16n8k16.row.col.f32.bf16.bf16.f32 "
        "{%0,%1,%2,%3},{%4,%5,%6,%7},{%8,%9},{%0,%1,%2,%3};\n"
        : "+f"(d[0]), "+f"(d[1]), "+f"(d[2]), "+f"(d[3])
        : "r"(a[0]), "r"(a[1]), "r"(a[2]), "r"(a[3]), "r"(b0), "r"(b1));
}
__device__ __forceinline__ void ldsm4(uint32_t* r, uint32_t addr) {
    asm volatile("ldmatrix.sync.aligned.m8n8.x4.shared.b16 {%0,%1,%2,%3}, [%4];\n"
                 : "=r"(r[0]), "=r"(r[1]), "=r"(r[2]), "=r"(r[3]) : "r"(addr));
}
__device__ __forceinline__ void cp16(uint32_t dst, const void* src, bool pred) {
    int sz = pred ? 16 : 0;
    asm volatile("cp.async.cg.shared.global [%0], [%1], 16, %2;\n"
                 :: "r"(dst), "l"(src), "r"(sz) : "memory");
}
__device__ __forceinline__ void cp_commit() { asm volatile("cp.async.commit_group;\n" ::: "memory"); }
__device__ __forceinline__ void cp_wait1()  { asm volatile("cp.async.wait_group 1;\n" ::: "memory"); }

// ---------------- mma.sync GEMM 128x128 (vectorized hi/lo epilogue) ----------------
#define BK_STAGES 3
#define SMEM_BYTES (BK_STAGES*32768)

template<int EPI, int OUT>
__global__ void __launch_bounds__(256, 2)
bgemm(const bf16* __restrict__ Ah, const bf16* __restrict__ Al, int lda, long long sA,
      const bf16* __restrict__ Bh, const bf16* __restrict__ Bl, int ldb, long long sB,
      float* __restrict__ C, int ldc, long long sC,
      bf16* __restrict__ Ch, long long planeC, int ldch, long long sCh,
      const float* __restrict__ bias, long long sBias,
      const float* __restrict__ aux, int auxMod,
      int M, int N, int K)
{
    extern __shared__ char smd[];
    const int zi = blockIdx.z;
    Ah += (size_t)zi * sA; Al += (size_t)zi * sA;
    Bh += (size_t)zi * sB; Bl += (size_t)zi * sB;
    if (OUT != 2) C += (size_t)zi * sC;
    if (OUT != 0) Ch += (size_t)zi * sCh;
    const float* bp = bias ? (bias + (size_t)zi * sBias) : nullptr;

    const int bm = blockIdx.y * 128;
    const int bn = blockIdx.x * 128;
    const int tid = threadIdx.x, lane = tid & 31, warp = tid >> 5;
    const int wm = warp & 1, wn = warp >> 1;

    const uint32_t smem_base = (uint32_t)__cvta_generic_to_shared(smd);

    auto load_stage = [&](int s, int kt) {
        const int k0 = kt * 32;
        const uint32_t As = smem_base + s * 32768;
        const uint32_t Bs = As + 16384;
#pragma unroll
        for (int i = 0; i < 4; i++) {
            int lin = i * 256 + tid;
            int row = lin >> 3, ch = lin & 7;
            const bf16* srcA = ((ch & 4) ? Al : Ah) + (size_t)(bm + row) * lda + k0 + (ch & 3) * 8;
            cp16(As + row * 128 + ((ch ^ (row & 7)) * 16), srcA, true);
        }
#pragma unroll
        for (int i = 0; i < 4; i++) {
            int lin = i * 256 + tid;
            int row = lin >> 3, ch = lin & 7;
            bool ok = (bn + row) < N;
            const bf16* srcB = ((ch & 4) ? Bl : Bh) +
                               (ok ? ((size_t)(bn + row) * ldb + k0 + (ch & 3) * 8) : 0);
            cp16(Bs + row * 128 + ((ch ^ (row & 7)) * 16), srcB, ok);
        }
    };

    float acc[4][4][4];
#pragma unroll
    for (int i = 0; i < 4; i++)
#pragma unroll
        for (int j = 0; j < 4; j++)
#pragma unroll
            for (int q = 0; q < 4; q++) acc[i][j][q] = 0.0f;

    const int nk = K / 32;
    if (nk > 0) load_stage(0, 0);
    cp_commit();
    if (nk > 1) load_stage(1, 1);
    cp_commit();

    const int g  = lane >> 3;
    const int lr = lane & 7;
    const int aRow0 = wm * 64 + (g & 1) * 8 + lr;
    const int bRow0 = wn * 32 + (g & 1) * 8 + lr;
    const int chHi  = (g >> 1);

    for (int kt = 0; kt < nk; kt++) {
        cp_wait1();
        __syncthreads();
        const uint32_t As = smem_base + (kt % BK_STAGES) * 32768;
        const uint32_t Bs = As + 16384;

#pragma unroll
        for (int step = 0; step < 2; step++) {
            uint32_t ah[4][4], al[4][4], bh[2][4], bl[2][4];
            const int cH = ((step * 2 + chHi) ^ lr) * 16;
            const int cL = ((4 + step * 2 + chHi) ^ lr) * 16;
#pragma unroll
            for (int mt = 0; mt < 4; mt++) {
                uint32_t rb = As + (uint32_t)(aRow0 + mt * 16) * 128;
                ldsm4(ah[mt], rb + cH);
                ldsm4(al[mt], rb + cL);
            }
#pragma unroll
            for (int p = 0; p < 2; p++) {
                uint32_t rb = Bs + (uint32_t)(bRow0 + p * 16) * 128;
                ldsm4(bh[p], rb + cH);
                ldsm4(bl[p], rb + cL);
            }
#pragma unroll
            for (int nt = 0; nt < 4; nt++) {
                const int p = nt >> 1, o = nt & 1;
                const uint32_t b0h = bh[p][o], b1h = bh[p][o + 2];
                const uint32_t b0l = bl[p][o], b1l = bl[p][o + 2];
#pragma unroll
                for (int mt = 0; mt < 4; mt++) {
                    mma16816(acc[mt][nt], ah[mt], b0h, b1h);
                    mma16816(acc[mt][nt], ah[mt], b0l, b1l);
                    mma16816(acc[mt][nt], al[mt], b0h, b1h);
                }
            }
        }
        __syncthreads();
        if (kt + 2 < nk) load_stage((kt + 2) % BK_STAGES, kt + 2);
        cp_commit();
    }

    const int r_ep = lane >> 2, c_ep = lane & 3;
#pragma unroll
    for (int mt = 0; mt < 4; mt++) {
        const int m0 = bm + wm * 64 + mt * 16 + r_ep;
#pragma unroll
        for (int nt = 0; nt < 4; nt++) {
            const int n0 = bn + wn * 32 + nt * 8 + 2 * c_ep;   // always even
#pragma unroll
            for (int half = 0; half < 2; half++) {
                const int m = m0 + half * 8;
                if (n0 < N) {
                    float v0 = acc[mt][nt][half * 2 + 0];
                    float v1 = acc[mt][nt][half * 2 + 1];
                    if (bp) { v0 += bp[n0]; v1 += bp[n0 + 1]; }
                    if (EPI == 1)      { v0 = geluf(v0);     v1 = geluf(v1); }
                    else if (EPI == 3) { v0 = softplusf(v0); v1 = softplusf(v1); }
                    else if (EPI == 4) {
                        const float* ar = aux + (size_t)(m % auxMod) * ldc;
                        v0 += ar[n0]; v1 += ar[n0 + 1];
                    } else if (EPI == 5) {
                        const float* ar = aux + (size_t)m * ldc;
                        v0 += ar[n0]; v1 += ar[n0 + 1];
                    }
                    if (OUT != 2) {
                        float2 f2; f2.x = v0; f2.y = v1;
                        *(float2*)(C + (size_t)m * ldc + n0) = f2;
                    }
                    if (OUT != 0) {
                        size_t o = (size_t)m * ldch + n0;
                        split2_store(Ch + o, Ch + planeC + o, v0, v1);
                    }
                }
            }
        }
    }
}

// ---------------- mma.sync GEMM 64x128 (small shapes, vectorized epilogue) ----------------
#define SMEM64_BYTES (3*24576)

template<int EPI, int OUT>
__global__ void __launch_bounds__(256, 2)
bgemm64(const bf16* __restrict__ Ah, const bf16* __restrict__ Al, int lda, long long sA,
        const bf16* __restrict__ Bh, const bf16* __restrict__ Bl, int ldb, long long sB,
        float* __restrict__ C, int ldc, long long sC,
        bf16* __restrict__ Ch, long long planeC, int ldch, long long sCh,
        const float* __restrict__ bias, long long sBias,
        const float* __restrict__ aux, int auxMod,
        int M, int N, int K)
{
    extern __shared__ char smd[];
    const int zi = blockIdx.z;
    Ah += (size_t)zi * sA; Al += (size_t)zi * sA;
    Bh += (size_t)zi * sB; Bl += (size_t)zi * sB;
    if (OUT != 2) C += (size_t)zi * sC;
    if (OUT != 0) Ch += (size_t)zi * sCh;
    const float* bp = bias ? (bias + (size_t)zi * sBias) : nullptr;

    const int bm = blockIdx.y * 64;
    const int bn = blockIdx.x * 128;
    const int tid = threadIdx.x, lane = tid & 31, warp = tid >> 5;
    const int wm = warp & 1, wn = warp >> 1;

    const uint32_t smem_base = (uint32_t)__cvta_generic_to_shared(smd);

    auto load_stage = [&](int s, int kt) {
        const int k0 = kt * 32;
        const uint32_t As = smem_base + s * 24576;
        const uint32_t Bs = As + 8192;
#pragma unroll
        for (int i = 0; i < 2; i++) {
            int lin = i * 256 + tid;
            int row = lin >> 3, ch = lin & 7;
            const bf16* srcA = ((ch & 4) ? Al : Ah) + (size_t)(bm + row) * lda + k0 + (ch & 3) * 8;
            cp16(As + row * 128 + ((ch ^ (row & 7)) * 16), srcA, true);
        }
#pragma unroll
        for (int i = 0; i < 4; i++) {
            int lin = i * 256 + tid;
            int row = lin >> 3, ch = lin & 7;
            bool ok = (bn + row) < N;
            const bf16* srcB = ((ch & 4) ? Bl : Bh) +
                               (ok ? ((size_t)(bn + row) * ldb + k0 + (ch & 3) * 8) : 0);
            cp16(Bs + row * 128 + ((ch ^ (row & 7)) * 16), srcB, ok);
        }
    };

    float acc[2][4][4];
#pragma unroll
    for (int i = 0; i < 2; i++)
#pragma unroll
        for (int j = 0; j < 4; j++)
#pragma unroll
            for (int q = 0; q < 4; q++) acc[i][j][q] = 0.0f;

    const int nk = K / 32;
    if (nk > 0) load_stage(0, 0);
    cp_commit();
    if (nk > 1) load_stage(1, 1);
    cp_commit();

    const int g  = lane >> 3;
    const int lr = lane & 7;
    const int aRow0 = wm * 32 + (g & 1) * 8 + lr;
    const int bRow0 = wn * 32 + (g & 1) * 8 + lr;
    const int chHi  = (g >> 1);

    for (int kt = 0; kt < nk; kt++) {
        cp_wait1();
        __syncthreads();
        const uint32_t As = smem_base + (kt % 3) * 24576;
        const uint32_t Bs = As + 8192;

#pragma unroll
        for (int step = 0; step < 2; step++) {
            uint32_t ah[2][4], al[2][4], bh[2][4], bl[2][4];
            const int cH = ((step * 2 + chHi) ^ lr) * 16;
            const int cL = ((4 + step * 2 + chHi) ^ lr) * 16;
#pragma unroll
            for (int mt = 0; mt < 2; mt++) {
                uint32_t rb = As + (uint32_t)(aRow0 + mt * 16) * 128;
                ldsm4(ah[mt], rb + cH);
                ldsm4(al[mt], rb + cL);
            }
#pragma unroll
            for (int p = 0; p < 2; p++) {
                uint32_t rb = Bs + (uint32_t)(bRow0 + p * 16) * 128;
                ldsm4(bh[p], rb + cH);
                ldsm4(bl[p], rb + cL);
            }
#pragma unroll
            for (int nt = 0; nt < 4; nt++) {
                const int p = nt >> 1, o = nt & 1;
                const uint32_t b0h = bh[p][o], b1h = bh[p][o + 2];
                const uint32_t b0l = bl[p][o], b1l = bl[p][o + 2];
#pragma unroll
                for (int mt = 0; mt < 2; mt++) {
                    mma16816(acc[mt][nt], ah[mt], b0h, b1h);
                    mma16816(acc[mt][nt], ah[mt], b0l, b1l);
                    mma16816(acc[mt][nt], al[mt], b0h, b1h);
                }
            }
        }
        __syncthreads();
        if (kt + 2 < nk) load_stage((kt + 2) % 3, kt + 2);
        cp_commit();
    }

    const int r_ep = lane >> 2, c_ep = lane & 3;
#pragma unroll
    for (int mt = 0; mt < 2; mt++) {
        const int m0 = bm + wm * 32 + mt * 16 + r_ep;
#pragma unroll
        for (int nt = 0; nt < 4; nt++) {
            const int n0 = bn + wn * 32 + nt * 8 + 2 * c_ep;
#pragma unroll
            for (int half = 0; half < 2; half++) {
                const int m = m0 + half * 8;
                if (n0 < N) {
                    float v0 = acc[mt][nt][half * 2 + 0];
                    float v1 = acc[mt][nt][half * 2 + 1];
                    if (bp) { v0 += bp[n0]; v1 += bp[n0 + 1]; }
                    if (EPI == 1)      { v0 = geluf(v0);     v1 = geluf(v1); }
                    else if (EPI == 3) { v0 = softplusf(v0); v1 = softplusf(v1); }
                    else if (EPI == 4) {
                        const float* ar = aux + (size_t)(m % auxMod) * ldc;
                        v0 += ar[n0]; v1 += ar[n0 + 1];
                    } else if (EPI == 5) {
                        const float* ar = aux + (size_t)m * ldc;
                        v0 += ar[n0]; v1 += ar[n0 + 1];
                    }
                    if (OUT != 2) {
                        float2 f2; f2.x = v0; f2.y = v1;
                        *(float2*)(C + (size_t)m * ldc + n0) = f2;
                    }
                    if (OUT != 0) {
                        size_t o = (size_t)m * ldch + n0;
                        split2_store(Ch + o, Ch + planeC + o, v0, v1);
                    }
                }
            }
        }
    }
}

// ---------------- fused prepass ----------------
#define PRE_BLOCKS 23296

__global__ void fused_pre_k(
    const float* __restrict__ pos_w1, const float* __restrict__ pos_b1,
    const float* __restrict__ pos_w2, const float* __restrict__ mix_w,
    const float* __restrict__ m_out_w, const float* __restrict__ m_in_w,
    const float* __restrict__ m_xproj_w, const float* __restrict__ m_dt_w,
    const float* __restrict__ ffn_w1, const float* __restrict__ ffn_w2,
    bf16* __restrict__ wpos2, bf16* __restrict__ wpmix, bf16* __restrict__ wmixA,
    bf16* __restrict__ wTout, bf16* __restrict__ win, bf16* __restrict__ wxp,
    bf16* __restrict__ wdt, bf16* __restrict__ wf1, bf16* __restrict__ wf2,
    bf16* __restrict__ posh)
{
    const int bid = blockIdx.x, tid = threadIdx.x;
    bf16 h, l;
    if (bid < 1024) {
        int i = bid * 256 + tid;
        splitf(pos_w2[i], h, l); wpos2[i] = h; wpos2[262144 + i] = l;
    } else if (bid < 2048) {
        int i = (bid - 1024) * 256 + tid;
        int r = i >> 9, c = i & 511;
        splitf(mix_w[1024 + r * 1536 + c], h, l); wpmix[i] = h; wpmix[262144 + i] = l;
    } else if (bid < 3072) {
        int i = (bid - 2048) * 256 + tid;
        int r = i >> 9, c = i & 511;
        splitf(mix_w[r * 1536 + c], h, l); wmixA[i] = h; wmixA[524288 + i] = l;
    } else if (bid < 4096) {
        int i = (bid - 3072) * 256 + tid;
        int r = i >> 9, c = i & 511;
        splitf(mix_w[512 + r * 1536 + c], h, l);
        wmixA[262144 + i] = h; wmixA[524288 + 262144 + i] = l;
    } else if (bid < 6144) {
        int i = (bid - 4096) * 256 + tid;
        int e = i >> 9, j = i & 511;
        splitf(m_out_w[(size_t)j * 1024 + e], h, l);
        wTout[i] = h; wTout[1048576 + i] = l;
    } else if (bid < 8192) {
        int i = (bid - 6144) * 256 + tid;
        int e = i >> 9, j = i & 511;
        splitf(m_out_w[524288 + (size_t)j * 1024 + e], h, l);
        wTout[524288 + i] = h; wTout[1048576 + 524288 + i] = l;
    } else if (bid < 16384) {
        int i = (bid - 8192) * 256 + tid;
        splitf(m_in_w[i], h, l); win[i] = h; win[2097152 + i] = l;
    } else if (bid < 16896) {
        int i = (bid - 16384) * 256 + tid;
        splitf(m_xproj_w[i], h, l); wxp[i] = h; wxp[131072 + i] = l;
    } else if (bid < 17152) {
        int i = (bid - 16896) * 256 + tid;
        splitf(m_dt_w[i], h, l); wdt[i] = h; wdt[65536 + i] = l;
    } else if (bid < 19200) {
        int i = (bid - 17152) * 256 + tid;
        splitf(ffn_w1[i], h, l); wf1[i] = h; wf1[524288 + i] = l;
    } else if (bid < 21248) {
        int i = (bid - 19200) * 256 + tid;
        splitf(ffn_w2[i], h, l); wf2[i] = h; wf2[524288 + i] = l;
    } else {
        int i = (bid - 21248) * 256 + tid;
        int t = i >> 9, c = i & 511;
        int y = t >> 5, x = t & 31;
        const float PI = 3.14159265358979323846f;
        float yy = ((y + 0.5f) / 32.0f) * 2.0f - 1.0f;
        float xx = ((x + 0.5f) / 32.0f) * 2.0f - 1.0f;
        float f2 = sinf(PI * yy), f3 = cosf(PI * yy);
        float f4 = sinf(PI * xx), f5 = cosf(PI * xx);
        const float* w = pos_w1 + c * 6;
        float v = pos_b1[c] + yy * w[0] + xx * w[1] + f2 * w[2] + f3 * w[3] + f4 * w[4] + f5 * w[5];
        v = geluf(v);
        splitf(v, h, l); posh[i] = h; posh[524288 + i] = l;
    }
}

// ---------------- LN(tokens) + pos -> hi/lo ----------------
__global__ void ln_add_pos_k(const float* __restrict__ x,
                             const float* __restrict__ g, const float* __restrict__ b,
                             const float* __restrict__ pos, bf16* __restrict__ out)
{
    __shared__ float sh[16];
    const int row = blockIdx.x;
    const int tid = threadIdx.x;
    float4 v = ((const float4*)(x + (size_t)row * DIM))[tid];
    float s = v.x + v.y + v.z + v.w;
    float q = v.x * v.x + v.y * v.y + v.z * v.z + v.w * v.w;
#pragma unroll
    for (int o = 16; o; o >>= 1) {
        s += __shfl_xor_sync(0xffffffffu, s, o);
        q += __shfl_xor_sync(0xffffffffu, q, o);
    }
    if ((tid & 31) == 0) { sh[tid >> 5] = s; sh[4 + (tid >> 5)] = q; }
    __syncthreads();
    if (tid == 0) {
        float S = sh[0] + sh[1] + sh[2] + sh[3];
        float Q = sh[4] + sh[5] + sh[6] + sh[7];
        float mu = S * (1.0f / DIM);
        float var = Q * (1.0f / DIM) - mu * mu;
        sh[8] = mu; sh[9] = rsqrtf(var + 1e-5f);
    }
    __syncthreads();
    const float mu = sh[8], rs = sh[9];
    const int t = row & (LSEQ - 1);
    float4 g4 = ((const float4*)g)[tid];
    float4 b4 = ((const float4*)b)[tid];
    float4 p4 = ((const float4*)(pos + (size_t)t * DIM))[tid];
    float4 r;
    r.x = (v.x - mu) * rs * g4.x + b4.x + p4.x;
    r.y = (v.y - mu) * rs * g4.y + b4.y + p4.y;
    r.z = (v.z - mu) * rs * g4.z + b4.z + p4.z;
    r.w = (v.w - mu) * rs * g4.w + b4.w + p4.w;
    bf16* ph = out + (size_t)row * DIM + tid * 4;
    split4_store(ph, ph + (long long)ROWS * DIM, r);
}

// ---------------- causal conv + SiLU (reads hi/lo xz) ----------------
__global__ void conv_silu_k(const bf16* __restrict__ xzh,
                            const float* __restrict__ cw, const float* __restrict__ cb,
                            bf16* __restrict__ xch)
{
    size_t gidx = (size_t)blockIdx.x * 256 + threadIdx.x;
    int dq  = (int)(gidx & 255);
    int row = (int)((gidx >> 8) & (ROWS - 1));
    int dir = (int)(gidx >> 21);
    int d = dq * 4;
    int t = row & (LSEQ - 1);
    int b = row >> 10;

    float4 acc = *(const float4*)&cb[dir * DI + d];
    const float4* wrow = (const float4*)&cw[(size_t)(dir * DI + d) * 4];
    float4 w0 = wrow[0], w1 = wrow[1], w2 = wrow[2], w3 = wrow[3];

#pragma unroll
    for (int k = 0; k < 4; k++) {
        int off = dir ? (3 - k) : (k - 3);
        int tt = t + off;
        if (tt >= 0 && tt < LSEQ) {
            float4 v = hl4(xzh, XZPLANE, ((size_t)(b * LSEQ + tt)) * 4096 + dir * 2048 + d);
            acc.x = fmaf(fcomp(w0, k), v.x, acc.x);
            acc.y = fmaf(fcomp(w1, k), v.y, acc.y);
            acc.z = fmaf(fcomp(w2, k), v.z, acc.z);
            acc.w = fmaf(fcomp(w3, k), v.w, acc.w);
        }
    }
    float4 r;
    r.x = siluf(acc.x); r.y = siluf(acc.y); r.z = siluf(acc.z); r.w = siluf(acc.w);
    bf16* ph = xch + gidx * 4;
    split4_store(ph, ph + XPLANE, r);
}

// ================= chunked selective scan =================
__global__ void scan_part1_k(const bf16* __restrict__ dsph, const bf16* __restrict__ xch,
                             const float* __restrict__ proj, const float* __restrict__ A_log,
                             float* __restrict__ hend, float* __restrict__ prodv)
{
    const int chunk = blockIdx.x >> 3;
    const int dblk  = blockIdx.x & 7;
    const int b = blockIdx.y, dir = blockIdx.z;
    const int d = dblk * 128 + threadIdx.x;

    float a[DS];
    bool fast = true;
#pragma unroll
    for (int s = 0; s < DS; s++) {
        a[s] = -expf(A_log[((size_t)dir * DI + d) * DS + s]);
        fast = fast && (fabsf(a[s] + (float)(s + 1)) < 1e-4f * (float)(s + 1));
    }

    const size_t base_row = (size_t)dir * ROWS + (size_t)b * LSEQ;
    __shared__ float sB[CLEN][DS];
    for (int i = threadIdx.x; i < CLEN * DS; i += 128) {
        int st = chunk * CLEN + (i >> 4);
        int c = i & 15;
        int r = dir ? (LSEQ - 1 - st) : st;
        sB[i >> 4][c] = proj[(base_row + r) * 64 + 32 + c];
    }
    __syncthreads();

    float h[DS], p[DS];
#pragma unroll
    for (int s = 0; s < DS; s++) h[s] = 0.0f;

    if (fast) {
        float prodE1 = 1.0f;
        for (int i = 0; i < CLEN; i++) {
            int st = chunk * CLEN + i;
            int r = dir ? (LSEQ - 1 - st) : st;
            size_t ro = (base_row + r) * (size_t)DI + d;
            float delta = hlval(dsph, DSPLANE, ro);
            float x     = hlval(xch, XPLANE, ro);
            float dx    = delta * x;
            float e1 = __expf(-delta);
            prodE1 *= e1;
            float ep = e1;
#pragma unroll
            for (int s = 0; s < DS; s++) {
                h[s] = fmaf(h[s], ep, dx * sB[i][s]);
                ep *= e1;
            }
        }
        float ep = prodE1;
#pragma unroll
        for (int s = 0; s < DS; s++) { p[s] = ep; ep *= prodE1; }
    } else {
#pragma unroll
        for (int s = 0; s < DS; s++) p[s] = 1.0f;
        for (int i = 0; i < CLEN; i++) {
            int st = chunk * CLEN + i;
            int r = dir ? (LSEQ - 1 - st) : st;
            size_t ro = (base_row + r) * (size_t)DI + d;
            float delta = hlval(dsph, DSPLANE, ro);
            float x     = hlval(xch, XPLANE, ro);
            float dx    = delta * x;
#pragma unroll
            for (int s = 0; s < DS; s++) {
                float e = __expf(delta * a[s]);
                h[s] = fmaf(h[s], e, dx * sB[i][s]);
                p[s] *= e;
            }
        }
    }

    const int CH = (dir * BATCH + b) * DI + d;
    size_t o = ((size_t)chunk * NCH + CH) * DS;
#pragma unroll
    for (int s = 0; s < DS; s++) { hend[o + s] = h[s]; prodv[o + s] = p[s]; }
}

__global__ void scan_part2_k(const float* __restrict__ hend, const float* __restrict__ prodv,
                             float* __restrict__ hinit)
{
    int idx = blockIdx.x * 256 + threadIdx.x;
    if (idx >= NCH * DS) return;
    float H = 0.0f;
#pragma unroll 4
    for (int c = 0; c < NCHUNK; c++) {
        size_t o = (size_t)c * (NCH * DS) + idx;
        hinit[o] = H;
        H = fmaf(prodv[o], H, hend[o]);
    }
}

__global__ void scan_part3_k(const bf16* __restrict__ dsph, const bf16* __restrict__ xch,
                             const float* __restrict__ proj, const bf16* __restrict__ xzh,
                             const float* __restrict__ A_log, const float* __restrict__ Dp,
                             const float* __restrict__ hinit, bf16* __restrict__ ycat)
{
    const int chunk = blockIdx.x >> 3;
    const int dblk  = blockIdx.x & 7;
    const int b = blockIdx.y, dir = blockIdx.z;
    const int d = dblk * 128 + threadIdx.x;

    float a[DS];
    bool fast = true;
#pragma unroll
    for (int s = 0; s < DS; s++) {
        a[s] = -expf(A_log[((size_t)dir * DI + d) * DS + s]);
        fast = fast && (fabsf(a[s] + (float)(s + 1)) < 1e-4f * (float)(s + 1));
    }
    const float Dv = Dp[dir * DI + d];

    const size_t base_row = (size_t)dir * ROWS + (size_t)b * LSEQ;
    const long long plane = (long long)ROWS * 2048;
    __shared__ float sBC[CLEN][32];
    for (int i = threadIdx.x; i < CLEN * 32; i += 128) {
        int st = chunk * CLEN + (i >> 5);
        int c = i & 31;
        int r = dir ? (LSEQ - 1 - st) : st;
        sBC[i >> 5][c] = proj[(base_row + r) * 64 + 32 + c];
    }
    __syncthreads();

    const int CH = (dir * BATCH + b) * DI + d;
    size_t ho = ((size_t)chunk * NCH + CH) * DS;
    float h[DS];
#pragma unroll
    for (int s = 0; s < DS; s++) h[s] = hinit[ho + s];

    if (fast) {
        for (int i = 0; i < CLEN; i++) {
            int st = chunk * CLEN + i;
            int r = dir ? (LSEQ - 1 - st) : st;
            size_t ro = (base_row + r) * (size_t)DI + d;
            float delta = hlval(dsph, DSPLANE, ro);
            float x     = hlval(xch, XPLANE, ro);
            float dx    = delta * x;
            float y = 0.0f;
            float e1 = __expf(-delta);
            float ep = e1;
#pragma unroll
            for (int s = 0; s < DS; s++) {
                h[s] = fmaf(h[s], ep, dx * sBC[i][s]);
                y = fmaf(h[s], sBC[i][16 + s], y);
                ep *= e1;
            }
            float z = hlval(xzh, XZPLANE, ((size_t)(b * LSEQ + r)) * 4096 + dir * 2048 + DI + d);
            float outv = (y + x * Dv) * siluf(z);
            bf16 hh, ll; splitf(outv, hh, ll);
            size_t oo = ((size_t)(b * LSEQ + r)) * 2048 + dir * DI + d;
            ycat[oo] = hh; ycat[plane + oo] = ll;
        }
    } else {
        for (int i = 0; i < CLEN; i++) {
            int st = chunk * CLEN + i;
            int r = dir ? (LSEQ - 1 - st) : st;
            size_t ro = (base_row + r) * (size_t)DI + d;
            float delta = hlval(dsph, DSPLANE, ro);
            float x     = hlval(xch, XPLANE, ro);
            float dx    = delta * x;
            float y = 0.0f;
#pragma unroll
            for (int s = 0; s < DS; s++) {
                float e = __expf(delta * a[s]);
                h[s] = fmaf(h[s], e, dx * sBC[i][s]);
                y = fmaf(h[s], sBC[i][16 + s], y);
            }
            float z = hlval(xzh, XZPLANE, ((size_t)(b * LSEQ + r)) * 4096 + dir * 2048 + DI + d);
            float outv = (y + x * Dv) * siluf(z);
            bf16 hh, ll; splitf(outv, hh, ll);
            size_t oo = ((size_t)(b * LSEQ + r)) * 2048 + dir * DI + d;
            ycat[oo] = hh; ycat[plane + oo] = ll;
        }
    }
}

// ---------------- dual LayerNorm ----------------
__global__ void ln_dual_k(const float* __restrict__ in,
                          const float* __restrict__ g1, const float* __restrict__ b1,
                          const float* __restrict__ g2, const float* __restrict__ b2,
                          float* __restrict__ out1, bf16* __restrict__ out2)
{
    __shared__ float sh[16];
    const int row = blockIdx.x;
    const int tid = threadIdx.x;
    float4 v = ((const float4*)(in + (size_t)row * DIM))[tid];
    float s = v.x + v.y + v.z + v.w;
    float q = v.x * v.x + v.y * v.y + v.z * v.z + v.w * v.w;
#pragma unroll
    for (int o = 16; o; o >>= 1) {
        s += __shfl_xor_sync(0xffffffffu, s, o);
        q += __shfl_xor_sync(0xffffffffu, q, o);
    }
    if ((tid & 31) == 0) { sh[tid >> 5] = s; sh[4 + (tid >> 5)] = q; }
    __syncthreads();
    if (tid == 0) {
        float S = sh[0] + sh[1] + sh[2] + sh[3];
        float Q = sh[4] + sh[5] + sh[6] + sh[7];
        float mu = S * (1.0f / DIM);
        float var = Q * (1.0f / DIM) - mu * mu;
        sh[8] = mu; sh[9] = rsqrtf(var + 1e-5f);
    }
    __syncthreads();
    float mu = sh[8], rs = sh[9];
    float4 g4 = ((const float4*)g1)[tid];
    float4 b4 = ((const float4*)b1)[tid];
    float4 x4;
    x4.x = (v.x - mu) * rs * g4.x + b4.x;
    x4.y = (v.y - mu) * rs * g4.y + b4.y;
    x4.z = (v.z - mu) * rs * g4.z + b4.z;
    x4.w = (v.w - mu) * rs * g4.w + b4.w;
    ((float4*)(out1 + (size_t)row * DIM))[tid] = x4;

    __syncthreads();
    s = x4.x + x4.y + x4.z + x4.w;
    q = x4.x * x4.x + x4.y * x4.y + x4.z * x4.z + x4.w * x4.w;
#pragma unroll
    for (int o = 16; o; o >>= 1) {
        s += __shfl_xor_sync(0xffffffffu, s, o);
        q += __shfl_xor_sync(0xffffffffu, q, o);
    }
    if ((tid & 31) == 0) { sh[tid >> 5] = s; sh[4 + (tid >> 5)] = q; }
    __syncthreads();
    if (tid == 0) {
        float S = sh[0] + sh[1] + sh[2] + sh[3];
        float Q = sh[4] + sh[5] + sh[6] + sh[7];
        float mu2 = S * (1.0f / DIM);
        float var2 = Q * (1.0f / DIM) - mu2 * mu2;
        sh[8] = mu2; sh[9] = rsqrtf(var2 + 1e-5f);
    }
    __syncthreads();
    float mu2 = sh[8], rs2 = sh[9];
    float4 G = ((const float4*)g2)[tid];
    float4 B = ((const float4*)b2)[tid];
    float4 r;
    r.x = (x4.x - mu2) * rs2 * G.x + B.x;
    r.y = (x4.y - mu2) * rs2 * G.y + B.y;
    r.z = (x4.z - mu2) * rs2 * G.z + B.z;
    r.w = (x4.w - mu2) * rs2 * G.w + B.w;
    bf16* ph = out2 + (size_t)row * DIM + tid * 4;
    split4_store(ph, ph + (long long)ROWS * DIM, r);
}

// ---------------- host launcher ----------------
extern "C" void kernel_launch(void* const* d_in, const int* in_sizes, int n_in,
                              void* d_out, int out_size)
{
    const float* tokens    = (const float*)d_in[0];
    const float* in_g      = (const float*)d_in[3];
    const float* in_b      = (const float*)d_in[4];
    const float* pos_w1    = (const float*)d_in[5];
    const float* pos_b1    = (const float*)d_in[6];
    const float* pos_w2    = (const float*)d_in[7];
    const float* pos_b2    = (const float*)d_in[8];
    const float* m_in_w    = (const float*)d_in[9];
    const float* m_conv_w  = (const float*)d_in[10];
    const float* m_conv_b  = (const float*)d_in[11];
    const float* m_xproj_w = (const float*)d_in[12];
    const float* m_dt_w    = (const float*)d_in[13];
    const float* m_dt_b    = (const float*)d_in[14];
    const float* m_A_log   = (const float*)d_in[15];
    const float* m_D       = (const float*)d_in[16];
    const float* m_out_w   = (const float*)d_in[17];
    const float* mix_w     = (const float*)d_in[18];
    const float* mix_b     = (const float*)d_in[19];
    const float* dn_g      = (const float*)d_in[20];
    const float* dn_b      = (const float*)d_in[21];
    const float* fn_g      = (const float*)d_in[22];
    const float* fn_b      = (const float*)d_in[23];
    const float* ffn_w1    = (const float*)d_in[24];
    const float* ffn_b1    = (const float*)d_in[25];
    const float* ffn_w2    = (const float*)d_in[26];
    const float* ffn_b2    = (const float*)d_in[27];
    float* out = (float*)d_out;

    float *pos, *pos_mix, *proj, *dmix, *dln, *hend, *prodv, *hinit;
    bf16 *sin_hl, *posh_hl, *pos_hl, *wpos2, *wpmix, *wmixA, *wTout, *win, *wxp, *wdt, *wf1, *wf2;
    bf16 *xzh, *dsph, *xc_hl, *proj_hl, *ycat_hl, *wc_hl, *lnf_hl, *h1_hl;
    cudaGetSymbolAddress((void**)&pos,     g_pos);
    cudaGetSymbolAddress((void**)&pos_mix, g_pos_mix);
    cudaGetSymbolAddress((void**)&proj,    g_proj);
    cudaGetSymbolAddress((void**)&dmix,    g_dmix);
    cudaGetSymbolAddress((void**)&dln,     g_dln);
    cudaGetSymbolAddress((void**)&hend,    g_hend);
    cudaGetSymbolAddress((void**)&prodv,   g_prod);
    cudaGetSymbolAddress((void**)&hinit,   g_hinit);
    cudaGetSymbolAddress((void**)&sin_hl,  hl_scan_in);
    cudaGetSymbolAddress((void**)&posh_hl, hl_pos_h);
    cudaGetSymbolAddress((void**)&pos_hl,  hl_pos);
    cudaGetSymbolAddress((void**)&wpos2,   hl_w_pos2);
    cudaGetSymbolAddress((void**)&wpmix,   hl_w_pmix);
    cudaGetSymbolAddress((void**)&wmixA,   hl_w_mixA);
    cudaGetSymbolAddress((void**)&wTout,   hl_wT_out);
    cudaGetSymbolAddress((void**)&win,     hl_w_in);
    cudaGetSymbolAddress((void**)&wxp,     hl_w_xp);
    cudaGetSymbolAddress((void**)&wdt,     hl_w_dt);
    cudaGetSymbolAddress((void**)&wf1,     hl_w_f1);
    cudaGetSymbolAddress((void**)&wf2,     hl_w_f2);
    cudaGetSymbolAddress((void**)&xzh,     hl_xz);
    cudaGetSymbolAddress((void**)&dsph,    hl_dsp);
    cudaGetSymbolAddress((void**)&xc_hl,   hl_xc);
    cudaGetSymbolAddress((void**)&proj_hl, hl_proj);
    cudaGetSymbolAddress((void**)&ycat_hl, hl_ycat);
    cudaGetSymbolAddress((void**)&wc_hl,   hl_wc);
    cudaGetSymbolAddress((void**)&lnf_hl,  hl_lnf);
    cudaGetSymbolAddress((void**)&h1_hl,   hl_h1);

    cudaFuncSetAttribute(bgemm<0,2>, cudaFuncAttributeMaxDynamicSharedMemorySize, SMEM_BYTES);
    cudaFuncSetAttribute(bgemm<4,0>, cudaFuncAttributeMaxDynamicSharedMemorySize, SMEM_BYTES);
    cudaFuncSetAttribute(bgemm<1,2>, cudaFuncAttributeMaxDynamicSharedMemorySize, SMEM_BYTES);
    cudaFuncSetAttribute(bgemm<5,0>, cudaFuncAttributeMaxDynamicSharedMemorySize, SMEM_BYTES);
    cudaFuncSetAttribute(bgemm64<0,0>, cudaFuncAttributeMaxDynamicSharedMemorySize, SMEM64_BYTES);
    cudaFuncSetAttribute(bgemm64<0,1>, cudaFuncAttributeMaxDynamicSharedMemorySize, SMEM64_BYTES);
    cudaFuncSetAttribute(bgemm64<0,2>, cudaFuncAttributeMaxDynamicSharedMemorySize, SMEM64_BYTES);
    cudaFuncSetAttribute(bgemm64<3,2>, cudaFuncAttributeMaxDynamicSharedMemorySize, SMEM64_BYTES);

    // 1: fused converts + pos_hidden
    fused_pre_k<<<PRE_BLOCKS, 256>>>(pos_w1, pos_b1, pos_w2, mix_w, m_out_w, m_in_w,
                                     m_xproj_w, m_dt_w, ffn_w1, ffn_w2,
                                     wpos2, wpmix, wmixA, wTout, win, wxp, wdt, wf1, wf2,
                                     posh_hl);
    // 2: pos = gelu_h @ pos_w2^T + b2
    bgemm64<0,1><<<dim3(4,16,1), 256, SMEM64_BYTES>>>(
        posh_hl, posh_hl + LSEQ*DIM, 512, 0,  wpos2, wpos2 + 512*512, 512, 0,
        pos, 512, 0,  pos_hl, (long long)LSEQ*DIM, 512, 0,
        pos_b2, 0, nullptr, 1, LSEQ, 512, 512);
    // 3: scan_in = LN(tokens) + pos
    ln_add_pos_k<<<ROWS, 128>>>(tokens, in_g, in_b, pos, sin_hl);
    // 4: xz = scan_in @ in_w^T -> hi/lo bf16 (vectorized epilogue)  <-- profiled slot
    bgemm<0,2><<<dim3(32,64,1), 256, SMEM_BYTES>>>(
        sin_hl, sin_hl + (long long)ROWS*DIM, 512, 0,
        win, win + (long long)4096*512, 512, 0,
        nullptr, 4096, 0,
        xzh, (long long)XZPLANE, 4096, 0,
        nullptr, 0, nullptr, 1, ROWS, 4096, 512);

    conv_silu_k<<<(2*ROWS*DI)/1024, 256>>>(xzh, m_conv_w, m_conv_b, xc_hl);
    // proj = xc @ xproj^T per dir
    bgemm64<0,1><<<dim3(1,128,2), 256, SMEM64_BYTES>>>(
        xc_hl, xc_hl + (long long)2*ROWS*DI, 1024, (long long)ROWS*DI,
        wxp, wxp + (long long)128*1024, 1024, (long long)64*1024,
        proj, 64, (long long)ROWS*64,
        proj_hl, (long long)2*ROWS*64, 64, (long long)ROWS*64,
        nullptr, 0, nullptr, 1, ROWS, 64, 1024);
    // dsp = softplus(dt @ dt_w^T + dt_b) -> hi/lo bf16
    bgemm64<3,2><<<dim3(8,128,2), 256, SMEM64_BYTES>>>(
        proj_hl, proj_hl + (long long)2*ROWS*64, 64, (long long)ROWS*64,
        wdt, wdt + (long long)2048*32, 32, (long long)1024*32,
        nullptr, 1024, 0,
        dsph, (long long)DSPLANE, 1024, (long long)ROWS*DI,
        m_dt_b, 1024, nullptr, 1, ROWS, 1024, 32);

    // chunked scan
    scan_part1_k<<<dim3(8*NCHUNK, BATCH, 2), 128>>>(dsph, xc_hl, proj, m_A_log, hend, prodv);
    scan_part2_k<<<(NCH*DS)/256, 256>>>(hend, prodv, hinit);
    scan_part3_k<<<dim3(8*NCHUNK, BATCH, 2), 128>>>(dsph, xc_hl, proj, xzh, m_A_log, m_D, hinit, ycat_hl);

    // pos_mix = pos @ mix_w[:,1024:1536]^T + mix_b
    bgemm64<0,0><<<dim3(4,16,1), 256, SMEM64_BYTES>>>(
        pos_hl, pos_hl + LSEQ*DIM, 512, 0,  wpmix, wpmix + 512*512, 512, 0,
        pos_mix, 512, 0,  nullptr, 0, 0, 0,
        mix_b, 0, nullptr, 1, LSEQ, 512, 512);
    // Wc[dir] = mix_w_slice @ out_w[dir]
    bgemm64<0,2><<<dim3(8,8,2), 256, SMEM64_BYTES>>>(
        wmixA, wmixA + (long long)2*512*512, 512, (long long)512*512,
        wTout, wTout + (long long)2*1024*512, 512, (long long)1024*512,
        nullptr, 0, 0,
        wc_hl, (long long)512*2048, 2048, 1024,
        nullptr, 0, nullptr, 1, 512, 1024, 512);
    // dmix = ycat @ Wc^T + pos_mix
    bgemm<4,0><<<dim3(4,64,1), 256, SMEM_BYTES>>>(
        ycat_hl, ycat_hl + (long long)ROWS*2048, 2048, 0,
        wc_hl, wc_hl + (long long)512*2048, 2048, 0,
        dmix, 512, 0, nullptr, 0, 0, 0,
        nullptr, 0, pos_mix, LSEQ, ROWS, 512, 2048);
    ln_dual_k<<<ROWS, 128>>>(dmix, dn_g, dn_b, fn_g, fn_b, dln, lnf_hl);
    bgemm<1,2><<<dim3(8,64,1), 256, SMEM_BYTES>>>(
        lnf_hl, lnf_hl + (long long)ROWS*DIM, 512, 0,
        wf1, wf1 + (long long)1024*512, 512, 0,
        nullptr, 1024, 0,
        h1_hl, (long long)ROWS*HID, 1024, 0,
        ffn_b1, 0, nullptr, 1, ROWS, 1024, 512);
    bgemm<5,0><<<dim3(4,64,1), 256, SMEM_BYTES>>>(
        h1_hl, h1_hl + (long long)ROWS*HID, 1024, 0,
        wf2, wf2 + (long long)512*1024, 1024, 0,
        out, 512, 0, nullptr, 0, 0, 0,
        ffn_b2, 0, dln, 1, ROWS, 512, 1024);

    (void)in_sizes; (void)n_in; (void)out_size;
}

// round 15
// speedup vs baseline: 1.1558x; 1.0566x over previous
#include <cuda_runtime.h>
#include <cuda_bf16.h>
#include <cstdint>
#include <math.h>

#define BATCH 8
#define LSEQ  1024
#define DIM   512
#define DI    1024
#define DS    16
#define HID   1024
#define ROWS  (BATCH*LSEQ)    // 8192
#define NCHUNK 32
#define CLEN   32
#define NCH    16384
#define XPLANE ((size_t)2*ROWS*DI)

typedef __nv_bfloat16 bf16;

// ---------------- fp32 scratch ----------------
__device__ float g_pos    [LSEQ*DIM];
__device__ float g_pos_mix[LSEQ*DIM];
__device__ float g_xz     [ROWS*4096];
__device__ float g_proj   [2*ROWS*64];
__device__ float g_dsp    [2*ROWS*DI];
__device__ float g_dmix   [ROWS*DIM];
__device__ float g_dln    [ROWS*DIM];
__device__ float g_hend [NCHUNK*NCH*DS];
__device__ float g_prod [NCHUNK*NCH*DS];
__device__ float g_hinit[NCHUNK*NCH*DS];

// ---------------- bf16 hi/lo scratch ----------------
__device__ __align__(16) bf16 hl_scan_in[2*ROWS*DIM];
__device__ __align__(16) bf16 hl_pos_h  [2*LSEQ*DIM];
__device__ __align__(16) bf16 hl_pos    [2*LSEQ*DIM];
__device__ __align__(16) bf16 hl_w_pos2 [2*DIM*DIM];
__device__ __align__(16) bf16 hl_w_pmix [2*DIM*DIM];
__device__ __align__(16) bf16 hl_w_mixA [2*2*DIM*DIM];
__device__ __align__(16) bf16 hl_wT_out [2*2*DI*DIM];
__device__ __align__(16) bf16 hl_w_in   [2*4096*DIM];
__device__ __align__(16) bf16 hl_w_xp   [2*2*64*DI];
__device__ __align__(16) bf16 hl_w_dt   [2*2*DI*32];
__device__ __align__(16) bf16 hl_w_f1   [2*HID*DIM];
__device__ __align__(16) bf16 hl_w_f2   [2*DIM*HID];
__device__ __align__(16) bf16 hl_xc     [2*2*ROWS*DI];
__device__ __align__(16) bf16 hl_proj   [2*2*ROWS*64];
__device__ __align__(16) bf16 hl_ycat   [2*ROWS*2048];
__device__ __align__(16) bf16 hl_wc     [2*DIM*2048];
__device__ __align__(16) bf16 hl_lnf    [2*ROWS*DIM];
__device__ __align__(16) bf16 hl_h1     [2*ROWS*HID];

// ---------------- math helpers ----------------
__device__ __forceinline__ float geluf(float x) {
    return 0.5f * x * (1.0f + erff(x * 0.70710678118654752440f));
}
__device__ __forceinline__ float siluf(float x) { return x / (1.0f + __expf(-x)); }
__device__ __forceinline__ float softplusf(float x) { return (x > 20.0f) ? x : log1pf(__expf(x)); }
__device__ __forceinline__ void splitf(float v, bf16& h, bf16& l) {
    h = __float2bfloat16(v);
    l = __float2bfloat16(v - __bfloat162float(h));
}
__device__ __forceinline__ float fcomp(float4 f, int k) {
    return k == 0 ? f.x : (k == 1 ? f.y : (k == 2 ? f.z : f.w));
}
__device__ __forceinline__ void split4_store(bf16* ph, bf16* pl, float4 v) {
    bf16 h0, l0, h1, l1, h2, l2, h3, l3;
    splitf(v.x, h0, l0); splitf(v.y, h1, l1);
    splitf(v.z, h2, l2); splitf(v.w, h3, l3);
    __nv_bfloat162 a; a.x = h0; a.y = h1;
    __nv_bfloat162 b; b.x = h2; b.y = h3;
    __nv_bfloat162 c; c.x = l0; c.y = l1;
    __nv_bfloat162 d; d.x = l2; d.y = l3;
    *(__nv_bfloat162*)ph = a; *(__nv_bfloat162*)(ph + 2) = b;
    *(__nv_bfloat162*)pl = c; *(__nv_bfloat162*)(pl + 2) = d;
}
// packed pair hi/lo store (n must be 2-aligned)
__device__ __forceinline__ void split2_store(bf16* ph, bf16* pl, float v0, float v1) {
    bf16 h0, l0, h1, l1;
    splitf(v0, h0, l0); splitf(v1, h1, l1);
    __nv_bfloat162 hh; hh.x = h0; hh.y = h1;
    __nv_bfloat162 ll; ll.x = l0; ll.y = l1;
    *(__nv_bfloat162*)ph = hh;
    *(__nv_bfloat162*)pl = ll;
}
__device__ __forceinline__ float hlval(const bf16* p, size_t plane, size_t i) {
    return __bfloat162float(p[i]) + __bfloat162float(p[plane + i]);
}

// ---------------- PTX helpers ----------------
__device__ __forceinline__ void mma16816(float* d, const uint32_t* a, uint32_t b0, uint32_t b1) {
    asm volatile(
        "mma.sync.aligned.m16n8k16.row.col.f32.bf16.bf16.f32 "
        "{%0,%1,%2,%3},{%4,%5,%6,%7},{%8,%9},{%0,%1,%2,%3};\n"
        : "+f"(d[0]), "+f"(d[1]), "+f"(d[2]), "+f"(d[3])
        : "r"(a[0]), "r"(a[1]), "r"(a[2]), "r"(a[3]), "r"(b0), "r"(b1));
}
__device__ __forceinline__ void ldsm4(uint32_t* r, uint32_t addr) {
    asm volatile("ldmatrix.sync.aligned.m8n8.x4.shared.b16 {%0,%1,%2,%3}, [%4];\n"
                 : "=r"(r[0]), "=r"(r[1]), "=r"(r[2]), "=r"(r[3]) : "r"(addr));
}
__device__ __forceinline__ void cp16(uint32_t dst, const void* src, bool pred) {
    int sz = pred ? 16 : 0;
    asm volatile("cp.async.cg.shared.global [%0], [%1], 16, %2;\n"
                 :: "r"(dst), "l"(src), "r"(sz) : "memory");
}
__device__ __forceinline__ void cp_commit() { asm volatile("cp.async.commit_group;\n" ::: "memory"); }
__device__ __forceinline__ void cp_wait1()  { asm volatile("cp.async.wait_group 1;\n" ::: "memory"); }

// ---------------- mma.sync GEMM 128x128 (R12 structure + vectorized epilogue) ----------------
#define BK_STAGES 3
#define SMEM_BYTES (BK_STAGES*32768)

template<int EPI, int OUT>
__global__ void __launch_bounds__(256, 2)
bgemm(const bf16* __restrict__ Ah, const bf16* __restrict__ Al, int lda, long long sA,
      const bf16* __restrict__ Bh, const bf16* __restrict__ Bl, int ldb, long long sB,
      float* __restrict__ C, int ldc, long long sC,
      bf16* __restrict__ Ch, long long planeC, int ldch, long long sCh,
      const float* __restrict__ bias, long long sBias,
      const float* __restrict__ aux, int auxMod,
      int M, int N, int K)
{
    extern __shared__ char smd[];
    const int zi = blockIdx.z;
    Ah += (size_t)zi * sA; Al += (size_t)zi * sA;
    Bh += (size_t)zi * sB; Bl += (size_t)zi * sB;
    if (OUT != 2) C += (size_t)zi * sC;
    if (OUT != 0) Ch += (size_t)zi * sCh;
    const float* bp = bias ? (bias + (size_t)zi * sBias) : nullptr;

    const int bm = blockIdx.y * 128;
    const int bn = blockIdx.x * 128;
    const int tid = threadIdx.x, lane = tid & 31, warp = tid >> 5;
    const int wm = warp & 1, wn = warp >> 1;

    const uint32_t smem_base = (uint32_t)__cvta_generic_to_shared(smd);

    auto load_stage = [&](int s, int kt) {
        const int k0 = kt * 32;
        const uint32_t As = smem_base + s * 32768;
        const uint32_t Bs = As + 16384;
#pragma unroll
        for (int i = 0; i < 4; i++) {
            int lin = i * 256 + tid;
            int row = lin >> 3, ch = lin & 7;
            const bf16* srcA = ((ch & 4) ? Al : Ah) + (size_t)(bm + row) * lda + k0 + (ch & 3) * 8;
            cp16(As + row * 128 + ((ch ^ (row & 7)) * 16), srcA, true);
        }
#pragma unroll
        for (int i = 0; i < 4; i++) {
            int lin = i * 256 + tid;
            int row = lin >> 3, ch = lin & 7;
            bool ok = (bn + row) < N;
            const bf16* srcB = ((ch & 4) ? Bl : Bh) +
                               (ok ? ((size_t)(bn + row) * ldb + k0 + (ch & 3) * 8) : 0);
            cp16(Bs + row * 128 + ((ch ^ (row & 7)) * 16), srcB, ok);
        }
    };

    float acc[4][4][4];
#pragma unroll
    for (int i = 0; i < 4; i++)
#pragma unroll
        for (int j = 0; j < 4; j++)
#pragma unroll
            for (int q = 0; q < 4; q++) acc[i][j][q] = 0.0f;

    const int nk = K / 32;
    if (nk > 0) load_stage(0, 0);
    cp_commit();
    if (nk > 1) load_stage(1, 1);
    cp_commit();

    const int g  = lane >> 3;
    const int lr = lane & 7;
    const int aRow0 = wm * 64 + (g & 1) * 8 + lr;
    const int bRow0 = wn * 32 + (g & 1) * 8 + lr;
    const int chHi  = (g >> 1);

    for (int kt = 0; kt < nk; kt++) {
        cp_wait1();
        __syncthreads();
        const uint32_t As = smem_base + (kt % BK_STAGES) * 32768;
        const uint32_t Bs = As + 16384;

#pragma unroll
        for (int step = 0; step < 2; step++) {
            uint32_t ah[4][4], al[4][4], bh[2][4], bl[2][4];
            const int cH = ((step * 2 + chHi) ^ lr) * 16;
            const int cL = ((4 + step * 2 + chHi) ^ lr) * 16;
#pragma unroll
            for (int mt = 0; mt < 4; mt++) {
                uint32_t rb = As + (uint32_t)(aRow0 + mt * 16) * 128;
                ldsm4(ah[mt], rb + cH);
                ldsm4(al[mt], rb + cL);
            }
#pragma unroll
            for (int p = 0; p < 2; p++) {
                uint32_t rb = Bs + (uint32_t)(bRow0 + p * 16) * 128;
                ldsm4(bh[p], rb + cH);
                ldsm4(bl[p], rb + cL);
            }
#pragma unroll
            for (int nt = 0; nt < 4; nt++) {
                const int p = nt >> 1, o = nt & 1;
                const uint32_t b0h = bh[p][o], b1h = bh[p][o + 2];
                const uint32_t b0l = bl[p][o], b1l = bl[p][o + 2];
#pragma unroll
                for (int mt = 0; mt < 4; mt++) {
                    mma16816(acc[mt][nt], ah[mt], b0h, b1h);
                    mma16816(acc[mt][nt], ah[mt], b0l, b1l);
                    mma16816(acc[mt][nt], al[mt], b0h, b1h);
                }
            }
        }
        __syncthreads();
        if (kt + 2 < nk) load_stage((kt + 2) % BK_STAGES, kt + 2);
        cp_commit();
    }

    const int r_ep = lane >> 2, c_ep = lane & 3;
#pragma unroll
    for (int mt = 0; mt < 4; mt++) {
        const int m0 = bm + wm * 64 + mt * 16 + r_ep;
#pragma unroll
        for (int nt = 0; nt < 4; nt++) {
            const int n0 = bn + wn * 32 + nt * 8 + 2 * c_ep;   // always even
#pragma unroll
            for (int half = 0; half < 2; half++) {
                const int m = m0 + half * 8;
                if (n0 < N) {
                    float v0 = acc[mt][nt][half * 2 + 0];
                    float v1 = acc[mt][nt][half * 2 + 1];
                    if (bp) { v0 += bp[n0]; v1 += bp[n0 + 1]; }
                    if (EPI == 1)      { v0 = geluf(v0);     v1 = geluf(v1); }
                    else if (EPI == 3) { v0 = softplusf(v0); v1 = softplusf(v1); }
                    else if (EPI == 4) {
                        const float* ar = aux + (size_t)(m % auxMod) * ldc;
                        v0 += ar[n0]; v1 += ar[n0 + 1];
                    } else if (EPI == 5) {
                        const float* ar = aux + (size_t)m * ldc;
                        v0 += ar[n0]; v1 += ar[n0 + 1];
                    }
                    if (OUT != 2) {
                        float2 f2; f2.x = v0; f2.y = v1;
                        *(float2*)(C + (size_t)m * ldc + n0) = f2;
                    }
                    if (OUT != 0) {
                        size_t o = (size_t)m * ldch + n0;
                        split2_store(Ch + o, Ch + planeC + o, v0, v1);
                    }
                }
            }
        }
    }
}

// ---------------- mma.sync GEMM 64x128 (small shapes, vectorized epilogue) ----------------
#define SMEM64_BYTES (3*24576)

template<int EPI, int OUT>
__global__ void __launch_bounds__(256, 2)
bgemm64(const bf16* __restrict__ Ah, const bf16* __restrict__ Al, int lda, long long sA,
        const bf16* __restrict__ Bh, const bf16* __restrict__ Bl, int ldb, long long sB,
        float* __restrict__ C, int ldc, long long sC,
        bf16* __restrict__ Ch, long long planeC, int ldch, long long sCh,
        const float* __restrict__ bias, long long sBias,
        const float* __restrict__ aux, int auxMod,
        int M, int N, int K)
{
    extern __shared__ char smd[];
    const int zi = blockIdx.z;
    Ah += (size_t)zi * sA; Al += (size_t)zi * sA;
    Bh += (size_t)zi * sB; Bl += (size_t)zi * sB;
    if (OUT != 2) C += (size_t)zi * sC;
    if (OUT != 0) Ch += (size_t)zi * sCh;
    const float* bp = bias ? (bias + (size_t)zi * sBias) : nullptr;

    const int bm = blockIdx.y * 64;
    const int bn = blockIdx.x * 128;
    const int tid = threadIdx.x, lane = tid & 31, warp = tid >> 5;
    const int wm = warp & 1, wn = warp >> 1;

    const uint32_t smem_base = (uint32_t)__cvta_generic_to_shared(smd);

    auto load_stage = [&](int s, int kt) {
        const int k0 = kt * 32;
        const uint32_t As = smem_base + s * 24576;
        const uint32_t Bs = As + 8192;
#pragma unroll
        for (int i = 0; i < 2; i++) {
            int lin = i * 256 + tid;
            int row = lin >> 3, ch = lin & 7;
            const bf16* srcA = ((ch & 4) ? Al : Ah) + (size_t)(bm + row) * lda + k0 + (ch & 3) * 8;
            cp16(As + row * 128 + ((ch ^ (row & 7)) * 16), srcA, true);
        }
#pragma unroll
        for (int i = 0; i < 4; i++) {
            int lin = i * 256 + tid;
            int row = lin >> 3, ch = lin & 7;
            bool ok = (bn + row) < N;
            const bf16* srcB = ((ch & 4) ? Bl : Bh) +
                               (ok ? ((size_t)(bn + row) * ldb + k0 + (ch & 3) * 8) : 0);
            cp16(Bs + row * 128 + ((ch ^ (row & 7)) * 16), srcB, ok);
        }
    };

    float acc[2][4][4];
#pragma unroll
    for (int i = 0; i < 2; i++)
#pragma unroll
        for (int j = 0; j < 4; j++)
#pragma unroll
            for (int q = 0; q < 4; q++) acc[i][j][q] = 0.0f;

    const int nk = K / 32;
    if (nk > 0) load_stage(0, 0);
    cp_commit();
    if (nk > 1) load_stage(1, 1);
    cp_commit();

    const int g  = lane >> 3;
    const int lr = lane & 7;
    const int aRow0 = wm * 32 + (g & 1) * 8 + lr;
    const int bRow0 = wn * 32 + (g & 1) * 8 + lr;
    const int chHi  = (g >> 1);

    for (int kt = 0; kt < nk; kt++) {
        cp_wait1();
        __syncthreads();
        const uint32_t As = smem_base + (kt % 3) * 24576;
        const uint32_t Bs = As + 8192;

#pragma unroll
        for (int step = 0; step < 2; step++) {
            uint32_t ah[2][4], al[2][4], bh[2][4], bl[2][4];
            const int cH = ((step * 2 + chHi) ^ lr) * 16;
            const int cL = ((4 + step * 2 + chHi) ^ lr) * 16;
#pragma unroll
            for (int mt = 0; mt < 2; mt++) {
                uint32_t rb = As + (uint32_t)(aRow0 + mt * 16) * 128;
                ldsm4(ah[mt], rb + cH);
                ldsm4(al[mt], rb + cL);
            }
#pragma unroll
            for (int p = 0; p < 2; p++) {
                uint32_t rb = Bs + (uint32_t)(bRow0 + p * 16) * 128;
                ldsm4(bh[p], rb + cH);
                ldsm4(bl[p], rb + cL);
            }
#pragma unroll
            for (int nt = 0; nt < 4; nt++) {
                const int p = nt >> 1, o = nt & 1;
                const uint32_t b0h = bh[p][o], b1h = bh[p][o + 2];
                const uint32_t b0l = bl[p][o], b1l = bl[p][o + 2];
#pragma unroll
                for (int mt = 0; mt < 2; mt++) {
                    mma16816(acc[mt][nt], ah[mt], b0h, b1h);
                    mma16816(acc[mt][nt], ah[mt], b0l, b1l);
                    mma16816(acc[mt][nt], al[mt], b0h, b1h);
                }
            }
        }
        __syncthreads();
        if (kt + 2 < nk) load_stage((kt + 2) % 3, kt + 2);
        cp_commit();
    }

    const int r_ep = lane >> 2, c_ep = lane & 3;
#pragma unroll
    for (int mt = 0; mt < 2; mt++) {
        const int m0 = bm + wm * 32 + mt * 16 + r_ep;
#pragma unroll
        for (int nt = 0; nt < 4; nt++) {
            const int n0 = bn + wn * 32 + nt * 8 + 2 * c_ep;
#pragma unroll
            for (int half = 0; half < 2; half++) {
                const int m = m0 + half * 8;
                if (n0 < N) {
                    float v0 = acc[mt][nt][half * 2 + 0];
                    float v1 = acc[mt][nt][half * 2 + 1];
                    if (bp) { v0 += bp[n0]; v1 += bp[n0 + 1]; }
                    if (EPI == 1)      { v0 = geluf(v0);     v1 = geluf(v1); }
                    else if (EPI == 3) { v0 = softplusf(v0); v1 = softplusf(v1); }
                    else if (EPI == 4) {
                        const float* ar = aux + (size_t)(m % auxMod) * ldc;
                        v0 += ar[n0]; v1 += ar[n0 + 1];
                    } else if (EPI == 5) {
                        const float* ar = aux + (size_t)m * ldc;
                        v0 += ar[n0]; v1 += ar[n0 + 1];
                    }
                    if (OUT != 2) {
                        float2 f2; f2.x = v0; f2.y = v1;
                        *(float2*)(C + (size_t)m * ldc + n0) = f2;
                    }
                    if (OUT != 0) {
                        size_t o = (size_t)m * ldch + n0;
                        split2_store(Ch + o, Ch + planeC + o, v0, v1);
                    }
                }
            }
        }
    }
}

// ---------------- fused prepass ----------------
#define PRE_BLOCKS 23296

__global__ void fused_pre_k(
    const float* __restrict__ pos_w1, const float* __restrict__ pos_b1,
    const float* __restrict__ pos_w2, const float* __restrict__ mix_w,
    const float* __restrict__ m_out_w, const float* __restrict__ m_in_w,
    const float* __restrict__ m_xproj_w, const float* __restrict__ m_dt_w,
    const float* __restrict__ ffn_w1, const float* __restrict__ ffn_w2,
    bf16* __restrict__ wpos2, bf16* __restrict__ wpmix, bf16* __restrict__ wmixA,
    bf16* __restrict__ wTout, bf16* __restrict__ win, bf16* __restrict__ wxp,
    bf16* __restrict__ wdt, bf16* __restrict__ wf1, bf16* __restrict__ wf2,
    bf16* __restrict__ posh)
{
    const int bid = blockIdx.x, tid = threadIdx.x;
    bf16 h, l;
    if (bid < 1024) {
        int i = bid * 256 + tid;
        splitf(pos_w2[i], h, l); wpos2[i] = h; wpos2[262144 + i] = l;
    } else if (bid < 2048) {
        int i = (bid - 1024) * 256 + tid;
        int r = i >> 9, c = i & 511;
        splitf(mix_w[1024 + r * 1536 + c], h, l); wpmix[i] = h; wpmix[262144 + i] = l;
    } else if (bid < 3072) {
        int i = (bid - 2048) * 256 + tid;
        int r = i >> 9, c = i & 511;
        splitf(mix_w[r * 1536 + c], h, l); wmixA[i] = h; wmixA[524288 + i] = l;
    } else if (bid < 4096) {
        int i = (bid - 3072) * 256 + tid;
        int r = i >> 9, c = i & 511;
        splitf(mix_w[512 + r * 1536 + c], h, l);
        wmixA[262144 + i] = h; wmixA[524288 + 262144 + i] = l;
    } else if (bid < 6144) {
        int i = (bid - 4096) * 256 + tid;
        int e = i >> 9, j = i & 511;
        splitf(m_out_w[(size_t)j * 1024 + e], h, l);
        wTout[i] = h; wTout[1048576 + i] = l;
    } else if (bid < 8192) {
        int i = (bid - 6144) * 256 + tid;
        int e = i >> 9, j = i & 511;
        splitf(m_out_w[524288 + (size_t)j * 1024 + e], h, l);
        wTout[524288 + i] = h; wTout[1048576 + 524288 + i] = l;
    } else if (bid < 16384) {
        int i = (bid - 8192) * 256 + tid;
        splitf(m_in_w[i], h, l); win[i] = h; win[2097152 + i] = l;
    } else if (bid < 16896) {
        int i = (bid - 16384) * 256 + tid;
        splitf(m_xproj_w[i], h, l); wxp[i] = h; wxp[131072 + i] = l;
    } else if (bid < 17152) {
        int i = (bid - 16896) * 256 + tid;
        splitf(m_dt_w[i], h, l); wdt[i] = h; wdt[65536 + i] = l;
    } else if (bid < 19200) {
        int i = (bid - 17152) * 256 + tid;
        splitf(ffn_w1[i], h, l); wf1[i] = h; wf1[524288 + i] = l;
    } else if (bid < 21248) {
        int i = (bid - 19200) * 256 + tid;
        splitf(ffn_w2[i], h, l); wf2[i] = h; wf2[524288 + i] = l;
    } else {
        int i = (bid - 21248) * 256 + tid;
        int t = i >> 9, c = i & 511;
        int y = t >> 5, x = t & 31;
        const float PI = 3.14159265358979323846f;
        float yy = ((y + 0.5f) / 32.0f) * 2.0f - 1.0f;
        float xx = ((x + 0.5f) / 32.0f) * 2.0f - 1.0f;
        float f2 = sinf(PI * yy), f3 = cosf(PI * yy);
        float f4 = sinf(PI * xx), f5 = cosf(PI * xx);
        const float* w = pos_w1 + c * 6;
        float v = pos_b1[c] + yy * w[0] + xx * w[1] + f2 * w[2] + f3 * w[3] + f4 * w[4] + f5 * w[5];
        v = geluf(v);
        splitf(v, h, l); posh[i] = h; posh[524288 + i] = l;
    }
}

// ---------------- LN(tokens) + pos -> hi/lo ----------------
__global__ void ln_add_pos_k(const float* __restrict__ x,
                             const float* __restrict__ g, const float* __restrict__ b,
                             const float* __restrict__ pos, bf16* __restrict__ out)
{
    __shared__ float sh[16];
    const int row = blockIdx.x;
    const int tid = threadIdx.x;
    float4 v = ((const float4*)(x + (size_t)row * DIM))[tid];
    float s = v.x + v.y + v.z + v.w;
    float q = v.x * v.x + v.y * v.y + v.z * v.z + v.w * v.w;
#pragma unroll
    for (int o = 16; o; o >>= 1) {
        s += __shfl_xor_sync(0xffffffffu, s, o);
        q += __shfl_xor_sync(0xffffffffu, q, o);
    }
    if ((tid & 31) == 0) { sh[tid >> 5] = s; sh[4 + (tid >> 5)] = q; }
    __syncthreads();
    if (tid == 0) {
        float S = sh[0] + sh[1] + sh[2] + sh[3];
        float Q = sh[4] + sh[5] + sh[6] + sh[7];
        float mu = S * (1.0f / DIM);
        float var = Q * (1.0f / DIM) - mu * mu;
        sh[8] = mu; sh[9] = rsqrtf(var + 1e-5f);
    }
    __syncthreads();
    const float mu = sh[8], rs = sh[9];
    const int t = row & (LSEQ - 1);
    float4 g4 = ((const float4*)g)[tid];
    float4 b4 = ((const float4*)b)[tid];
    float4 p4 = ((const float4*)(pos + (size_t)t * DIM))[tid];
    float4 r;
    r.x = (v.x - mu) * rs * g4.x + b4.x + p4.x;
    r.y = (v.y - mu) * rs * g4.y + b4.y + p4.y;
    r.z = (v.z - mu) * rs * g4.z + b4.z + p4.z;
    r.w = (v.w - mu) * rs * g4.w + b4.w + p4.w;
    bf16* ph = out + (size_t)row * DIM + tid * 4;
    split4_store(ph, ph + (long long)ROWS * DIM, r);
}

// ---------------- causal conv + SiLU (fp32 xz in, hi/lo xc out) ----------------
__global__ void conv_silu_k(const float* __restrict__ xz,
                            const float* __restrict__ cw, const float* __restrict__ cb,
                            bf16* __restrict__ xch)
{
    size_t gidx = (size_t)blockIdx.x * 256 + threadIdx.x;
    int dq  = (int)(gidx & 255);
    int row = (int)((gidx >> 8) & (ROWS - 1));
    int dir = (int)(gidx >> 21);
    int d = dq * 4;
    int t = row & (LSEQ - 1);
    int b = row >> 10;

    float4 acc = *(const float4*)&cb[dir * DI + d];
    const float4* wrow = (const float4*)&cw[(size_t)(dir * DI + d) * 4];
    float4 w0 = wrow[0], w1 = wrow[1], w2 = wrow[2], w3 = wrow[3];

#pragma unroll
    for (int k = 0; k < 4; k++) {
        int off = dir ? (3 - k) : (k - 3);
        int tt = t + off;
        if (tt >= 0 && tt < LSEQ) {
            float4 v = *(const float4*)&xz[((size_t)(b * LSEQ + tt)) * 4096 + dir * 2048 + d];
            acc.x = fmaf(fcomp(w0, k), v.x, acc.x);
            acc.y = fmaf(fcomp(w1, k), v.y, acc.y);
            acc.z = fmaf(fcomp(w2, k), v.z, acc.z);
            acc.w = fmaf(fcomp(w3, k), v.w, acc.w);
        }
    }
    float4 r;
    r.x = siluf(acc.x); r.y = siluf(acc.y); r.z = siluf(acc.z); r.w = siluf(acc.w);
    bf16* ph = xch + gidx * 4;
    split4_store(ph, ph + XPLANE, r);
}

// ================= chunked selective scan (R12-proven) =================
__global__ void scan_part1_k(const float* __restrict__ dsp, const bf16* __restrict__ xch,
                             const float* __restrict__ proj, const float* __restrict__ A_log,
                             float* __restrict__ hend, float* __restrict__ prodv)
{
    const int chunk = blockIdx.x >> 3;
    const int dblk  = blockIdx.x & 7;
    const int b = blockIdx.y, dir = blockIdx.z;
    const int d = dblk * 128 + threadIdx.x;

    float a[DS];
    bool fast = true;
#pragma unroll
    for (int s = 0; s < DS; s++) {
        a[s] = -expf(A_log[((size_t)dir * DI + d) * DS + s]);
        fast = fast && (fabsf(a[s] + (float)(s + 1)) < 1e-4f * (float)(s + 1));
    }

    const size_t base_row = (size_t)dir * ROWS + (size_t)b * LSEQ;
    __shared__ float sB[CLEN][DS];
    for (int i = threadIdx.x; i < CLEN * DS; i += 128) {
        int st = chunk * CLEN + (i >> 4);
        int c = i & 15;
        int r = dir ? (LSEQ - 1 - st) : st;
        sB[i >> 4][c] = proj[(base_row + r) * 64 + 32 + c];
    }
    __syncthreads();

    float h[DS], p[DS];
#pragma unroll
    for (int s = 0; s < DS; s++) h[s] = 0.0f;

    if (fast) {
        float prodE1 = 1.0f;
        for (int i = 0; i < CLEN; i++) {
            int st = chunk * CLEN + i;
            int r = dir ? (LSEQ - 1 - st) : st;
            size_t ro = (base_row + r) * (size_t)DI + d;
            float delta = dsp[ro];
            float x     = hlval(xch, XPLANE, ro);
            float dx    = delta * x;
            float e1 = __expf(-delta);
            prodE1 *= e1;
            float ep = e1;
#pragma unroll
            for (int s = 0; s < DS; s++) {
                h[s] = fmaf(h[s], ep, dx * sB[i][s]);
                ep *= e1;
            }
        }
        float ep = prodE1;
#pragma unroll
        for (int s = 0; s < DS; s++) { p[s] = ep; ep *= prodE1; }
    } else {
#pragma unroll
        for (int s = 0; s < DS; s++) p[s] = 1.0f;
        for (int i = 0; i < CLEN; i++) {
            int st = chunk * CLEN + i;
            int r = dir ? (LSEQ - 1 - st) : st;
            size_t ro = (base_row + r) * (size_t)DI + d;
            float delta = dsp[ro];
            float x     = hlval(xch, XPLANE, ro);
            float dx    = delta * x;
#pragma unroll
            for (int s = 0; s < DS; s++) {
                float e = __expf(delta * a[s]);
                h[s] = fmaf(h[s], e, dx * sB[i][s]);
                p[s] *= e;
            }
        }
    }

    const int CH = (dir * BATCH + b) * DI + d;
    size_t o = ((size_t)chunk * NCH + CH) * DS;
#pragma unroll
    for (int s = 0; s < DS; s++) { hend[o + s] = h[s]; prodv[o + s] = p[s]; }
}

__global__ void scan_part2_k(const float* __restrict__ hend, const float* __restrict__ prodv,
                             float* __restrict__ hinit)
{
    int idx = blockIdx.x * 256 + threadIdx.x;
    if (idx >= NCH * DS) return;
    float H = 0.0f;
#pragma unroll 4
    for (int c = 0; c < NCHUNK; c++) {
        size_t o = (size_t)c * (NCH * DS) + idx;
        hinit[o] = H;
        H = fmaf(prodv[o], H, hend[o]);
    }
}

__global__ void scan_part3_k(const float* __restrict__ dsp, const bf16* __restrict__ xch,
                             const float* __restrict__ proj, const float* __restrict__ xz,
                             const float* __restrict__ A_log, const float* __restrict__ Dp,
                             const float* __restrict__ hinit, bf16* __restrict__ ycat)
{
    const int chunk = blockIdx.x >> 3;
    const int dblk  = blockIdx.x & 7;
    const int b = blockIdx.y, dir = blockIdx.z;
    const int d = dblk * 128 + threadIdx.x;

    float a[DS];
    bool fast = true;
#pragma unroll
    for (int s = 0; s < DS; s++) {
        a[s] = -expf(A_log[((size_t)dir * DI + d) * DS + s]);
        fast = fast && (fabsf(a[s] + (float)(s + 1)) < 1e-4f * (float)(s + 1));
    }
    const float Dv = Dp[dir * DI + d];

    const size_t base_row = (size_t)dir * ROWS + (size_t)b * LSEQ;
    const long long plane = (long long)ROWS * 2048;
    __shared__ float sBC[CLEN][32];
    for (int i = threadIdx.x; i < CLEN * 32; i += 128) {
        int st = chunk * CLEN + (i >> 5);
        int c = i & 31;
        int r = dir ? (LSEQ - 1 - st) : st;
        sBC[i >> 5][c] = proj[(base_row + r) * 64 + 32 + c];
    }
    __syncthreads();

    const int CH = (dir * BATCH + b) * DI + d;
    size_t ho = ((size_t)chunk * NCH + CH) * DS;
    float h[DS];
#pragma unroll
    for (int s = 0; s < DS; s++) h[s] = hinit[ho + s];

    if (fast) {
        for (int i = 0; i < CLEN; i++) {
            int st = chunk * CLEN + i;
            int r = dir ? (LSEQ - 1 - st) : st;
            size_t ro = (base_row + r) * (size_t)DI + d;
            float delta = dsp[ro];
            float x     = hlval(xch, XPLANE, ro);
            float dx    = delta * x;
            float y = 0.0f;
            float e1 = __expf(-delta);
            float ep = e1;
#pragma unroll
            for (int s = 0; s < DS; s++) {
                h[s] = fmaf(h[s], ep, dx * sBC[i][s]);
                y = fmaf(h[s], sBC[i][16 + s], y);
                ep *= e1;
            }
            float z = xz[((size_t)(b * LSEQ + r)) * 4096 + dir * 2048 + DI + d];
            float outv = (y + x * Dv) * siluf(z);
            bf16 hh, ll; splitf(outv, hh, ll);
            size_t oo = ((size_t)(b * LSEQ + r)) * 2048 + dir * DI + d;
            ycat[oo] = hh; ycat[plane + oo] = ll;
        }
    } else {
        for (int i = 0; i < CLEN; i++) {
            int st = chunk * CLEN + i;
            int r = dir ? (LSEQ - 1 - st) : st;
            size_t ro = (base_row + r) * (size_t)DI + d;
            float delta = dsp[ro];
            float x     = hlval(xch, XPLANE, ro);
            float dx    = delta * x;
            float y = 0.0f;
#pragma unroll
            for (int s = 0; s < DS; s++) {
                float e = __expf(delta * a[s]);
                h[s] = fmaf(h[s], e, dx * sBC[i][s]);
                y = fmaf(h[s], sBC[i][16 + s], y);
            }
            float z = xz[((size_t)(b * LSEQ + r)) * 4096 + dir * 2048 + DI + d];
            float outv = (y + x * Dv) * siluf(z);
            bf16 hh, ll; splitf(outv, hh, ll);
            size_t oo = ((size_t)(b * LSEQ + r)) * 2048 + dir * DI + d;
            ycat[oo] = hh; ycat[plane + oo] = ll;
        }
    }
}

// ---------------- dual LayerNorm ----------------
__global__ void ln_dual_k(const float* __restrict__ in,
                          const float* __restrict__ g1, const float* __restrict__ b1,
                          const float* __restrict__ g2, const float* __restrict__ b2,
                          float* __restrict__ out1, bf16* __restrict__ out2)
{
    __shared__ float sh[16];
    const int row = blockIdx.x;
    const int tid = threadIdx.x;
    float4 v = ((const float4*)(in + (size_t)row * DIM))[tid];
    float s = v.x + v.y + v.z + v.w;
    float q = v.x * v.x + v.y * v.y + v.z * v.z + v.w * v.w;
#pragma unroll
    for (int o = 16; o; o >>= 1) {
        s += __shfl_xor_sync(0xffffffffu, s, o);
        q += __shfl_xor_sync(0xffffffffu, q, o);
    }
    if ((tid & 31) == 0) { sh[tid >> 5] = s; sh[4 + (tid >> 5)] = q; }
    __syncthreads();
    if (tid == 0) {
        float S = sh[0] + sh[1] + sh[2] + sh[3];
        float Q = sh[4] + sh[5] + sh[6] + sh[7];
        float mu = S * (1.0f / DIM);
        float var = Q * (1.0f / DIM) - mu * mu;
        sh[8] = mu; sh[9] = rsqrtf(var + 1e-5f);
    }
    __syncthreads();
    float mu = sh[8], rs = sh[9];
    float4 g4 = ((const float4*)g1)[tid];
    float4 b4 = ((const float4*)b1)[tid];
    float4 x4;
    x4.x = (v.x - mu) * rs * g4.x + b4.x;
    x4.y = (v.y - mu) * rs * g4.y + b4.y;
    x4.z = (v.z - mu) * rs * g4.z + b4.z;
    x4.w = (v.w - mu) * rs * g4.w + b4.w;
    ((float4*)(out1 + (size_t)row * DIM))[tid] = x4;

    __syncthreads();
    s = x4.x + x4.y + x4.z + x4.w;
    q = x4.x * x4.x + x4.y * x4.y + x4.z * x4.z + x4.w * x4.w;
#pragma unroll
    for (int o = 16; o; o >>= 1) {
        s += __shfl_xor_sync(0xffffffffu, s, o);
        q += __shfl_xor_sync(0xffffffffu, q, o);
    }
    if ((tid & 31) == 0) { sh[tid >> 5] = s; sh[4 + (tid >> 5)] = q; }
    __syncthreads();
    if (tid == 0) {
        float S = sh[0] + sh[1] + sh[2] + sh[3];
        float Q = sh[4] + sh[5] + sh[6] + sh[7];
        float mu2 = S * (1.0f / DIM);
        float var2 = Q * (1.0f / DIM) - mu2 * mu2;
        sh[8] = mu2; sh[9] = rsqrtf(var2 + 1e-5f);
    }
    __syncthreads();
    float mu2 = sh[8], rs2 = sh[9];
    float4 G = ((const float4*)g2)[tid];
    float4 B = ((const float4*)b2)[tid];
    float4 r;
    r.x = (x4.x - mu2) * rs2 * G.x + B.x;
    r.y = (x4.y - mu2) * rs2 * G.y + B.y;
    r.z = (x4.z - mu2) * rs2 * G.z + B.z;
    r.w = (x4.w - mu2) * rs2 * G.w + B.w;
    bf16* ph = out2 + (size_t)row * DIM + tid * 4;
    split4_store(ph, ph + (long long)ROWS * DIM, r);
}

// ---------------- host launcher ----------------
extern "C" void kernel_launch(void* const* d_in, const int* in_sizes, int n_in,
                              void* d_out, int out_size)
{
    const float* tokens    = (const float*)d_in[0];
    const float* in_g      = (const float*)d_in[3];
    const float* in_b      = (const float*)d_in[4];
    const float* pos_w1    = (const float*)d_in[5];
    const float* pos_b1    = (const float*)d_in[6];
    const float* pos_w2    = (const float*)d_in[7];
    const float* pos_b2    = (const float*)d_in[8];
    const float* m_in_w    = (const float*)d_in[9];
    const float* m_conv_w  = (const float*)d_in[10];
    const float* m_conv_b  = (const float*)d_in[11];
    const float* m_xproj_w = (const float*)d_in[12];
    const float* m_dt_w    = (const float*)d_in[13];
    const float* m_dt_b    = (const float*)d_in[14];
    const float* m_A_log   = (const float*)d_in[15];
    const float* m_D       = (const float*)d_in[16];
    const float* m_out_w   = (const float*)d_in[17];
    const float* mix_w     = (const float*)d_in[18];
    const float* mix_b     = (const float*)d_in[19];
    const float* dn_g      = (const float*)d_in[20];
    const float* dn_b      = (const float*)d_in[21];
    const float* fn_g      = (const float*)d_in[22];
    const float* fn_b      = (const float*)d_in[23];
    const float* ffn_w1    = (const float*)d_in[24];
    const float* ffn_b1    = (const float*)d_in[25];
    const float* ffn_w2    = (const float*)d_in[26];
    const float* ffn_b2    = (const float*)d_in[27];
    float* out = (float*)d_out;

    float *pos, *pos_mix, *xz, *proj, *dsp, *dmix, *dln, *hend, *prodv, *hinit;
    bf16 *sin_hl, *posh_hl, *pos_hl, *wpos2, *wpmix, *wmixA, *wTout, *win, *wxp, *wdt, *wf1, *wf2;
    bf16 *xc_hl, *proj_hl, *ycat_hl, *wc_hl, *lnf_hl, *h1_hl;
    cudaGetSymbolAddress((void**)&pos,     g_pos);
    cudaGetSymbolAddress((void**)&pos_mix, g_pos_mix);
    cudaGetSymbolAddress((void**)&xz,      g_xz);
    cudaGetSymbolAddress((void**)&proj,    g_proj);
    cudaGetSymbolAddress((void**)&dsp,     g_dsp);
    cudaGetSymbolAddress((void**)&dmix,    g_dmix);
    cudaGetSymbolAddress((void**)&dln,     g_dln);
    cudaGetSymbolAddress((void**)&hend,    g_hend);
    cudaGetSymbolAddress((void**)&prodv,   g_prod);
    cudaGetSymbolAddress((void**)&hinit,   g_hinit);
    cudaGetSymbolAddress((void**)&sin_hl,  hl_scan_in);
    cudaGetSymbolAddress((void**)&posh_hl, hl_pos_h);
    cudaGetSymbolAddress((void**)&pos_hl,  hl_pos);
    cudaGetSymbolAddress((void**)&wpos2,   hl_w_pos2);
    cudaGetSymbolAddress((void**)&wpmix,   hl_w_pmix);
    cudaGetSymbolAddress((void**)&wmixA,   hl_w_mixA);
    cudaGetSymbolAddress((void**)&wTout,   hl_wT_out);
    cudaGetSymbolAddress((void**)&win,     hl_w_in);
    cudaGetSymbolAddress((void**)&wxp,     hl_w_xp);
    cudaGetSymbolAddress((void**)&wdt,     hl_w_dt);
    cudaGetSymbolAddress((void**)&wf1,     hl_w_f1);
    cudaGetSymbolAddress((void**)&wf2,     hl_w_f2);
    cudaGetSymbolAddress((void**)&xc_hl,   hl_xc);
    cudaGetSymbolAddress((void**)&proj_hl, hl_proj);
    cudaGetSymbolAddress((void**)&ycat_hl, hl_ycat);
    cudaGetSymbolAddress((void**)&wc_hl,   hl_wc);
    cudaGetSymbolAddress((void**)&lnf_hl,  hl_lnf);
    cudaGetSymbolAddress((void**)&h1_hl,   hl_h1);

    cudaFuncSetAttribute(bgemm<0,0>, cudaFuncAttributeMaxDynamicSharedMemorySize, SMEM_BYTES);
    cudaFuncSetAttribute(bgemm<4,0>, cudaFuncAttributeMaxDynamicSharedMemorySize, SMEM_BYTES);
    cudaFuncSetAttribute(bgemm<1,2>, cudaFuncAttributeMaxDynamicSharedMemorySize, SMEM_BYTES);
    cudaFuncSetAttribute(bgemm<5,0>, cudaFuncAttributeMaxDynamicSharedMemorySize, SMEM_BYTES);
    cudaFuncSetAttribute(bgemm64<0,0>, cudaFuncAttributeMaxDynamicSharedMemorySize, SMEM64_BYTES);
    cudaFuncSetAttribute(bgemm64<0,1>, cudaFuncAttributeMaxDynamicSharedMemorySize, SMEM64_BYTES);
    cudaFuncSetAttribute(bgemm64<0,2>, cudaFuncAttributeMaxDynamicSharedMemorySize, SMEM64_BYTES);
    cudaFuncSetAttribute(bgemm64<3,0>, cudaFuncAttributeMaxDynamicSharedMemorySize, SMEM64_BYTES);

    // 1: fused converts + pos_hidden
    fused_pre_k<<<PRE_BLOCKS, 256>>>(pos_w1, pos_b1, pos_w2, mix_w, m_out_w, m_in_w,
                                     m_xproj_w, m_dt_w, ffn_w1, ffn_w2,
                                     wpos2, wpmix, wmixA, wTout, win, wxp, wdt, wf1, wf2,
                                     posh_hl);
    // 2: pos = gelu_h @ pos_w2^T + b2
    bgemm64<0,1><<<dim3(4,16,1), 256, SMEM64_BYTES>>>(
        posh_hl, posh_hl + LSEQ*DIM, 512, 0,  wpos2, wpos2 + 512*512, 512, 0,
        pos, 512, 0,  pos_hl, (long long)LSEQ*DIM, 512, 0,
        pos_b2, 0, nullptr, 1, LSEQ, 512, 512);
    // 3: scan_in = LN(tokens) + pos
    ln_add_pos_k<<<ROWS, 128>>>(tokens, in_g, in_b, pos, sin_hl);
    // 4: xz = scan_in @ in_w^T (fp32 out)  <-- profiled slot
    bgemm<0,0><<<dim3(32,64,1), 256, SMEM_BYTES>>>(
        sin_hl, sin_hl + (long long)ROWS*DIM, 512, 0,
        win, win + (long long)4096*512, 512, 0,
        xz, 4096, 0, nullptr, 0, 0, 0,
        nullptr, 0, nullptr, 1, ROWS, 4096, 512);

    conv_silu_k<<<(2*ROWS*DI)/1024, 256>>>(xz, m_conv_w, m_conv_b, xc_hl);
    // proj = xc @ xproj^T per dir
    bgemm64<0,1><<<dim3(1,128,2), 256, SMEM64_BYTES>>>(
        xc_hl, xc_hl + (long long)2*ROWS*DI, 1024, (long long)ROWS*DI,
        wxp, wxp + (long long)128*1024, 1024, (long long)64*1024,
        proj, 64, (long long)ROWS*64,
        proj_hl, (long long)2*ROWS*64, 64, (long long)ROWS*64,
        nullptr, 0, nullptr, 1, ROWS, 64, 1024);
    // dsp = softplus(dt @ dt_w^T + dt_b) (fp32 out)
    bgemm64<3,0><<<dim3(8,128,2), 256, SMEM64_BYTES>>>(
        proj_hl, proj_hl + (long long)2*ROWS*64, 64, (long long)ROWS*64,
        wdt, wdt + (long long)2048*32, 32, (long long)1024*32,
        dsp, 1024, (long long)ROWS*DI, nullptr, 0, 0, 0,
        m_dt_b, 1024, nullptr, 1, ROWS, 1024, 32);

    // chunked scan
    scan_part1_k<<<dim3(8*NCHUNK, BATCH, 2), 128>>>(dsp, xc_hl, proj, m_A_log, hend, prodv);
    scan_part2_k<<<(NCH*DS)/256, 256>>>(hend, prodv, hinit);
    scan_part3_k<<<dim3(8*NCHUNK, BATCH, 2), 128>>>(dsp, xc_hl, proj, xz, m_A_log, m_D, hinit, ycat_hl);

    // pos_mix = pos @ mix_w[:,1024:1536]^T + mix_b
    bgemm64<0,0><<<dim3(4,16,1), 256, SMEM64_BYTES>>>(
        pos_hl, pos_hl + LSEQ*DIM, 512, 0,  wpmix, wpmix + 512*512, 512, 0,
        pos_mix, 512, 0,  nullptr, 0, 0, 0,
        mix_b, 0, nullptr, 1, LSEQ, 512, 512);
    // Wc[dir] = mix_w_slice @ out_w[dir]
    bgemm64<0,2><<<dim3(8,8,2), 256, SMEM64_BYTES>>>(
        wmixA, wmixA + (long long)2*512*512, 512, (long long)512*512,
        wTout, wTout + (long long)2*1024*512, 512, (long long)1024*512,
        nullptr, 0, 0,
        wc_hl, (long long)512*2048, 2048, 1024,
        nullptr, 0, nullptr, 1, 512, 1024, 512);
    // dmix = ycat @ Wc^T + pos_mix
    bgemm<4,0><<<dim3(4,64,1), 256, SMEM_BYTES>>>(
        ycat_hl, ycat_hl + (long long)ROWS*2048, 2048, 0,
        wc_hl, wc_hl + (long long)512*2048, 2048, 0,
        dmix, 512, 0, nullptr, 0, 0, 0,
        nullptr, 0, pos_mix, LSEQ, ROWS, 512, 2048);
    ln_dual_k<<<ROWS, 128>>>(dmix, dn_g, dn_b, fn_g, fn_b, dln, lnf_hl);
    bgemm<1,2><<<dim3(8,64,1), 256, SMEM_BYTES>>>(
        lnf_hl, lnf_hl + (long long)ROWS*DIM, 512, 0,
        wf1, wf1 + (long long)1024*512, 512, 0,
        nullptr, 1024, 0,
        h1_hl, (long long)ROWS*HID, 1024, 0,
        ffn_b1, 0, nullptr, 1, ROWS, 1024, 512);
    bgemm<5,0><<<dim3(4,64,1), 256, SMEM_BYTES>>>(
        h1_hl, h1_hl + (long long)ROWS*HID, 1024, 0,
        wf2, wf2 + (long long)512*1024, 1024, 0,
        out, 512, 0, nullptr, 0, 0, 0,
        ffn_b2, 0, dln, 1, ROWS, 512, 1024);

    (void)in_sizes; (void)n_in; (void)out_size;
}

// round 16
// speedup vs baseline: 1.1691x; 1.0116x over previous
#include <cuda_runtime.h>
#include <cuda_bf16.h>
#include <cstdint>
#include <math.h>

#define BATCH 8
#define LSEQ  1024
#define DIM   512
#define DI    1024
#define DS    16
#define HID   1024
#define ROWS  (BATCH*LSEQ)    // 8192
#define NCHUNK 32
#define CLEN   32
#define NCH    16384
#define XPLANE ((size_t)2*ROWS*DI)

typedef __nv_bfloat16 bf16;

// ---------------- fp32 scratch ----------------
__device__ float g_pos    [LSEQ*DIM];
__device__ float g_pos_mix[LSEQ*DIM];
__device__ float g_xz     [ROWS*4096];
__device__ float g_proj   [2*ROWS*64];
__device__ float g_dsp    [2*ROWS*DI];
__device__ float g_dmix   [ROWS*DIM];
__device__ float g_dln    [ROWS*DIM];
__device__ float g_hend [NCHUNK*NCH*DS];
__device__ float g_prod [NCHUNK*NCH*DS];
__device__ float g_hinit[NCHUNK*NCH*DS];

// ---------------- bf16 hi/lo scratch ----------------
__device__ __align__(16) bf16 hl_scan_in[2*ROWS*DIM];
__device__ __align__(16) bf16 hl_pos_h  [2*LSEQ*DIM];
__device__ __align__(16) bf16 hl_pos    [2*LSEQ*DIM];
__device__ __align__(16) bf16 hl_w_pos2 [2*DIM*DIM];
__device__ __align__(16) bf16 hl_w_pmix [2*DIM*DIM];
__device__ __align__(16) bf16 hl_w_mixA [2*2*DIM*DIM];
__device__ __align__(16) bf16 hl_wT_out [2*2*DI*DIM];
__device__ __align__(16) bf16 hl_w_in   [2*4096*DIM];
__device__ __align__(16) bf16 hl_w_xp   [2*2*64*DI];
__device__ __align__(16) bf16 hl_w_dt   [2*2*DI*32];
__device__ __align__(16) bf16 hl_w_f1   [2*HID*DIM];
__device__ __align__(16) bf16 hl_w_f2   [2*DIM*HID];
__device__ __align__(16) bf16 hl_xc     [2*2*ROWS*DI];
__device__ __align__(16) bf16 hl_proj   [2*2*ROWS*64];
__device__ __align__(16) bf16 hl_ycat   [2*ROWS*2048];
__device__ __align__(16) bf16 hl_wc     [2*DIM*2048];
__device__ __align__(16) bf16 hl_lnf    [2*ROWS*DIM];
__device__ __align__(16) bf16 hl_h1     [2*ROWS*HID];

// ---------------- math helpers ----------------
__device__ __forceinline__ float geluf(float x) {
    return 0.5f * x * (1.0f + erff(x * 0.70710678118654752440f));
}
__device__ __forceinline__ float siluf(float x) { return x / (1.0f + __expf(-x)); }
__device__ __forceinline__ float softplusf(float x) { return (x > 20.0f) ? x : log1pf(__expf(x)); }
__device__ __forceinline__ void splitf(float v, bf16& h, bf16& l) {
    h = __float2bfloat16(v);
    l = __float2bfloat16(v - __bfloat162float(h));
}
__device__ __forceinline__ float fcomp(float4 f, int k) {
    return k == 0 ? f.x : (k == 1 ? f.y : (k == 2 ? f.z : f.w));
}
__device__ __forceinline__ void split4_store(bf16* ph, bf16* pl, float4 v) {
    bf16 h0, l0, h1, l1, h2, l2, h3, l3;
    splitf(v.x, h0, l0); splitf(v.y, h1, l1);
    splitf(v.z, h2, l2); splitf(v.w, h3, l3);
    __nv_bfloat162 a; a.x = h0; a.y = h1;
    __nv_bfloat162 b; b.x = h2; b.y = h3;
    __nv_bfloat162 c; c.x = l0; c.y = l1;
    __nv_bfloat162 d; d.x = l2; d.y = l3;
    *(__nv_bfloat162*)ph = a; *(__nv_bfloat162*)(ph + 2) = b;
    *(__nv_bfloat162*)pl = c; *(__nv_bfloat162*)(pl + 2) = d;
}
__device__ __forceinline__ void split2_store(bf16* ph, bf16* pl, float v0, float v1) {
    bf16 h0, l0, h1, l1;
    splitf(v0, h0, l0); splitf(v1, h1, l1);
    __nv_bfloat162 hh; hh.x = h0; hh.y = h1;
    __nv_bfloat162 ll; ll.x = l0; ll.y = l1;
    *(__nv_bfloat162*)ph = hh;
    *(__nv_bfloat162*)pl = ll;
}
__device__ __forceinline__ float hlval(const bf16* p, size_t plane, size_t i) {
    return __bfloat162float(p[i]) + __bfloat162float(p[plane + i]);
}

// ---------------- PTX helpers ----------------
__device__ __forceinline__ void mma16816(float* d, const uint32_t* a, uint32_t b0, uint32_t b1) {
    asm volatile(
        "mma.sync.aligned.m16n8k16.row.col.f32.bf16.bf16.f32 "
        "{%0,%1,%2,%3},{%4,%5,%6,%7},{%8,%9},{%0,%1,%2,%3};\n"
        : "+f"(d[0]), "+f"(d[1]), "+f"(d[2]), "+f"(d[3])
        : "r"(a[0]), "r"(a[1]), "r"(a[2]), "r"(a[3]), "r"(b0), "r"(b1));
}
__device__ __forceinline__ void ldsm4(uint32_t* r, uint32_t addr) {
    asm volatile("ldmatrix.sync.aligned.m8n8.x4.shared.b16 {%0,%1,%2,%3}, [%4];\n"
                 : "=r"(r[0]), "=r"(r[1]), "=r"(r[2]), "=r"(r[3]) : "r"(addr));
}
__device__ __forceinline__ void cp16(uint32_t dst, const void* src, bool pred) {
    int sz = pred ? 16 : 0;
    asm volatile("cp.async.cg.shared.global [%0], [%1], 16, %2;\n"
                 :: "r"(dst), "l"(src), "r"(sz) : "memory");
}
__device__ __forceinline__ void cp_commit() { asm volatile("cp.async.commit_group;\n" ::: "memory"); }
__device__ __forceinline__ void cp_wait1()  { asm volatile("cp.async.wait_group 1;\n" ::: "memory"); }

// ---------------- mma.sync GEMM 128x128 (single-barrier mainloop) ----------------
#define BK_STAGES 3
#define SMEM_BYTES (BK_STAGES*32768)

template<int EPI, int OUT>
__global__ void __launch_bounds__(256, 2)
bgemm(const bf16* __restrict__ Ah, const bf16* __restrict__ Al, int lda, long long sA,
      const bf16* __restrict__ Bh, const bf16* __restrict__ Bl, int ldb, long long sB,
      float* __restrict__ C, int ldc, long long sC,
      bf16* __restrict__ Ch, long long planeC, int ldch, long long sCh,
      const float* __restrict__ bias, long long sBias,
      const float* __restrict__ aux, int auxMod,
      int M, int N, int K)
{
    extern __shared__ char smd[];
    const int zi = blockIdx.z;
    Ah += (size_t)zi * sA; Al += (size_t)zi * sA;
    Bh += (size_t)zi * sB; Bl += (size_t)zi * sB;
    if (OUT != 2) C += (size_t)zi * sC;
    if (OUT != 0) Ch += (size_t)zi * sCh;
    const float* bp = bias ? (bias + (size_t)zi * sBias) : nullptr;

    const int bm = blockIdx.y * 128;
    const int bn = blockIdx.x * 128;
    const int tid = threadIdx.x, lane = tid & 31, warp = tid >> 5;
    const int wm = warp & 1, wn = warp >> 1;

    const uint32_t smem_base = (uint32_t)__cvta_generic_to_shared(smd);

    auto load_stage = [&](int s, int kt) {
        const int k0 = kt * 32;
        const uint32_t As = smem_base + s * 32768;
        const uint32_t Bs = As + 16384;
#pragma unroll
        for (int i = 0; i < 4; i++) {
            int lin = i * 256 + tid;
            int row = lin >> 3, ch = lin & 7;
            const bf16* srcA = ((ch & 4) ? Al : Ah) + (size_t)(bm + row) * lda + k0 + (ch & 3) * 8;
            cp16(As + row * 128 + ((ch ^ (row & 7)) * 16), srcA, true);
        }
#pragma unroll
        for (int i = 0; i < 4; i++) {
            int lin = i * 256 + tid;
            int row = lin >> 3, ch = lin & 7;
            bool ok = (bn + row) < N;
            const bf16* srcB = ((ch & 4) ? Bl : Bh) +
                               (ok ? ((size_t)(bn + row) * ldb + k0 + (ch & 3) * 8) : 0);
            cp16(Bs + row * 128 + ((ch ^ (row & 7)) * 16), srcB, ok);
        }
    };

    float acc[4][4][4];
#pragma unroll
    for (int i = 0; i < 4; i++)
#pragma unroll
        for (int j = 0; j < 4; j++)
#pragma unroll
            for (int q = 0; q < 4; q++) acc[i][j][q] = 0.0f;

    const int nk = K / 32;
    if (nk > 0) load_stage(0, 0);
    cp_commit();
    if (nk > 1) load_stage(1, 1);
    cp_commit();

    const int g  = lane >> 3;
    const int lr = lane & 7;
    const int aRow0 = wm * 64 + (g & 1) * 8 + lr;
    const int bRow0 = wn * 32 + (g & 1) * 8 + lr;
    const int chHi  = (g >> 1);

    for (int kt = 0; kt < nk; kt++) {
        cp_wait1();
        __syncthreads();
        // prefetch kt+2 into slot (kt+2)%3 == (kt-1)%3; all reads of that slot
        // completed before the barrier above (they happened in iteration kt-1).
        if (kt + 2 < nk) load_stage((kt + 2) % BK_STAGES, kt + 2);
        cp_commit();

        const uint32_t As = smem_base + (kt % BK_STAGES) * 32768;
        const uint32_t Bs = As + 16384;

#pragma unroll
        for (int step = 0; step < 2; step++) {
            uint32_t ah[4][4], al[4][4], bh[2][4], bl[2][4];
            const int cH = ((step * 2 + chHi) ^ lr) * 16;
            const int cL = ((4 + step * 2 + chHi) ^ lr) * 16;
#pragma unroll
            for (int mt = 0; mt < 4; mt++) {
                uint32_t rb = As + (uint32_t)(aRow0 + mt * 16) * 128;
                ldsm4(ah[mt], rb + cH);
                ldsm4(al[mt], rb + cL);
            }
#pragma unroll
            for (int p = 0; p < 2; p++) {
                uint32_t rb = Bs + (uint32_t)(bRow0 + p * 16) * 128;
                ldsm4(bh[p], rb + cH);
                ldsm4(bl[p], rb + cL);
            }
#pragma unroll
            for (int nt = 0; nt < 4; nt++) {
                const int p = nt >> 1, o = nt & 1;
                const uint32_t b0h = bh[p][o], b1h = bh[p][o + 2];
                const uint32_t b0l = bl[p][o], b1l = bl[p][o + 2];
#pragma unroll
                for (int mt = 0; mt < 4; mt++) {
                    mma16816(acc[mt][nt], ah[mt], b0h, b1h);
                    mma16816(acc[mt][nt], ah[mt], b0l, b1l);
                    mma16816(acc[mt][nt], al[mt], b0h, b1h);
                }
            }
        }
    }

    const int r_ep = lane >> 2, c_ep = lane & 3;
#pragma unroll
    for (int mt = 0; mt < 4; mt++) {
        const int m0 = bm + wm * 64 + mt * 16 + r_ep;
#pragma unroll
        for (int nt = 0; nt < 4; nt++) {
            const int n0 = bn + wn * 32 + nt * 8 + 2 * c_ep;   // always even
#pragma unroll
            for (int half = 0; half < 2; half++) {
                const int m = m0 + half * 8;
                if (n0 < N) {
                    float v0 = acc[mt][nt][half * 2 + 0];
                    float v1 = acc[mt][nt][half * 2 + 1];
                    if (bp) { v0 += bp[n0]; v1 += bp[n0 + 1]; }
                    if (EPI == 1)      { v0 = geluf(v0);     v1 = geluf(v1); }
                    else if (EPI == 3) { v0 = softplusf(v0); v1 = softplusf(v1); }
                    else if (EPI == 4) {
                        const float* ar = aux + (size_t)(m % auxMod) * ldc;
                        v0 += ar[n0]; v1 += ar[n0 + 1];
                    } else if (EPI == 5) {
                        const float* ar = aux + (size_t)m * ldc;
                        v0 += ar[n0]; v1 += ar[n0 + 1];
                    }
                    if (OUT != 2) {
                        float2 f2; f2.x = v0; f2.y = v1;
                        *(float2*)(C + (size_t)m * ldc + n0) = f2;
                    }
                    if (OUT != 0) {
                        size_t o = (size_t)m * ldch + n0;
                        split2_store(Ch + o, Ch + planeC + o, v0, v1);
                    }
                }
            }
        }
    }
}

// ---------------- mma.sync GEMM 64x128 (small shapes, single-barrier) ----------------
#define SMEM64_BYTES (3*24576)

template<int EPI, int OUT>
__global__ void __launch_bounds__(256, 2)
bgemm64(const bf16* __restrict__ Ah, const bf16* __restrict__ Al, int lda, long long sA,
        const bf16* __restrict__ Bh, const bf16* __restrict__ Bl, int ldb, long long sB,
        float* __restrict__ C, int ldc, long long sC,
        bf16* __restrict__ Ch, long long planeC, int ldch, long long sCh,
        const float* __restrict__ bias, long long sBias,
        const float* __restrict__ aux, int auxMod,
        int M, int N, int K)
{
    extern __shared__ char smd[];
    const int zi = blockIdx.z;
    Ah += (size_t)zi * sA; Al += (size_t)zi * sA;
    Bh += (size_t)zi * sB; Bl += (size_t)zi * sB;
    if (OUT != 2) C += (size_t)zi * sC;
    if (OUT != 0) Ch += (size_t)zi * sCh;
    const float* bp = bias ? (bias + (size_t)zi * sBias) : nullptr;

    const int bm = blockIdx.y * 64;
    const int bn = blockIdx.x * 128;
    const int tid = threadIdx.x, lane = tid & 31, warp = tid >> 5;
    const int wm = warp & 1, wn = warp >> 1;

    const uint32_t smem_base = (uint32_t)__cvta_generic_to_shared(smd);

    auto load_stage = [&](int s, int kt) {
        const int k0 = kt * 32;
        const uint32_t As = smem_base + s * 24576;
        const uint32_t Bs = As + 8192;
#pragma unroll
        for (int i = 0; i < 2; i++) {
            int lin = i * 256 + tid;
            int row = lin >> 3, ch = lin & 7;
            const bf16* srcA = ((ch & 4) ? Al : Ah) + (size_t)(bm + row) * lda + k0 + (ch & 3) * 8;
            cp16(As + row * 128 + ((ch ^ (row & 7)) * 16), srcA, true);
        }
#pragma unroll
        for (int i = 0; i < 4; i++) {
            int lin = i * 256 + tid;
            int row = lin >> 3, ch = lin & 7;
            bool ok = (bn + row) < N;
            const bf16* srcB = ((ch & 4) ? Bl : Bh) +
                               (ok ? ((size_t)(bn + row) * ldb + k0 + (ch & 3) * 8) : 0);
            cp16(Bs + row * 128 + ((ch ^ (row & 7)) * 16), srcB, ok);
        }
    };

    float acc[2][4][4];
#pragma unroll
    for (int i = 0; i < 2; i++)
#pragma unroll
        for (int j = 0; j < 4; j++)
#pragma unroll
            for (int q = 0; q < 4; q++) acc[i][j][q] = 0.0f;

    const int nk = K / 32;
    if (nk > 0) load_stage(0, 0);
    cp_commit();
    if (nk > 1) load_stage(1, 1);
    cp_commit();

    const int g  = lane >> 3;
    const int lr = lane & 7;
    const int aRow0 = wm * 32 + (g & 1) * 8 + lr;
    const int bRow0 = wn * 32 + (g & 1) * 8 + lr;
    const int chHi  = (g >> 1);

    for (int kt = 0; kt < nk; kt++) {
        cp_wait1();
        __syncthreads();
        if (kt + 2 < nk) load_stage((kt + 2) % 3, kt + 2);
        cp_commit();

        const uint32_t As = smem_base + (kt % 3) * 24576;
        const uint32_t Bs = As + 8192;

#pragma unroll
        for (int step = 0; step < 2; step++) {
            uint32_t ah[2][4], al[2][4], bh[2][4], bl[2][4];
            const int cH = ((step * 2 + chHi) ^ lr) * 16;
            const int cL = ((4 + step * 2 + chHi) ^ lr) * 16;
#pragma unroll
            for (int mt = 0; mt < 2; mt++) {
                uint32_t rb = As + (uint32_t)(aRow0 + mt * 16) * 128;
                ldsm4(ah[mt], rb + cH);
                ldsm4(al[mt], rb + cL);
            }
#pragma unroll
            for (int p = 0; p < 2; p++) {
                uint32_t rb = Bs + (uint32_t)(bRow0 + p * 16) * 128;
                ldsm4(bh[p], rb + cH);
                ldsm4(bl[p], rb + cL);
            }
#pragma unroll
            for (int nt = 0; nt < 4; nt++) {
                const int p = nt >> 1, o = nt & 1;
                const uint32_t b0h = bh[p][o], b1h = bh[p][o + 2];
                const uint32_t b0l = bl[p][o], b1l = bl[p][o + 2];
#pragma unroll
                for (int mt = 0; mt < 2; mt++) {
                    mma16816(acc[mt][nt], ah[mt], b0h, b1h);
                    mma16816(acc[mt][nt], ah[mt], b0l, b1l);
                    mma16816(acc[mt][nt], al[mt], b0h, b1h);
                }
            }
        }
    }

    const int r_ep = lane >> 2, c_ep = lane & 3;
#pragma unroll
    for (int mt = 0; mt < 2; mt++) {
        const int m0 = bm + wm * 32 + mt * 16 + r_ep;
#pragma unroll
        for (int nt = 0; nt < 4; nt++) {
            const int n0 = bn + wn * 32 + nt * 8 + 2 * c_ep;
#pragma unroll
            for (int half = 0; half < 2; half++) {
                const int m = m0 + half * 8;
                if (n0 < N) {
                    float v0 = acc[mt][nt][half * 2 + 0];
                    float v1 = acc[mt][nt][half * 2 + 1];
                    if (bp) { v0 += bp[n0]; v1 += bp[n0 + 1]; }
                    if (EPI == 1)      { v0 = geluf(v0);     v1 = geluf(v1); }
                    else if (EPI == 3) { v0 = softplusf(v0); v1 = softplusf(v1); }
                    else if (EPI == 4) {
                        const float* ar = aux + (size_t)(m % auxMod) * ldc;
                        v0 += ar[n0]; v1 += ar[n0 + 1];
                    } else if (EPI == 5) {
                        const float* ar = aux + (size_t)m * ldc;
                        v0 += ar[n0]; v1 += ar[n0 + 1];
                    }
                    if (OUT != 2) {
                        float2 f2; f2.x = v0; f2.y = v1;
                        *(float2*)(C + (size_t)m * ldc + n0) = f2;
                    }
                    if (OUT != 0) {
                        size_t o = (size_t)m * ldch + n0;
                        split2_store(Ch + o, Ch + planeC + o, v0, v1);
                    }
                }
            }
        }
    }
}

// ---------------- fused prepass (vectorized contiguous segments, 4 elems/thread) ----------------
// blocks: [0,256) wpos2 | [256,512) wpmix | [512,768) wmixA-a | [768,1024) wmixA-b
// [1024,3072) win | [3072,3200) wxp | [3200,3264) wdt | [3264,3776) wf1 | [3776,4288) wf2
// [4288,6336) wTout-a (scalar) | [6336,8384) wTout-b (scalar) | [8384,10432) pos_hidden (scalar)
#define PRE_BLOCKS 10432

__global__ void fused_pre_k(
    const float* __restrict__ pos_w1, const float* __restrict__ pos_b1,
    const float* __restrict__ pos_w2, const float* __restrict__ mix_w,
    const float* __restrict__ m_out_w, const float* __restrict__ m_in_w,
    const float* __restrict__ m_xproj_w, const float* __restrict__ m_dt_w,
    const float* __restrict__ ffn_w1, const float* __restrict__ ffn_w2,
    bf16* __restrict__ wpos2, bf16* __restrict__ wpmix, bf16* __restrict__ wmixA,
    bf16* __restrict__ wTout, bf16* __restrict__ win, bf16* __restrict__ wxp,
    bf16* __restrict__ wdt, bf16* __restrict__ wf1, bf16* __restrict__ wf2,
    bf16* __restrict__ posh)
{
    const int bid = blockIdx.x, tid = threadIdx.x;
    if (bid < 256) {
        int i = (bid * 256 + tid) * 4;
        float4 v = *(const float4*)&pos_w2[i];
        split4_store(wpos2 + i, wpos2 + 262144 + i, v);
    } else if (bid < 512) {
        int i = ((bid - 256) * 256 + tid) * 4;
        int r = i >> 9, c = i & 511;
        float4 v = *(const float4*)&mix_w[1024 + r * 1536 + c];
        split4_store(wpmix + i, wpmix + 262144 + i, v);
    } else if (bid < 768) {
        int i = ((bid - 512) * 256 + tid) * 4;
        int r = i >> 9, c = i & 511;
        float4 v = *(const float4*)&mix_w[r * 1536 + c];
        split4_store(wmixA + i, wmixA + 524288 + i, v);
    } else if (bid < 1024) {
        int i = ((bid - 768) * 256 + tid) * 4;
        int r = i >> 9, c = i & 511;
        float4 v = *(const float4*)&mix_w[512 + r * 1536 + c];
        split4_store(wmixA + 262144 + i, wmixA + 524288 + 262144 + i, v);
    } else if (bid < 3072) {
        int i = ((bid - 1024) * 256 + tid) * 4;
        float4 v = *(const float4*)&m_in_w[i];
        split4_store(win + i, win + 2097152 + i, v);
    } else if (bid < 3200) {
        int i = ((bid - 3072) * 256 + tid) * 4;
        float4 v = *(const float4*)&m_xproj_w[i];
        split4_store(wxp + i, wxp + 131072 + i, v);
    } else if (bid < 3264) {
        int i = ((bid - 3200) * 256 + tid) * 4;
        float4 v = *(const float4*)&m_dt_w[i];
        split4_store(wdt + i, wdt + 65536 + i, v);
    } else if (bid < 3776) {
        int i = ((bid - 3264) * 256 + tid) * 4;
        float4 v = *(const float4*)&ffn_w1[i];
        split4_store(wf1 + i, wf1 + 524288 + i, v);
    } else if (bid < 4288) {
        int i = ((bid - 3776) * 256 + tid) * 4;
        float4 v = *(const float4*)&ffn_w2[i];
        split4_store(wf2 + i, wf2 + 524288 + i, v);
    } else if (bid < 6336) {
        int i = (bid - 4288) * 256 + tid;    // transpose: dst(e,j) = src(j,e)
        int e = i >> 9, j = i & 511;
        bf16 h, l;
        splitf(m_out_w[(size_t)j * 1024 + e], h, l);
        wTout[i] = h; wTout[1048576 + i] = l;
    } else if (bid < 8384) {
        int i = (bid - 6336) * 256 + tid;
        int e = i >> 9, j = i & 511;
        bf16 h, l;
        splitf(m_out_w[524288 + (size_t)j * 1024 + e], h, l);
        wTout[524288 + i] = h; wTout[1048576 + 524288 + i] = l;
    } else {
        int i = (bid - 8384) * 256 + tid;
        int t = i >> 9, c = i & 511;
        int y = t >> 5, x = t & 31;
        const float PI = 3.14159265358979323846f;
        float yy = ((y + 0.5f) / 32.0f) * 2.0f - 1.0f;
        float xx = ((x + 0.5f) / 32.0f) * 2.0f - 1.0f;
        float f2 = sinf(PI * yy), f3 = cosf(PI * yy);
        float f4 = sinf(PI * xx), f5 = cosf(PI * xx);
        const float* w = pos_w1 + c * 6;
        float v = pos_b1[c] + yy * w[0] + xx * w[1] + f2 * w[2] + f3 * w[3] + f4 * w[4] + f5 * w[5];
        v = geluf(v);
        bf16 h, l; splitf(v, h, l);
        posh[i] = h; posh[524288 + i] = l;
    }
}

// ---------------- LN(tokens) + pos -> hi/lo ----------------
__global__ void ln_add_pos_k(const float* __restrict__ x,
                             const float* __restrict__ g, const float* __restrict__ b,
                             const float* __restrict__ pos, bf16* __restrict__ out)
{
    __shared__ float sh[16];
    const int row = blockIdx.x;
    const int tid = threadIdx.x;
    float4 v = ((const float4*)(x + (size_t)row * DIM))[tid];
    float s = v.x + v.y + v.z + v.w;
    float q = v.x * v.x + v.y * v.y + v.z * v.z + v.w * v.w;
#pragma unroll
    for (int o = 16; o; o >>= 1) {
        s += __shfl_xor_sync(0xffffffffu, s, o);
        q += __shfl_xor_sync(0xffffffffu, q, o);
    }
    if ((tid & 31) == 0) { sh[tid >> 5] = s; sh[4 + (tid >> 5)] = q; }
    __syncthreads();
    if (tid == 0) {
        float S = sh[0] + sh[1] + sh[2] + sh[3];
        float Q = sh[4] + sh[5] + sh[6] + sh[7];
        float mu = S * (1.0f / DIM);
        float var = Q * (1.0f / DIM) - mu * mu;
        sh[8] = mu; sh[9] = rsqrtf(var + 1e-5f);
    }
    __syncthreads();
    const float mu = sh[8], rs = sh[9];
    const int t = row & (LSEQ - 1);
    float4 g4 = ((const float4*)g)[tid];
    float4 b4 = ((const float4*)b)[tid];
    float4 p4 = ((const float4*)(pos + (size_t)t * DIM))[tid];
    float4 r;
    r.x = (v.x - mu) * rs * g4.x + b4.x + p4.x;
    r.y = (v.y - mu) * rs * g4.y + b4.y + p4.y;
    r.z = (v.z - mu) * rs * g4.z + b4.z + p4.z;
    r.w = (v.w - mu) * rs * g4.w + b4.w + p4.w;
    bf16* ph = out + (size_t)row * DIM + tid * 4;
    split4_store(ph, ph + (long long)ROWS * DIM, r);
}

// ---------------- causal conv + SiLU ----------------
__global__ void conv_silu_k(const float* __restrict__ xz,
                            const float* __restrict__ cw, const float* __restrict__ cb,
                            bf16* __restrict__ xch)
{
    size_t gidx = (size_t)blockIdx.x * 256 + threadIdx.x;
    int dq  = (int)(gidx & 255);
    int row = (int)((gidx >> 8) & (ROWS - 1));
    int dir = (int)(gidx >> 21);
    int d = dq * 4;
    int t = row & (LSEQ - 1);
    int b = row >> 10;

    float4 acc = *(const float4*)&cb[dir * DI + d];
    const float4* wrow = (const float4*)&cw[(size_t)(dir * DI + d) * 4];
    float4 w0 = wrow[0], w1 = wrow[1], w2 = wrow[2], w3 = wrow[3];

#pragma unroll
    for (int k = 0; k < 4; k++) {
        int off = dir ? (3 - k) : (k - 3);
        int tt = t + off;
        if (tt >= 0 && tt < LSEQ) {
            float4 v = *(const float4*)&xz[((size_t)(b * LSEQ + tt)) * 4096 + dir * 2048 + d];
            acc.x = fmaf(fcomp(w0, k), v.x, acc.x);
            acc.y = fmaf(fcomp(w1, k), v.y, acc.y);
            acc.z = fmaf(fcomp(w2, k), v.z, acc.z);
            acc.w = fmaf(fcomp(w3, k), v.w, acc.w);
        }
    }
    float4 r;
    r.x = siluf(acc.x); r.y = siluf(acc.y); r.z = siluf(acc.z); r.w = siluf(acc.w);
    bf16* ph = xch + gidx * 4;
    split4_store(ph, ph + XPLANE, r);
}

// ================= chunked selective scan =================
__global__ void scan_part1_k(const float* __restrict__ dsp, const bf16* __restrict__ xch,
                             const float* __restrict__ proj, const float* __restrict__ A_log,
                             float* __restrict__ hend, float* __restrict__ prodv)
{
    const int chunk = blockIdx.x >> 3;
    const int dblk  = blockIdx.x & 7;
    const int b = blockIdx.y, dir = blockIdx.z;
    const int d = dblk * 128 + threadIdx.x;

    float a[DS];
    bool fast = true;
#pragma unroll
    for (int s = 0; s < DS; s++) {
        a[s] = -expf(A_log[((size_t)dir * DI + d) * DS + s]);
        fast = fast && (fabsf(a[s] + (float)(s + 1)) < 1e-4f * (float)(s + 1));
    }

    const size_t base_row = (size_t)dir * ROWS + (size_t)b * LSEQ;
    __shared__ float sB[CLEN][DS];
    for (int i = threadIdx.x; i < CLEN * DS; i += 128) {
        int st = chunk * CLEN + (i >> 4);
        int c = i & 15;
        int r = dir ? (LSEQ - 1 - st) : st;
        sB[i >> 4][c] = proj[(base_row + r) * 64 + 32 + c];
    }
    __syncthreads();

    float h[DS], p[DS];
#pragma unroll
    for (int s = 0; s < DS; s++) h[s] = 0.0f;

    if (fast) {
        float prodE1 = 1.0f;
        for (int i = 0; i < CLEN; i++) {
            int st = chunk * CLEN + i;
            int r = dir ? (LSEQ - 1 - st) : st;
            size_t ro = (base_row + r) * (size_t)DI + d;
            float delta = dsp[ro];
            float x     = hlval(xch, XPLANE, ro);
            float dx    = delta * x;
            float e1 = __expf(-delta);
            prodE1 *= e1;
            float ep = e1;
#pragma unroll
            for (int s = 0; s < DS; s++) {
                h[s] = fmaf(h[s], ep, dx * sB[i][s]);
                ep *= e1;
            }
        }
        float ep = prodE1;
#pragma unroll
        for (int s = 0; s < DS; s++) { p[s] = ep; ep *= prodE1; }
    } else {
#pragma unroll
        for (int s = 0; s < DS; s++) p[s] = 1.0f;
        for (int i = 0; i < CLEN; i++) {
            int st = chunk * CLEN + i;
            int r = dir ? (LSEQ - 1 - st) : st;
            size_t ro = (base_row + r) * (size_t)DI + d;
            float delta = dsp[ro];
            float x     = hlval(xch, XPLANE, ro);
            float dx    = delta * x;
#pragma unroll
            for (int s = 0; s < DS; s++) {
                float e = __expf(delta * a[s]);
                h[s] = fmaf(h[s], e, dx * sB[i][s]);
                p[s] *= e;
            }
        }
    }

    const int CH = (dir * BATCH + b) * DI + d;
    size_t o = ((size_t)chunk * NCH + CH) * DS;
#pragma unroll
    for (int s = 0; s < DS; s++) { hend[o + s] = h[s]; prodv[o + s] = p[s]; }
}

__global__ void scan_part2_k(const float* __restrict__ hend, const float* __restrict__ prodv,
                             float* __restrict__ hinit)
{
    int idx = blockIdx.x * 256 + threadIdx.x;
    if (idx >= NCH * DS) return;
    float H = 0.0f;
#pragma unroll 4
    for (int c = 0; c < NCHUNK; c++) {
        size_t o = (size_t)c * (NCH * DS) + idx;
        hinit[o] = H;
        H = fmaf(prodv[o], H, hend[o]);
    }
}

__global__ void scan_part3_k(const float* __restrict__ dsp, const bf16* __restrict__ xch,
                             const float* __restrict__ proj, const float* __restrict__ xz,
                             const float* __restrict__ A_log, const float* __restrict__ Dp,
                             const float* __restrict__ hinit, bf16* __restrict__ ycat)
{
    const int chunk = blockIdx.x >> 3;
    const int dblk  = blockIdx.x & 7;
    const int b = blockIdx.y, dir = blockIdx.z;
    const int d = dblk * 128 + threadIdx.x;

    float a[DS];
    bool fast = true;
#pragma unroll
    for (int s = 0; s < DS; s++) {
        a[s] = -expf(A_log[((size_t)dir * DI + d) * DS + s]);
        fast = fast && (fabsf(a[s] + (float)(s + 1)) < 1e-4f * (float)(s + 1));
    }
    const float Dv = Dp[dir * DI + d];

    const size_t base_row = (size_t)dir * ROWS + (size_t)b * LSEQ;
    const long long plane = (long long)ROWS * 2048;
    __shared__ float sBC[CLEN][32];
    for (int i = threadIdx.x; i < CLEN * 32; i += 128) {
        int st = chunk * CLEN + (i >> 5);
        int c = i & 31;
        int r = dir ? (LSEQ - 1 - st) : st;
        sBC[i >> 5][c] = proj[(base_row + r) * 64 + 32 + c];
    }
    __syncthreads();

    const int CH = (dir * BATCH + b) * DI + d;
    size_t ho = ((size_t)chunk * NCH + CH) * DS;
    float h[DS];
#pragma unroll
    for (int s = 0; s < DS; s++) h[s] = hinit[ho + s];

    if (fast) {
        for (int i = 0; i < CLEN; i++) {
            int st = chunk * CLEN + i;
            int r = dir ? (LSEQ - 1 - st) : st;
            size_t ro = (base_row + r) * (size_t)DI + d;
            float delta = dsp[ro];
            float x     = hlval(xch, XPLANE, ro);
            float dx    = delta * x;
            float y = 0.0f;
            float e1 = __expf(-delta);
            float ep = e1;
#pragma unroll
            for (int s = 0; s < DS; s++) {
                h[s] = fmaf(h[s], ep, dx * sBC[i][s]);
                y = fmaf(h[s], sBC[i][16 + s], y);
                ep *= e1;
            }
            float z = xz[((size_t)(b * LSEQ + r)) * 4096 + dir * 2048 + DI + d];
            float outv = (y + x * Dv) * siluf(z);
            bf16 hh, ll; splitf(outv, hh, ll);
            size_t oo = ((size_t)(b * LSEQ + r)) * 2048 + dir * DI + d;
            ycat[oo] = hh; ycat[plane + oo] = ll;
        }
    } else {
        for (int i = 0; i < CLEN; i++) {
            int st = chunk * CLEN + i;
            int r = dir ? (LSEQ - 1 - st) : st;
            size_t ro = (base_row + r) * (size_t)DI + d;
            float delta = dsp[ro];
            float x     = hlval(xch, XPLANE, ro);
            float dx    = delta * x;
            float y = 0.0f;
#pragma unroll
            for (int s = 0; s < DS; s++) {
                float e = __expf(delta * a[s]);
                h[s] = fmaf(h[s], e, dx * sBC[i][s]);
                y = fmaf(h[s], sBC[i][16 + s], y);
            }
            float z = xz[((size_t)(b * LSEQ + r)) * 4096 + dir * 2048 + DI + d];
            float outv = (y + x * Dv) * siluf(z);
            bf16 hh, ll; splitf(outv, hh, ll);
            size_t oo = ((size_t)(b * LSEQ + r)) * 2048 + dir * DI + d;
            ycat[oo] = hh; ycat[plane + oo] = ll;
        }
    }
}

// ---------------- dual LayerNorm ----------------
__global__ void ln_dual_k(const float* __restrict__ in,
                          const float* __restrict__ g1, const float* __restrict__ b1,
                          const float* __restrict__ g2, const float* __restrict__ b2,
                          float* __restrict__ out1, bf16* __restrict__ out2)
{
    __shared__ float sh[16];
    const int row = blockIdx.x;
    const int tid = threadIdx.x;
    float4 v = ((const float4*)(in + (size_t)row * DIM))[tid];
    float s = v.x + v.y + v.z + v.w;
    float q = v.x * v.x + v.y * v.y + v.z * v.z + v.w * v.w;
#pragma unroll
    for (int o = 16; o; o >>= 1) {
        s += __shfl_xor_sync(0xffffffffu, s, o);
        q += __shfl_xor_sync(0xffffffffu, q, o);
    }
    if ((tid & 31) == 0) { sh[tid >> 5] = s; sh[4 + (tid >> 5)] = q; }
    __syncthreads();
    if (tid == 0) {
        float S = sh[0] + sh[1] + sh[2] + sh[3];
        float Q = sh[4] + sh[5] + sh[6] + sh[7];
        float mu = S * (1.0f / DIM);
        float var = Q * (1.0f / DIM) - mu * mu;
        sh[8] = mu; sh[9] = rsqrtf(var + 1e-5f);
    }
    __syncthreads();
    float mu = sh[8], rs = sh[9];
    float4 g4 = ((const float4*)g1)[tid];
    float4 b4 = ((const float4*)b1)[tid];
    float4 x4;
    x4.x = (v.x - mu) * rs * g4.x + b4.x;
    x4.y = (v.y - mu) * rs * g4.y + b4.y;
    x4.z = (v.z - mu) * rs * g4.z + b4.z;
    x4.w = (v.w - mu) * rs * g4.w + b4.w;
    ((float4*)(out1 + (size_t)row * DIM))[tid] = x4;

    __syncthreads();
    s = x4.x + x4.y + x4.z + x4.w;
    q = x4.x * x4.x + x4.y * x4.y + x4.z * x4.z + x4.w * x4.w;
#pragma unroll
    for (int o = 16; o; o >>= 1) {
        s += __shfl_xor_sync(0xffffffffu, s, o);
        q += __shfl_xor_sync(0xffffffffu, q, o);
    }
    if ((tid & 31) == 0) { sh[tid >> 5] = s; sh[4 + (tid >> 5)] = q; }
    __syncthreads();
    if (tid == 0) {
        float S = sh[0] + sh[1] + sh[2] + sh[3];
        float Q = sh[4] + sh[5] + sh[6] + sh[7];
        float mu2 = S * (1.0f / DIM);
        float var2 = Q * (1.0f / DIM) - mu2 * mu2;
        sh[8] = mu2; sh[9] = rsqrtf(var2 + 1e-5f);
    }
    __syncthreads();
    float mu2 = sh[8], rs2 = sh[9];
    float4 G = ((const float4*)g2)[tid];
    float4 B = ((const float4*)b2)[tid];
    float4 r;
    r.x = (x4.x - mu2) * rs2 * G.x + B.x;
    r.y = (x4.y - mu2) * rs2 * G.y + B.y;
    r.z = (x4.z - mu2) * rs2 * G.z + B.z;
    r.w = (x4.w - mu2) * rs2 * G.w + B.w;
    bf16* ph = out2 + (size_t)row * DIM + tid * 4;
    split4_store(ph, ph + (long long)ROWS * DIM, r);
}

// ---------------- host launcher ----------------
extern "C" void kernel_launch(void* const* d_in, const int* in_sizes, int n_in,
                              void* d_out, int out_size)
{
    const float* tokens    = (const float*)d_in[0];
    const float* in_g      = (const float*)d_in[3];
    const float* in_b      = (const float*)d_in[4];
    const float* pos_w1    = (const float*)d_in[5];
    const float* pos_b1    = (const float*)d_in[6];
    const float* pos_w2    = (const float*)d_in[7];
    const float* pos_b2    = (const float*)d_in[8];
    const float* m_in_w    = (const float*)d_in[9];
    const float* m_conv_w  = (const float*)d_in[10];
    const float* m_conv_b  = (const float*)d_in[11];
    const float* m_xproj_w = (const float*)d_in[12];
    const float* m_dt_w    = (const float*)d_in[13];
    const float* m_dt_b    = (const float*)d_in[14];
    const float* m_A_log   = (const float*)d_in[15];
    const float* m_D       = (const float*)d_in[16];
    const float* m_out_w   = (const float*)d_in[17];
    const float* mix_w     = (const float*)d_in[18];
    const float* mix_b     = (const float*)d_in[19];
    const float* dn_g      = (const float*)d_in[20];
    const float* dn_b      = (const float*)d_in[21];
    const float* fn_g      = (const float*)d_in[22];
    const float* fn_b      = (const float*)d_in[23];
    const float* ffn_w1    = (const float*)d_in[24];
    const float* ffn_b1    = (const float*)d_in[25];
    const float* ffn_w2    = (const float*)d_in[26];
    const float* ffn_b2    = (const float*)d_in[27];
    float* out = (float*)d_out;

    float *pos, *pos_mix, *xz, *proj, *dsp, *dmix, *dln, *hend, *prodv, *hinit;
    bf16 *sin_hl, *posh_hl, *pos_hl, *wpos2, *wpmix, *wmixA, *wTout, *win, *wxp, *wdt, *wf1, *wf2;
    bf16 *xc_hl, *proj_hl, *ycat_hl, *wc_hl, *lnf_hl, *h1_hl;
    cudaGetSymbolAddress((void**)&pos,     g_pos);
    cudaGetSymbolAddress((void**)&pos_mix, g_pos_mix);
    cudaGetSymbolAddress((void**)&xz,      g_xz);
    cudaGetSymbolAddress((void**)&proj,    g_proj);
    cudaGetSymbolAddress((void**)&dsp,     g_dsp);
    cudaGetSymbolAddress((void**)&dmix,    g_dmix);
    cudaGetSymbolAddress((void**)&dln,     g_dln);
    cudaGetSymbolAddress((void**)&hend,    g_hend);
    cudaGetSymbolAddress((void**)&prodv,   g_prod);
    cudaGetSymbolAddress((void**)&hinit,   g_hinit);
    cudaGetSymbolAddress((void**)&sin_hl,  hl_scan_in);
    cudaGetSymbolAddress((void**)&posh_hl, hl_pos_h);
    cudaGetSymbolAddress((void**)&pos_hl,  hl_pos);
    cudaGetSymbolAddress((void**)&wpos2,   hl_w_pos2);
    cudaGetSymbolAddress((void**)&wpmix,   hl_w_pmix);
    cudaGetSymbolAddress((void**)&wmixA,   hl_w_mixA);
    cudaGetSymbolAddress((void**)&wTout,   hl_wT_out);
    cudaGetSymbolAddress((void**)&win,     hl_w_in);
    cudaGetSymbolAddress((void**)&wxp,     hl_w_xp);
    cudaGetSymbolAddress((void**)&wdt,     hl_w_dt);
    cudaGetSymbolAddress((void**)&wf1,     hl_w_f1);
    cudaGetSymbolAddress((void**)&wf2,     hl_w_f2);
    cudaGetSymbolAddress((void**)&xc_hl,   hl_xc);
    cudaGetSymbolAddress((void**)&proj_hl, hl_proj);
    cudaGetSymbolAddress((void**)&ycat_hl, hl_ycat);
    cudaGetSymbolAddress((void**)&wc_hl,   hl_wc);
    cudaGetSymbolAddress((void**)&lnf_hl,  hl_lnf);
    cudaGetSymbolAddress((void**)&h1_hl,   hl_h1);

    cudaFuncSetAttribute(bgemm<0,0>, cudaFuncAttributeMaxDynamicSharedMemorySize, SMEM_BYTES);
    cudaFuncSetAttribute(bgemm<4,0>, cudaFuncAttributeMaxDynamicSharedMemorySize, SMEM_BYTES);
    cudaFuncSetAttribute(bgemm<1,2>, cudaFuncAttributeMaxDynamicSharedMemorySize, SMEM_BYTES);
    cudaFuncSetAttribute(bgemm<5,0>, cudaFuncAttributeMaxDynamicSharedMemorySize, SMEM_BYTES);
    cudaFuncSetAttribute(bgemm64<0,0>, cudaFuncAttributeMaxDynamicSharedMemorySize, SMEM64_BYTES);
    cudaFuncSetAttribute(bgemm64<0,1>, cudaFuncAttributeMaxDynamicSharedMemorySize, SMEM64_BYTES);
    cudaFuncSetAttribute(bgemm64<0,2>, cudaFuncAttributeMaxDynamicSharedMemorySize, SMEM64_BYTES);
    cudaFuncSetAttribute(bgemm64<3,0>, cudaFuncAttributeMaxDynamicSharedMemorySize, SMEM64_BYTES);

    // 1: fused converts + pos_hidden
    fused_pre_k<<<PRE_BLOCKS, 256>>>(pos_w1, pos_b1, pos_w2, mix_w, m_out_w, m_in_w,
                                     m_xproj_w, m_dt_w, ffn_w1, ffn_w2,
                                     wpos2, wpmix, wmixA, wTout, win, wxp, wdt, wf1, wf2,
                                     posh_hl);
    // 2: pos = gelu_h @ pos_w2^T + b2
    bgemm64<0,1><<<dim3(4,16,1), 256, SMEM64_BYTES>>>(
        posh_hl, posh_hl + LSEQ*DIM, 512, 0,  wpos2, wpos2 + 512*512, 512, 0,
        pos, 512, 0,  pos_hl, (long long)LSEQ*DIM, 512, 0,
        pos_b2, 0, nullptr, 1, LSEQ, 512, 512);
    // 3: scan_in = LN(tokens) + pos
    ln_add_pos_k<<<ROWS, 128>>>(tokens, in_g, in_b, pos, sin_hl);
    // 4: xz = scan_in @ in_w^T (fp32 out)  <-- profiled slot
    bgemm<0,0><<<dim3(32,64,1), 256, SMEM_BYTES>>>(
        sin_hl, sin_hl + (long long)ROWS*DIM, 512, 0,
        win, win + (long long)4096*512, 512, 0,
        xz, 4096, 0, nullptr, 0, 0, 0,
        nullptr, 0, nullptr, 1, ROWS, 4096, 512);

    conv_silu_k<<<(2*ROWS*DI)/1024, 256>>>(xz, m_conv_w, m_conv_b, xc_hl);
    // proj = xc @ xproj^T per dir
    bgemm64<0,1><<<dim3(1,128,2), 256, SMEM64_BYTES>>>(
        xc_hl, xc_hl + (long long)2*ROWS*DI, 1024, (long long)ROWS*DI,
        wxp, wxp + (long long)128*1024, 1024, (long long)64*1024,
        proj, 64, (long long)ROWS*64,
        proj_hl, (long long)2*ROWS*64, 64, (long long)ROWS*64,
        nullptr, 0, nullptr, 1, ROWS, 64, 1024);
    // dsp = softplus(dt @ dt_w^T + dt_b) (fp32 out)
    bgemm64<3,0><<<dim3(8,128,2), 256, SMEM64_BYTES>>>(
        proj_hl, proj_hl + (long long)2*ROWS*64, 64, (long long)ROWS*64,
        wdt, wdt + (long long)2048*32, 32, (long long)1024*32,
        dsp, 1024, (long long)ROWS*DI, nullptr, 0, 0, 0,
        m_dt_b, 1024, nullptr, 1, ROWS, 1024, 32);

    // chunked scan
    scan_part1_k<<<dim3(8*NCHUNK, BATCH, 2), 128>>>(dsp, xc_hl, proj, m_A_log, hend, prodv);
    scan_part2_k<<<(NCH*DS)/256, 256>>>(hend, prodv, hinit);
    scan_part3_k<<<dim3(8*NCHUNK, BATCH, 2), 128>>>(dsp, xc_hl, proj, xz, m_A_log, m_D, hinit, ycat_hl);

    // pos_mix = pos @ mix_w[:,1024:1536]^T + mix_b
    bgemm64<0,0><<<dim3(4,16,1), 256, SMEM64_BYTES>>>(
        pos_hl, pos_hl + LSEQ*DIM, 512, 0,  wpmix, wpmix + 512*512, 512, 0,
        pos_mix, 512, 0,  nullptr, 0, 0, 0,
        mix_b, 0, nullptr, 1, LSEQ, 512, 512);
    // Wc[dir] = mix_w_slice @ out_w[dir]
    bgemm64<0,2><<<dim3(8,8,2), 256, SMEM64_BYTES>>>(
        wmixA, wmixA + (long long)2*512*512, 512, (long long)512*512,
        wTout, wTout + (long long)2*1024*512, 512, (long long)1024*512,
        nullptr, 0, 0,
        wc_hl, (long long)512*2048, 2048, 1024,
        nullptr, 0, nullptr, 1, 512, 1024, 512);
    // dmix = ycat @ Wc^T + pos_mix
    bgemm<4,0><<<dim3(4,64,1), 256, SMEM_BYTES>>>(
        ycat_hl, ycat_hl + (long long)ROWS*2048, 2048, 0,
        wc_hl, wc_hl + (long long)512*2048, 2048, 0,
        dmix, 512, 0, nullptr, 0, 0, 0,
        nullptr, 0, pos_mix, LSEQ, ROWS, 512, 2048);
    ln_dual_k<<<ROWS, 128>>>(dmix, dn_g, dn_b, fn_g, fn_b, dln, lnf_hl);
    bgemm<1,2><<<dim3(8,64,1), 256, SMEM_BYTES>>>(
        lnf_hl, lnf_hl + (long long)ROWS*DIM, 512, 0,
        wf1, wf1 + (long long)1024*512, 512, 0,
        nullptr, 1024, 0,
        h1_hl, (long long)ROWS*HID, 1024, 0,
        ffn_b1, 0, nullptr, 1, ROWS, 1024, 512);
    bgemm<5,0><<<dim3(4,64,1), 256, SMEM_BYTES>>>(
        h1_hl, h1_hl + (long long)ROWS*HID, 1024, 0,
        wf2, wf2 + (long long)512*1024, 1024, 0,
        out, 512, 0, nullptr, 0, 0, 0,
        ffn_b2, 0, dln, 1, ROWS, 512, 1024);

    (void)in_sizes; (void)n_in; (void)out_size;
}

// round 17
// speedup vs baseline: 1.2264x; 1.0490x over previous
#include <cuda_runtime.h>
#include <cuda_bf16.h>
#include <cstdint>
#include <math.h>

#define BATCH 8
#define LSEQ  1024
#define DIM   512
#define DI    1024
#define DS    16
#define HID   1024
#define ROWS  (BATCH*LSEQ)    // 8192
#define NCHUNK 32
#define CLEN   32
#define NCH    16384
#define XPLANE ((size_t)2*ROWS*DI)

typedef __nv_bfloat16 bf16;

// ---------------- fp32 scratch ----------------
__device__ float g_pos    [LSEQ*DIM];
__device__ float g_pos_mix[LSEQ*DIM];
__device__ float g_xz     [ROWS*4096];
__device__ float g_proj   [2*ROWS*64];
__device__ float g_dsp    [2*ROWS*DI];
__device__ float g_dmix   [ROWS*DIM];
__device__ float g_dln    [ROWS*DIM];
__device__ float g_hend [NCHUNK*NCH*DS];
__device__ float g_prod [NCHUNK*NCH*DS];
__device__ float g_hinit[NCHUNK*NCH*DS];

// ---------------- bf16 hi/lo scratch ----------------
__device__ __align__(16) bf16 hl_scan_in[2*ROWS*DIM];
__device__ __align__(16) bf16 hl_pos_h  [2*LSEQ*DIM];
__device__ __align__(16) bf16 hl_pos    [2*LSEQ*DIM];
__device__ __align__(16) bf16 hl_w_pos2 [2*DIM*DIM];
__device__ __align__(16) bf16 hl_w_pmix [2*DIM*DIM];
__device__ __align__(16) bf16 hl_w_mixA [2*2*DIM*DIM];
__device__ __align__(16) bf16 hl_wT_out [2*2*DI*DIM];
__device__ __align__(16) bf16 hl_w_in   [2*4096*DIM];
__device__ __align__(16) bf16 hl_w_xp   [2*2*64*DI];
__device__ __align__(16) bf16 hl_w_dt   [2*2*DI*32];
__device__ __align__(16) bf16 hl_w_f1   [2*HID*DIM];
__device__ __align__(16) bf16 hl_w_f2   [2*DIM*HID];
__device__ __align__(16) bf16 hl_xc     [2*2*ROWS*DI];
__device__ __align__(16) bf16 hl_proj   [2*2*ROWS*64];
__device__ __align__(16) bf16 hl_ycat   [2*ROWS*2048];
__device__ __align__(16) bf16 hl_wc     [2*DIM*2048];
__device__ __align__(16) bf16 hl_lnf    [2*ROWS*DIM];
__device__ __align__(16) bf16 hl_h1     [2*ROWS*HID];

// ---------------- math helpers ----------------
__device__ __forceinline__ float geluf(float x) {
    return 0.5f * x * (1.0f + erff(x * 0.70710678118654752440f));
}
__device__ __forceinline__ float siluf(float x) { return x / (1.0f + __expf(-x)); }
__device__ __forceinline__ float softplusf(float x) { return (x > 20.0f) ? x : log1pf(__expf(x)); }
__device__ __forceinline__ void splitf(float v, bf16& h, bf16& l) {
    h = __float2bfloat16(v);
    l = __float2bfloat16(v - __bfloat162float(h));
}
__device__ __forceinline__ float fcomp(float4 f, int k) {
    return k == 0 ? f.x : (k == 1 ? f.y : (k == 2 ? f.z : f.w));
}
__device__ __forceinline__ void split4_store(bf16* ph, bf16* pl, float4 v) {
    bf16 h0, l0, h1, l1, h2, l2, h3, l3;
    splitf(v.x, h0, l0); splitf(v.y, h1, l1);
    splitf(v.z, h2, l2); splitf(v.w, h3, l3);
    __nv_bfloat162 a; a.x = h0; a.y = h1;
    __nv_bfloat162 b; b.x = h2; b.y = h3;
    __nv_bfloat162 c; c.x = l0; c.y = l1;
    __nv_bfloat162 d; d.x = l2; d.y = l3;
    *(__nv_bfloat162*)ph = a; *(__nv_bfloat162*)(ph + 2) = b;
    *(__nv_bfloat162*)pl = c; *(__nv_bfloat162*)(pl + 2) = d;
}
__device__ __forceinline__ void split2_store(bf16* ph, bf16* pl, float v0, float v1) {
    bf16 h0, l0, h1, l1;
    splitf(v0, h0, l0); splitf(v1, h1, l1);
    __nv_bfloat162 hh; hh.x = h0; hh.y = h1;
    __nv_bfloat162 ll; ll.x = l0; ll.y = l1;
    *(__nv_bfloat162*)ph = hh;
    *(__nv_bfloat162*)pl = ll;
}
__device__ __forceinline__ float hlval(const bf16* p, size_t plane, size_t i) {
    return __bfloat162float(p[i]) + __bfloat162float(p[plane + i]);
}

// ---------------- PTX helpers ----------------
__device__ __forceinline__ void mma16816(float* d, const uint32_t* a, uint32_t b0, uint32_t b1) {
    asm volatile(
        "mma.sync.aligned.m16n8k16.row.col.f32.bf16.bf16.f32 "
        "{%0,%1,%2,%3},{%4,%5,%6,%7},{%8,%9},{%0,%1,%2,%3};\n"
        : "+f"(d[0]), "+f"(d[1]), "+f"(d[2]), "+f"(d[3])
        : "r"(a[0]), "r"(a[1]), "r"(a[2]), "r"(a[3]), "r"(b0), "r"(b1));
}
__device__ __forceinline__ void ldsm4(uint32_t* r, uint32_t addr) {
    asm volatile("ldmatrix.sync.aligned.m8n8.x4.shared.b16 {%0,%1,%2,%3}, [%4];\n"
                 : "=r"(r[0]), "=r"(r[1]), "=r"(r[2]), "=r"(r[3]) : "r"(addr));
}
__device__ __forceinline__ void cp16(uint32_t dst, const void* src, bool pred) {
    int sz = pred ? 16 : 0;
    asm volatile("cp.async.cg.shared.global [%0], [%1], 16, %2;\n"
                 :: "r"(dst), "l"(src), "r"(sz) : "memory");
}
__device__ __forceinline__ void cp_commit() { asm volatile("cp.async.commit_group;\n" ::: "memory"); }
__device__ __forceinline__ void cp_wait1()  { asm volatile("cp.async.wait_group 1;\n" ::: "memory"); }

// ---------------- mma.sync GEMM 128x128 (single-barrier mainloop) ----------------
#define BK_STAGES 3
#define SMEM_BYTES (BK_STAGES*32768)

template<int EPI, int OUT>
__global__ void __launch_bounds__(256, 2)
bgemm(const bf16* __restrict__ Ah, const bf16* __restrict__ Al, int lda, long long sA,
      const bf16* __restrict__ Bh, const bf16* __restrict__ Bl, int ldb, long long sB,
      float* __restrict__ C, int ldc, long long sC,
      bf16* __restrict__ Ch, long long planeC, int ldch, long long sCh,
      const float* __restrict__ bias, long long sBias,
      const float* __restrict__ aux, int auxMod,
      int M, int N, int K)
{
    extern __shared__ char smd[];
    const int zi = blockIdx.z;
    Ah += (size_t)zi * sA; Al += (size_t)zi * sA;
    Bh += (size_t)zi * sB; Bl += (size_t)zi * sB;
    if (OUT != 2) C += (size_t)zi * sC;
    if (OUT != 0) Ch += (size_t)zi * sCh;
    const float* bp = bias ? (bias + (size_t)zi * sBias) : nullptr;

    const int bm = blockIdx.y * 128;
    const int bn = blockIdx.x * 128;
    const int tid = threadIdx.x, lane = tid & 31, warp = tid >> 5;
    const int wm = warp & 1, wn = warp >> 1;

    const uint32_t smem_base = (uint32_t)__cvta_generic_to_shared(smd);

    auto load_stage = [&](int s, int kt) {
        const int k0 = kt * 32;
        const uint32_t As = smem_base + s * 32768;
        const uint32_t Bs = As + 16384;
#pragma unroll
        for (int i = 0; i < 4; i++) {
            int lin = i * 256 + tid;
            int row = lin >> 3, ch = lin & 7;
            const bf16* srcA = ((ch & 4) ? Al : Ah) + (size_t)(bm + row) * lda + k0 + (ch & 3) * 8;
            cp16(As + row * 128 + ((ch ^ (row & 7)) * 16), srcA, true);
        }
#pragma unroll
        for (int i = 0; i < 4; i++) {
            int lin = i * 256 + tid;
            int row = lin >> 3, ch = lin & 7;
            bool ok = (bn + row) < N;
            const bf16* srcB = ((ch & 4) ? Bl : Bh) +
                               (ok ? ((size_t)(bn + row) * ldb + k0 + (ch & 3) * 8) : 0);
            cp16(Bs + row * 128 + ((ch ^ (row & 7)) * 16), srcB, ok);
        }
    };

    float acc[4][4][4];
#pragma unroll
    for (int i = 0; i < 4; i++)
#pragma unroll
        for (int j = 0; j < 4; j++)
#pragma unroll
            for (int q = 0; q < 4; q++) acc[i][j][q] = 0.0f;

    const int nk = K / 32;
    if (nk > 0) load_stage(0, 0);
    cp_commit();
    if (nk > 1) load_stage(1, 1);
    cp_commit();

    const int g  = lane >> 3;
    const int lr = lane & 7;
    const int aRow0 = wm * 64 + (g & 1) * 8 + lr;
    const int bRow0 = wn * 32 + (g & 1) * 8 + lr;
    const int chHi  = (g >> 1);

    for (int kt = 0; kt < nk; kt++) {
        cp_wait1();
        __syncthreads();
        if (kt + 2 < nk) load_stage((kt + 2) % BK_STAGES, kt + 2);
        cp_commit();

        const uint32_t As = smem_base + (kt % BK_STAGES) * 32768;
        const uint32_t Bs = As + 16384;

#pragma unroll
        for (int step = 0; step < 2; step++) {
            uint32_t ah[4][4], al[4][4], bh[2][4], bl[2][4];
            const int cH = ((step * 2 + chHi) ^ lr) * 16;
            const int cL = ((4 + step * 2 + chHi) ^ lr) * 16;
#pragma unroll
            for (int mt = 0; mt < 4; mt++) {
                uint32_t rb = As + (uint32_t)(aRow0 + mt * 16) * 128;
                ldsm4(ah[mt], rb + cH);
                ldsm4(al[mt], rb + cL);
            }
#pragma unroll
            for (int p = 0; p < 2; p++) {
                uint32_t rb = Bs + (uint32_t)(bRow0 + p * 16) * 128;
                ldsm4(bh[p], rb + cH);
                ldsm4(bl[p], rb + cL);
            }
#pragma unroll
            for (int nt = 0; nt < 4; nt++) {
                const int p = nt >> 1, o = nt & 1;
                const uint32_t b0h = bh[p][o], b1h = bh[p][o + 2];
                const uint32_t b0l = bl[p][o], b1l = bl[p][o + 2];
#pragma unroll
                for (int mt = 0; mt < 4; mt++) {
                    mma16816(acc[mt][nt], ah[mt], b0h, b1h);
                    mma16816(acc[mt][nt], ah[mt], b0l, b1l);
                    mma16816(acc[mt][nt], al[mt], b0h, b1h);
                }
            }
        }
    }

    const int r_ep = lane >> 2, c_ep = lane & 3;
#pragma unroll
    for (int mt = 0; mt < 4; mt++) {
        const int m0 = bm + wm * 64 + mt * 16 + r_ep;
#pragma unroll
        for (int nt = 0; nt < 4; nt++) {
            const int n0 = bn + wn * 32 + nt * 8 + 2 * c_ep;
#pragma unroll
            for (int half = 0; half < 2; half++) {
                const int m = m0 + half * 8;
                if (n0 < N) {
                    float v0 = acc[mt][nt][half * 2 + 0];
                    float v1 = acc[mt][nt][half * 2 + 1];
                    if (bp) { v0 += bp[n0]; v1 += bp[n0 + 1]; }
                    if (EPI == 1)      { v0 = geluf(v0);     v1 = geluf(v1); }
                    else if (EPI == 3) { v0 = softplusf(v0); v1 = softplusf(v1); }
                    else if (EPI == 4) {
                        const float* ar = aux + (size_t)(m % auxMod) * ldc;
                        v0 += ar[n0]; v1 += ar[n0 + 1];
                    } else if (EPI == 5) {
                        const float* ar = aux + (size_t)m * ldc;
                        v0 += ar[n0]; v1 += ar[n0 + 1];
                    }
                    if (OUT != 2) {
                        float2 f2; f2.x = v0; f2.y = v1;
                        *(float2*)(C + (size_t)m * ldc + n0) = f2;
                    }
                    if (OUT != 0) {
                        size_t o = (size_t)m * ldch + n0;
                        split2_store(Ch + o, Ch + planeC + o, v0, v1);
                    }
                }
            }
        }
    }
}

// ---------------- mma.sync GEMM 64x128 (small shapes, single-barrier) ----------------
#define SMEM64_BYTES (3*24576)

template<int EPI, int OUT>
__global__ void __launch_bounds__(256, 2)
bgemm64(const bf16* __restrict__ Ah, const bf16* __restrict__ Al, int lda, long long sA,
        const bf16* __restrict__ Bh, const bf16* __restrict__ Bl, int ldb, long long sB,
        float* __restrict__ C, int ldc, long long sC,
        bf16* __restrict__ Ch, long long planeC, int ldch, long long sCh,
        const float* __restrict__ bias, long long sBias,
        const float* __restrict__ aux, int auxMod,
        int M, int N, int K)
{
    extern __shared__ char smd[];
    const int zi = blockIdx.z;
    Ah += (size_t)zi * sA; Al += (size_t)zi * sA;
    Bh += (size_t)zi * sB; Bl += (size_t)zi * sB;
    if (OUT != 2) C += (size_t)zi * sC;
    if (OUT != 0) Ch += (size_t)zi * sCh;
    const float* bp = bias ? (bias + (size_t)zi * sBias) : nullptr;

    const int bm = blockIdx.y * 64;
    const int bn = blockIdx.x * 128;
    const int tid = threadIdx.x, lane = tid & 31, warp = tid >> 5;
    const int wm = warp & 1, wn = warp >> 1;

    const uint32_t smem_base = (uint32_t)__cvta_generic_to_shared(smd);

    auto load_stage = [&](int s, int kt) {
        const int k0 = kt * 32;
        const uint32_t As = smem_base + s * 24576;
        const uint32_t Bs = As + 8192;
#pragma unroll
        for (int i = 0; i < 2; i++) {
            int lin = i * 256 + tid;
            int row = lin >> 3, ch = lin & 7;
            const bf16* srcA = ((ch & 4) ? Al : Ah) + (size_t)(bm + row) * lda + k0 + (ch & 3) * 8;
            cp16(As + row * 128 + ((ch ^ (row & 7)) * 16), srcA, true);
        }
#pragma unroll
        for (int i = 0; i < 4; i++) {
            int lin = i * 256 + tid;
            int row = lin >> 3, ch = lin & 7;
            bool ok = (bn + row) < N;
            const bf16* srcB = ((ch & 4) ? Bl : Bh) +
                               (ok ? ((size_t)(bn + row) * ldb + k0 + (ch & 3) * 8) : 0);
            cp16(Bs + row * 128 + ((ch ^ (row & 7)) * 16), srcB, ok);
        }
    };

    float acc[2][4][4];
#pragma unroll
    for (int i = 0; i < 2; i++)
#pragma unroll
        for (int j = 0; j < 4; j++)
#pragma unroll
            for (int q = 0; q < 4; q++) acc[i][j][q] = 0.0f;

    const int nk = K / 32;
    if (nk > 0) load_stage(0, 0);
    cp_commit();
    if (nk > 1) load_stage(1, 1);
    cp_commit();

    const int g  = lane >> 3;
    const int lr = lane & 7;
    const int aRow0 = wm * 32 + (g & 1) * 8 + lr;
    const int bRow0 = wn * 32 + (g & 1) * 8 + lr;
    const int chHi  = (g >> 1);

    for (int kt = 0; kt < nk; kt++) {
        cp_wait1();
        __syncthreads();
        if (kt + 2 < nk) load_stage((kt + 2) % 3, kt + 2);
        cp_commit();

        const uint32_t As = smem_base + (kt % 3) * 24576;
        const uint32_t Bs = As + 8192;

#pragma unroll
        for (int step = 0; step < 2; step++) {
            uint32_t ah[2][4], al[2][4], bh[2][4], bl[2][4];
            const int cH = ((step * 2 + chHi) ^ lr) * 16;
            const int cL = ((4 + step * 2 + chHi) ^ lr) * 16;
#pragma unroll
            for (int mt = 0; mt < 2; mt++) {
                uint32_t rb = As + (uint32_t)(aRow0 + mt * 16) * 128;
                ldsm4(ah[mt], rb + cH);
                ldsm4(al[mt], rb + cL);
            }
#pragma unroll
            for (int p = 0; p < 2; p++) {
                uint32_t rb = Bs + (uint32_t)(bRow0 + p * 16) * 128;
                ldsm4(bh[p], rb + cH);
                ldsm4(bl[p], rb + cL);
            }
#pragma unroll
            for (int nt = 0; nt < 4; nt++) {
                const int p = nt >> 1, o = nt & 1;
                const uint32_t b0h = bh[p][o], b1h = bh[p][o + 2];
                const uint32_t b0l = bl[p][o], b1l = bl[p][o + 2];
#pragma unroll
                for (int mt = 0; mt < 2; mt++) {
                    mma16816(acc[mt][nt], ah[mt], b0h, b1h);
                    mma16816(acc[mt][nt], ah[mt], b0l, b1l);
                    mma16816(acc[mt][nt], al[mt], b0h, b1h);
                }
            }
        }
    }

    const int r_ep = lane >> 2, c_ep = lane & 3;
#pragma unroll
    for (int mt = 0; mt < 2; mt++) {
        const int m0 = bm + wm * 32 + mt * 16 + r_ep;
#pragma unroll
        for (int nt = 0; nt < 4; nt++) {
            const int n0 = bn + wn * 32 + nt * 8 + 2 * c_ep;
#pragma unroll
            for (int half = 0; half < 2; half++) {
                const int m = m0 + half * 8;
                if (n0 < N) {
                    float v0 = acc[mt][nt][half * 2 + 0];
                    float v1 = acc[mt][nt][half * 2 + 1];
                    if (bp) { v0 += bp[n0]; v1 += bp[n0 + 1]; }
                    if (EPI == 1)      { v0 = geluf(v0);     v1 = geluf(v1); }
                    else if (EPI == 3) { v0 = softplusf(v0); v1 = softplusf(v1); }
                    else if (EPI == 4) {
                        const float* ar = aux + (size_t)(m % auxMod) * ldc;
                        v0 += ar[n0]; v1 += ar[n0 + 1];
                    } else if (EPI == 5) {
                        const float* ar = aux + (size_t)m * ldc;
                        v0 += ar[n0]; v1 += ar[n0 + 1];
                    }
                    if (OUT != 2) {
                        float2 f2; f2.x = v0; f2.y = v1;
                        *(float2*)(C + (size_t)m * ldc + n0) = f2;
                    }
                    if (OUT != 0) {
                        size_t o = (size_t)m * ldch + n0;
                        split2_store(Ch + o, Ch + planeC + o, v0, v1);
                    }
                }
            }
        }
    }
}

// ---------------- fused prepass (vectorized contiguous segments) ----------------
#define PRE_BLOCKS 10432

__global__ void fused_pre_k(
    const float* __restrict__ pos_w1, const float* __restrict__ pos_b1,
    const float* __restrict__ pos_w2, const float* __restrict__ mix_w,
    const float* __restrict__ m_out_w, const float* __restrict__ m_in_w,
    const float* __restrict__ m_xproj_w, const float* __restrict__ m_dt_w,
    const float* __restrict__ ffn_w1, const float* __restrict__ ffn_w2,
    bf16* __restrict__ wpos2, bf16* __restrict__ wpmix, bf16* __restrict__ wmixA,
    bf16* __restrict__ wTout, bf16* __restrict__ win, bf16* __restrict__ wxp,
    bf16* __restrict__ wdt, bf16* __restrict__ wf1, bf16* __restrict__ wf2,
    bf16* __restrict__ posh)
{
    const int bid = blockIdx.x, tid = threadIdx.x;
    if (bid < 256) {
        int i = (bid * 256 + tid) * 4;
        float4 v = *(const float4*)&pos_w2[i];
        split4_store(wpos2 + i, wpos2 + 262144 + i, v);
    } else if (bid < 512) {
        int i = ((bid - 256) * 256 + tid) * 4;
        int r = i >> 9, c = i & 511;
        float4 v = *(const float4*)&mix_w[1024 + r * 1536 + c];
        split4_store(wpmix + i, wpmix + 262144 + i, v);
    } else if (bid < 768) {
        int i = ((bid - 512) * 256 + tid) * 4;
        int r = i >> 9, c = i & 511;
        float4 v = *(const float4*)&mix_w[r * 1536 + c];
        split4_store(wmixA + i, wmixA + 524288 + i, v);
    } else if (bid < 1024) {
        int i = ((bid - 768) * 256 + tid) * 4;
        int r = i >> 9, c = i & 511;
        float4 v = *(const float4*)&mix_w[512 + r * 1536 + c];
        split4_store(wmixA + 262144 + i, wmixA + 524288 + 262144 + i, v);
    } else if (bid < 3072) {
        int i = ((bid - 1024) * 256 + tid) * 4;
        float4 v = *(const float4*)&m_in_w[i];
        split4_store(win + i, win + 2097152 + i, v);
    } else if (bid < 3200) {
        int i = ((bid - 3072) * 256 + tid) * 4;
        float4 v = *(const float4*)&m_xproj_w[i];
        split4_store(wxp + i, wxp + 131072 + i, v);
    } else if (bid < 3264) {
        int i = ((bid - 3200) * 256 + tid) * 4;
        float4 v = *(const float4*)&m_dt_w[i];
        split4_store(wdt + i, wdt + 65536 + i, v);
    } else if (bid < 3776) {
        int i = ((bid - 3264) * 256 + tid) * 4;
        float4 v = *(const float4*)&ffn_w1[i];
        split4_store(wf1 + i, wf1 + 524288 + i, v);
    } else if (bid < 4288) {
        int i = ((bid - 3776) * 256 + tid) * 4;
        float4 v = *(const float4*)&ffn_w2[i];
        split4_store(wf2 + i, wf2 + 524288 + i, v);
    } else if (bid < 6336) {
        int i = (bid - 4288) * 256 + tid;
        int e = i >> 9, j = i & 511;
        bf16 h, l;
        splitf(m_out_w[(size_t)j * 1024 + e], h, l);
        wTout[i] = h; wTout[1048576 + i] = l;
    } else if (bid < 8384) {
        int i = (bid - 6336) * 256 + tid;
        int e = i >> 9, j = i & 511;
        bf16 h, l;
        splitf(m_out_w[524288 + (size_t)j * 1024 + e], h, l);
        wTout[524288 + i] = h; wTout[1048576 + 524288 + i] = l;
    } else {
        int i = (bid - 8384) * 256 + tid;
        int t = i >> 9, c = i & 511;
        int y = t >> 5, x = t & 31;
        const float PI = 3.14159265358979323846f;
        float yy = ((y + 0.5f) / 32.0f) * 2.0f - 1.0f;
        float xx = ((x + 0.5f) / 32.0f) * 2.0f - 1.0f;
        float f2 = sinf(PI * yy), f3 = cosf(PI * yy);
        float f4 = sinf(PI * xx), f5 = cosf(PI * xx);
        const float* w = pos_w1 + c * 6;
        float v = pos_b1[c] + yy * w[0] + xx * w[1] + f2 * w[2] + f3 * w[3] + f4 * w[4] + f5 * w[5];
        v = geluf(v);
        bf16 h, l; splitf(v, h, l);
        posh[i] = h; posh[524288 + i] = l;
    }
}

// ---------------- LN(tokens) + pos -> hi/lo ----------------
__global__ void ln_add_pos_k(const float* __restrict__ x,
                             const float* __restrict__ g, const float* __restrict__ b,
                             const float* __restrict__ pos, bf16* __restrict__ out)
{
    __shared__ float sh[16];
    const int row = blockIdx.x;
    const int tid = threadIdx.x;
    float4 v = ((const float4*)(x + (size_t)row * DIM))[tid];
    float s = v.x + v.y + v.z + v.w;
    float q = v.x * v.x + v.y * v.y + v.z * v.z + v.w * v.w;
#pragma unroll
    for (int o = 16; o; o >>= 1) {
        s += __shfl_xor_sync(0xffffffffu, s, o);
        q += __shfl_xor_sync(0xffffffffu, q, o);
    }
    if ((tid & 31) == 0) { sh[tid >> 5] = s; sh[4 + (tid >> 5)] = q; }
    __syncthreads();
    if (tid == 0) {
        float S = sh[0] + sh[1] + sh[2] + sh[3];
        float Q = sh[4] + sh[5] + sh[6] + sh[7];
        float mu = S * (1.0f / DIM);
        float var = Q * (1.0f / DIM) - mu * mu;
        sh[8] = mu; sh[9] = rsqrtf(var + 1e-5f);
    }
    __syncthreads();
    const float mu = sh[8], rs = sh[9];
    const int t = row & (LSEQ - 1);
    float4 g4 = ((const float4*)g)[tid];
    float4 b4 = ((const float4*)b)[tid];
    float4 p4 = ((const float4*)(pos + (size_t)t * DIM))[tid];
    float4 r;
    r.x = (v.x - mu) * rs * g4.x + b4.x + p4.x;
    r.y = (v.y - mu) * rs * g4.y + b4.y + p4.y;
    r.z = (v.z - mu) * rs * g4.z + b4.z + p4.z;
    r.w = (v.w - mu) * rs * g4.w + b4.w + p4.w;
    bf16* ph = out + (size_t)row * DIM + tid * 4;
    split4_store(ph, ph + (long long)ROWS * DIM, r);
}

// ---------------- causal conv + SiLU (4 t per thread, 7-row register window) ----------------
// grid: 2 * (ROWS/4) * 256 threads total; one thread = 4 channels x 4 consecutive t.
__global__ void conv_silu_k(const float* __restrict__ xz,
                            const float* __restrict__ cw, const float* __restrict__ cb,
                            bf16* __restrict__ xch)
{
    size_t gidx = (size_t)blockIdx.x * 256 + threadIdx.x;   // [0, 2*2048*256)
    int dq   = (int)(gidx & 255);
    int tg   = (int)((gidx >> 8) & (ROWS / 4 - 1));   // global t-group (b*256 + tg_in)
    int dir  = (int)(gidx >> 19);
    int d = dq * 4;
    int b = tg >> 8;
    int t0 = (tg & 255) * 4;

    float4 bias4 = *(const float4*)&cb[dir * DI + d];
    const float4* wrow = (const float4*)&cw[(size_t)(dir * DI + d) * 4];
    float4 w0 = wrow[0], w1 = wrow[1], w2 = wrow[2], w3 = wrow[3];

    // window of 7 rows: dir==0 -> t0-3..t0+3 ; dir==1 -> t0..t0+6
    const int base = dir ? t0 : t0 - 3;
    float4 v[7];
#pragma unroll
    for (int i = 0; i < 7; i++) {
        int tt = base + i;
        if (tt >= 0 && tt < LSEQ)
            v[i] = *(const float4*)&xz[((size_t)(b * LSEQ + tt)) * 4096 + dir * 2048 + d];
        else
            v[i] = make_float4(0.f, 0.f, 0.f, 0.f);
    }

#pragma unroll
    for (int j = 0; j < 4; j++) {
        float4 acc = bias4;
#pragma unroll
        for (int k = 0; k < 4; k++) {
            // dir==0: tap tt = t-3+k -> window index j+k ; dir==1: tt = t+3-k -> j+3-k
            int vi = dir ? (j + 3 - k) : (j + k);
            float4 x4 = v[vi];
            acc.x = fmaf(fcomp(w0, k), x4.x, acc.x);
            acc.y = fmaf(fcomp(w1, k), x4.y, acc.y);
            acc.z = fmaf(fcomp(w2, k), x4.z, acc.z);
            acc.w = fmaf(fcomp(w3, k), x4.w, acc.w);
        }
        float4 r;
        r.x = siluf(acc.x); r.y = siluf(acc.y); r.z = siluf(acc.z); r.w = siluf(acc.w);
        bf16* ph = xch + ((size_t)dir * ROWS + (size_t)b * LSEQ + t0 + j) * DI + d;
        split4_store(ph, ph + XPLANE, r);
    }
}

// ================= chunked selective scan (unrolled load batching) =================
__global__ void scan_part1_k(const float* __restrict__ dsp, const bf16* __restrict__ xch,
                             const float* __restrict__ proj, const float* __restrict__ A_log,
                             float* __restrict__ hend, float* __restrict__ prodv)
{
    const int chunk = blockIdx.x >> 3;
    const int dblk  = blockIdx.x & 7;
    const int b = blockIdx.y, dir = blockIdx.z;
    const int d = dblk * 128 + threadIdx.x;

    float a[DS];
    bool fast = true;
#pragma unroll
    for (int s = 0; s < DS; s++) {
        a[s] = -expf(A_log[((size_t)dir * DI + d) * DS + s]);
        fast = fast && (fabsf(a[s] + (float)(s + 1)) < 1e-4f * (float)(s + 1));
    }

    const size_t base_row = (size_t)dir * ROWS + (size_t)b * LSEQ;
    __shared__ float sB[CLEN][DS];
    for (int i = threadIdx.x; i < CLEN * DS; i += 128) {
        int st = chunk * CLEN + (i >> 4);
        int c = i & 15;
        int r = dir ? (LSEQ - 1 - st) : st;
        sB[i >> 4][c] = proj[(base_row + r) * 64 + 32 + c];
    }
    __syncthreads();

    float h[DS], p[DS];
#pragma unroll
    for (int s = 0; s < DS; s++) h[s] = 0.0f;

    if (fast) {
        float prodE1 = 1.0f;
#pragma unroll 4
        for (int i = 0; i < CLEN; i++) {
            int st = chunk * CLEN + i;
            int r = dir ? (LSEQ - 1 - st) : st;
            size_t ro = (base_row + r) * (size_t)DI + d;
            float delta = dsp[ro];
            float x     = hlval(xch, XPLANE, ro);
            float dx    = delta * x;
            float e1 = __expf(-delta);
            prodE1 *= e1;
            float ep = e1;
#pragma unroll
            for (int s = 0; s < DS; s++) {
                h[s] = fmaf(h[s], ep, dx * sB[i][s]);
                ep *= e1;
            }
        }
        float ep = prodE1;
#pragma unroll
        for (int s = 0; s < DS; s++) { p[s] = ep; ep *= prodE1; }
    } else {
#pragma unroll
        for (int s = 0; s < DS; s++) p[s] = 1.0f;
#pragma unroll 4
        for (int i = 0; i < CLEN; i++) {
            int st = chunk * CLEN + i;
            int r = dir ? (LSEQ - 1 - st) : st;
            size_t ro = (base_row + r) * (size_t)DI + d;
            float delta = dsp[ro];
            float x     = hlval(xch, XPLANE, ro);
            float dx    = delta * x;
#pragma unroll
            for (int s = 0; s < DS; s++) {
                float e = __expf(delta * a[s]);
                h[s] = fmaf(h[s], e, dx * sB[i][s]);
                p[s] *= e;
            }
        }
    }

    const int CH = (dir * BATCH + b) * DI + d;
    size_t o = ((size_t)chunk * NCH + CH) * DS;
#pragma unroll
    for (int s = 0; s < DS; s++) { hend[o + s] = h[s]; prodv[o + s] = p[s]; }
}

__global__ void scan_part2_k(const float* __restrict__ hend, const float* __restrict__ prodv,
                             float* __restrict__ hinit)
{
    int idx = blockIdx.x * 256 + threadIdx.x;
    if (idx >= NCH * DS) return;
    float H = 0.0f;
#pragma unroll 4
    for (int c = 0; c < NCHUNK; c++) {
        size_t o = (size_t)c * (NCH * DS) + idx;
        hinit[o] = H;
        H = fmaf(prodv[o], H, hend[o]);
    }
}

__global__ void scan_part3_k(const float* __restrict__ dsp, const bf16* __restrict__ xch,
                             const float* __restrict__ proj, const float* __restrict__ xz,
                             const float* __restrict__ A_log, const float* __restrict__ Dp,
                             const float* __restrict__ hinit, bf16* __restrict__ ycat)
{
    const int chunk = blockIdx.x >> 3;
    const int dblk  = blockIdx.x & 7;
    const int b = blockIdx.y, dir = blockIdx.z;
    const int d = dblk * 128 + threadIdx.x;

    float a[DS];
    bool fast = true;
#pragma unroll
    for (int s = 0; s < DS; s++) {
        a[s] = -expf(A_log[((size_t)dir * DI + d) * DS + s]);
        fast = fast && (fabsf(a[s] + (float)(s + 1)) < 1e-4f * (float)(s + 1));
    }
    const float Dv = Dp[dir * DI + d];

    const size_t base_row = (size_t)dir * ROWS + (size_t)b * LSEQ;
    const long long plane = (long long)ROWS * 2048;
    __shared__ float sBC[CLEN][32];
    for (int i = threadIdx.x; i < CLEN * 32; i += 128) {
        int st = chunk * CLEN + (i >> 5);
        int c = i & 31;
        int r = dir ? (LSEQ - 1 - st) : st;
        sBC[i >> 5][c] = proj[(base_row + r) * 64 + 32 + c];
    }
    __syncthreads();

    const int CH = (dir * BATCH + b) * DI + d;
    size_t ho = ((size_t)chunk * NCH + CH) * DS;
    float h[DS];
#pragma unroll
    for (int s = 0; s < DS; s++) h[s] = hinit[ho + s];

    if (fast) {
#pragma unroll 4
        for (int i = 0; i < CLEN; i++) {
            int st = chunk * CLEN + i;
            int r = dir ? (LSEQ - 1 - st) : st;
            size_t ro = (base_row + r) * (size_t)DI + d;
            float delta = dsp[ro];
            float x     = hlval(xch, XPLANE, ro);
            float dx    = delta * x;
            float y = 0.0f;
            float e1 = __expf(-delta);
            float ep = e1;
#pragma unroll
            for (int s = 0; s < DS; s++) {
                h[s] = fmaf(h[s], ep, dx * sBC[i][s]);
                y = fmaf(h[s], sBC[i][16 + s], y);
                ep *= e1;
            }
            float z = xz[((size_t)(b * LSEQ + r)) * 4096 + dir * 2048 + DI + d];
            float outv = (y + x * Dv) * siluf(z);
            bf16 hh, ll; splitf(outv, hh, ll);
            size_t oo = ((size_t)(b * LSEQ + r)) * 2048 + dir * DI + d;
            ycat[oo] = hh; ycat[plane + oo] = ll;
        }
    } else {
#pragma unroll 4
        for (int i = 0; i < CLEN; i++) {
            int st = chunk * CLEN + i;
            int r = dir ? (LSEQ - 1 - st) : st;
            size_t ro = (base_row + r) * (size_t)DI + d;
            float delta = dsp[ro];
            float x     = hlval(xch, XPLANE, ro);
            float dx    = delta * x;
            float y = 0.0f;
#pragma unroll
            for (int s = 0; s < DS; s++) {
                float e = __expf(delta * a[s]);
                h[s] = fmaf(h[s], e, dx * sBC[i][s]);
                y = fmaf(h[s], sBC[i][16 + s], y);
            }
            float z = xz[((size_t)(b * LSEQ + r)) * 4096 + dir * 2048 + DI + d];
            float outv = (y + x * Dv) * siluf(z);
            bf16 hh, ll; splitf(outv, hh, ll);
            size_t oo = ((size_t)(b * LSEQ + r)) * 2048 + dir * DI + d;
            ycat[oo] = hh; ycat[plane + oo] = ll;
        }
    }
}

// ---------------- dual LayerNorm ----------------
__global__ void ln_dual_k(const float* __restrict__ in,
                          const float* __restrict__ g1, const float* __restrict__ b1,
                          const float* __restrict__ g2, const float* __restrict__ b2,
                          float* __restrict__ out1, bf16* __restrict__ out2)
{
    __shared__ float sh[16];
    const int row = blockIdx.x;
    const int tid = threadIdx.x;
    float4 v = ((const float4*)(in + (size_t)row * DIM))[tid];
    float s = v.x + v.y + v.z + v.w;
    float q = v.x * v.x + v.y * v.y + v.z * v.z + v.w * v.w;
#pragma unroll
    for (int o = 16; o; o >>= 1) {
        s += __shfl_xor_sync(0xffffffffu, s, o);
        q += __shfl_xor_sync(0xffffffffu, q, o);
    }
    if ((tid & 31) == 0) { sh[tid >> 5] = s; sh[4 + (tid >> 5)] = q; }
    __syncthreads();
    if (tid == 0) {
        float S = sh[0] + sh[1] + sh[2] + sh[3];
        float Q = sh[4] + sh[5] + sh[6] + sh[7];
        float mu = S * (1.0f / DIM);
        float var = Q * (1.0f / DIM) - mu * mu;
        sh[8] = mu; sh[9] = rsqrtf(var + 1e-5f);
    }
    __syncthreads();
    float mu = sh[8], rs = sh[9];
    float4 g4 = ((const float4*)g1)[tid];
    float4 b4 = ((const float4*)b1)[tid];
    float4 x4;
    x4.x = (v.x - mu) * rs * g4.x + b4.x;
    x4.y = (v.y - mu) * rs * g4.y + b4.y;
    x4.z = (v.z - mu) * rs * g4.z + b4.z;
    x4.w = (v.w - mu) * rs * g4.w + b4.w;
    ((float4*)(out1 + (size_t)row * DIM))[tid] = x4;

    __syncthreads();
    s = x4.x + x4.y + x4.z + x4.w;
    q = x4.x * x4.x + x4.y * x4.y + x4.z * x4.z + x4.w * x4.w;
#pragma unroll
    for (int o = 16; o; o >>= 1) {
        s += __shfl_xor_sync(0xffffffffu, s, o);
        q += __shfl_xor_sync(0xffffffffu, q, o);
    }
    if ((tid & 31) == 0) { sh[tid >> 5] = s; sh[4 + (tid >> 5)] = q; }
    __syncthreads();
    if (tid == 0) {
        float S = sh[0] + sh[1] + sh[2] + sh[3];
        float Q = sh[4] + sh[5] + sh[6] + sh[7];
        float mu2 = S * (1.0f / DIM);
        float var2 = Q * (1.0f / DIM) - mu2 * mu2;
        sh[8] = mu2; sh[9] = rsqrtf(var2 + 1e-5f);
    }
    __syncthreads();
    float mu2 = sh[8], rs2 = sh[9];
    float4 G = ((const float4*)g2)[tid];
    float4 B = ((const float4*)b2)[tid];
    float4 r;
    r.x = (x4.x - mu2) * rs2 * G.x + B.x;
    r.y = (x4.y - mu2) * rs2 * G.y + B.y;
    r.z = (x4.z - mu2) * rs2 * G.z + B.z;
    r.w = (x4.w - mu2) * rs2 * G.w + B.w;
    bf16* ph = out2 + (size_t)row * DIM + tid * 4;
    split4_store(ph, ph + (long long)ROWS * DIM, r);
}

// ---------------- host launcher ----------------
extern "C" void kernel_launch(void* const* d_in, const int* in_sizes, int n_in,
                              void* d_out, int out_size)
{
    const float* tokens    = (const float*)d_in[0];
    const float* in_g      = (const float*)d_in[3];
    const float* in_b      = (const float*)d_in[4];
    const float* pos_w1    = (const float*)d_in[5];
    const float* pos_b1    = (const float*)d_in[6];
    const float* pos_w2    = (const float*)d_in[7];
    const float* pos_b2    = (const float*)d_in[8];
    const float* m_in_w    = (const float*)d_in[9];
    const float* m_conv_w  = (const float*)d_in[10];
    const float* m_conv_b  = (const float*)d_in[11];
    const float* m_xproj_w = (const float*)d_in[12];
    const float* m_dt_w    = (const float*)d_in[13];
    const float* m_dt_b    = (const float*)d_in[14];
    const float* m_A_log   = (const float*)d_in[15];
    const float* m_D       = (const float*)d_in[16];
    const float* m_out_w   = (const float*)d_in[17];
    const float* mix_w     = (const float*)d_in[18];
    const float* mix_b     = (const float*)d_in[19];
    const float* dn_g      = (const float*)d_in[20];
    const float* dn_b      = (const float*)d_in[21];
    const float* fn_g      = (const float*)d_in[22];
    const float* fn_b      = (const float*)d_in[23];
    const float* ffn_w1    = (const float*)d_in[24];
    const float* ffn_b1    = (const float*)d_in[25];
    const float* ffn_w2    = (const float*)d_in[26];
    const float* ffn_b2    = (const float*)d_in[27];
    float* out = (float*)d_out;

    float *pos, *pos_mix, *xz, *proj, *dsp, *dmix, *dln, *hend, *prodv, *hinit;
    bf16 *sin_hl, *posh_hl, *pos_hl, *wpos2, *wpmix, *wmixA, *wTout, *win, *wxp, *wdt, *wf1, *wf2;
    bf16 *xc_hl, *proj_hl, *ycat_hl, *wc_hl, *lnf_hl, *h1_hl;
    cudaGetSymbolAddress((void**)&pos,     g_pos);
    cudaGetSymbolAddress((void**)&pos_mix, g_pos_mix);
    cudaGetSymbolAddress((void**)&xz,      g_xz);
    cudaGetSymbolAddress((void**)&proj,    g_proj);
    cudaGetSymbolAddress((void**)&dsp,     g_dsp);
    cudaGetSymbolAddress((void**)&dmix,    g_dmix);
    cudaGetSymbolAddress((void**)&dln,     g_dln);
    cudaGetSymbolAddress((void**)&hend,    g_hend);
    cudaGetSymbolAddress((void**)&prodv,   g_prod);
    cudaGetSymbolAddress((void**)&hinit,   g_hinit);
    cudaGetSymbolAddress((void**)&sin_hl,  hl_scan_in);
    cudaGetSymbolAddress((void**)&posh_hl, hl_pos_h);
    cudaGetSymbolAddress((void**)&pos_hl,  hl_pos);
    cudaGetSymbolAddress((void**)&wpos2,   hl_w_pos2);
    cudaGetSymbolAddress((void**)&wpmix,   hl_w_pmix);
    cudaGetSymbolAddress((void**)&wmixA,   hl_w_mixA);
    cudaGetSymbolAddress((void**)&wTout,   hl_wT_out);
    cudaGetSymbolAddress((void**)&win,     hl_w_in);
    cudaGetSymbolAddress((void**)&wxp,     hl_w_xp);
    cudaGetSymbolAddress((void**)&wdt,     hl_w_dt);
    cudaGetSymbolAddress((void**)&wf1,     hl_w_f1);
    cudaGetSymbolAddress((void**)&wf2,     hl_w_f2);
    cudaGetSymbolAddress((void**)&xc_hl,   hl_xc);
    cudaGetSymbolAddress((void**)&proj_hl, hl_proj);
    cudaGetSymbolAddress((void**)&ycat_hl, hl_ycat);
    cudaGetSymbolAddress((void**)&wc_hl,   hl_wc);
    cudaGetSymbolAddress((void**)&lnf_hl,  hl_lnf);
    cudaGetSymbolAddress((void**)&h1_hl,   hl_h1);

    cudaFuncSetAttribute(bgemm<0,0>, cudaFuncAttributeMaxDynamicSharedMemorySize, SMEM_BYTES);
    cudaFuncSetAttribute(bgemm<4,0>, cudaFuncAttributeMaxDynamicSharedMemorySize, SMEM_BYTES);
    cudaFuncSetAttribute(bgemm<1,2>, cudaFuncAttributeMaxDynamicSharedMemorySize, SMEM_BYTES);
    cudaFuncSetAttribute(bgemm<5,0>, cudaFuncAttributeMaxDynamicSharedMemorySize, SMEM_BYTES);
    cudaFuncSetAttribute(bgemm64<0,0>, cudaFuncAttributeMaxDynamicSharedMemorySize, SMEM64_BYTES);
    cudaFuncSetAttribute(bgemm64<0,1>, cudaFuncAttributeMaxDynamicSharedMemorySize, SMEM64_BYTES);
    cudaFuncSetAttribute(bgemm64<0,2>, cudaFuncAttributeMaxDynamicSharedMemorySize, SMEM64_BYTES);
    cudaFuncSetAttribute(bgemm64<3,0>, cudaFuncAttributeMaxDynamicSharedMemorySize, SMEM64_BYTES);

    // 1: fused converts + pos_hidden
    fused_pre_k<<<PRE_BLOCKS, 256>>>(pos_w1, pos_b1, pos_w2, mix_w, m_out_w, m_in_w,
                                     m_xproj_w, m_dt_w, ffn_w1, ffn_w2,
                                     wpos2, wpmix, wmixA, wTout, win, wxp, wdt, wf1, wf2,
                                     posh_hl);
    // 2: pos = gelu_h @ pos_w2^T + b2
    bgemm64<0,1><<<dim3(4,16,1), 256, SMEM64_BYTES>>>(
        posh_hl, posh_hl + LSEQ*DIM, 512, 0,  wpos2, wpos2 + 512*512, 512, 0,
        pos, 512, 0,  pos_hl, (long long)LSEQ*DIM, 512, 0,
        pos_b2, 0, nullptr, 1, LSEQ, 512, 512);
    // 3: scan_in = LN(tokens) + pos
    ln_add_pos_k<<<ROWS, 128>>>(tokens, in_g, in_b, pos, sin_hl);
    // 4: xz = scan_in @ in_w^T (fp32 out)  <-- profiled slot
    bgemm<0,0><<<dim3(32,64,1), 256, SMEM_BYTES>>>(
        sin_hl, sin_hl + (long long)ROWS*DIM, 512, 0,
        win, win + (long long)4096*512, 512, 0,
        xz, 4096, 0, nullptr, 0, 0, 0,
        nullptr, 0, nullptr, 1, ROWS, 4096, 512);

    conv_silu_k<<<(2*(ROWS/4)*256)/256, 256>>>(xz, m_conv_w, m_conv_b, xc_hl);
    // proj = xc @ xproj^T per dir
    bgemm64<0,1><<<dim3(1,128,2), 256, SMEM64_BYTES>>>(
        xc_hl, xc_hl + (long long)2*ROWS*DI, 1024, (long long)ROWS*DI,
        wxp, wxp + (long long)128*1024, 1024, (long long)64*1024,
        proj, 64, (long long)ROWS*64,
        proj_hl, (long long)2*ROWS*64, 64, (long long)ROWS*64,
        nullptr, 0, nullptr, 1, ROWS, 64, 1024);
    // dsp = softplus(dt @ dt_w^T + dt_b) (fp32 out)
    bgemm64<3,0><<<dim3(8,128,2), 256, SMEM64_BYTES>>>(
        proj_hl, proj_hl + (long long)2*ROWS*64, 64, (long long)ROWS*64,
        wdt, wdt + (long long)2048*32, 32, (long long)1024*32,
        dsp, 1024, (long long)ROWS*DI, nullptr, 0, 0, 0,
        m_dt_b, 1024, nullptr, 1, ROWS, 1024, 32);

    // chunked scan
    scan_part1_k<<<dim3(8*NCHUNK, BATCH, 2), 128>>>(dsp, xc_hl, proj, m_A_log, hend, prodv);
    scan_part2_k<<<(NCH*DS)/256, 256>>>(hend, prodv, hinit);
    scan_part3_k<<<dim3(8*NCHUNK, BATCH, 2), 128>>>(dsp, xc_hl, proj, xz, m_A_log, m_D, hinit, ycat_hl);

    // pos_mix = pos @ mix_w[:,1024:1536]^T + mix_b
    bgemm64<0,0><<<dim3(4,16,1), 256, SMEM64_BYTES>>>(
        pos_hl, pos_hl + LSEQ*DIM, 512, 0,  wpmix, wpmix + 512*512, 512, 0,
        pos_mix, 512, 0,  nullptr, 0, 0, 0,
        mix_b, 0, nullptr, 1, LSEQ, 512, 512);
    // Wc[dir] = mix_w_slice @ out_w[dir]
    bgemm64<0,2><<<dim3(8,8,2), 256, SMEM64_BYTES>>>(
        wmixA, wmixA + (long long)2*512*512, 512, (long long)512*512,
        wTout, wTout + (long long)2*1024*512, 512, (long long)1024*512,
        nullptr, 0, 0,
        wc_hl, (long long)512*2048, 2048, 1024,
        nullptr, 0, nullptr, 1, 512, 1024, 512);
    // dmix = ycat @ Wc^T + pos_mix
    bgemm<4,0><<<dim3(4,64,1), 256, SMEM_BYTES>>>(
        ycat_hl, ycat_hl + (long long)ROWS*2048, 2048, 0,
        wc_hl, wc_hl + (long long)512*2048, 2048, 0,
        dmix, 512, 0, nullptr, 0, 0, 0,
        nullptr, 0, pos_mix, LSEQ, ROWS, 512, 2048);
    ln_dual_k<<<ROWS, 128>>>(dmix, dn_g, dn_b, fn_g, fn_b, dln, lnf_hl);
    bgemm<1,2><<<dim3(8,64,1), 256, SMEM_BYTES>>>(
        lnf_hl, lnf_hl + (long long)ROWS*DIM, 512, 0,
        wf1, wf1 + (long long)1024*512, 512, 0,
        nullptr, 1024, 0,
        h1_hl, (long long)ROWS*HID, 1024, 0,
        ffn_b1, 0, nullptr, 1, ROWS, 1024, 512);
    bgemm<5,0><<<dim3(4,64,1), 256, SMEM_BYTES>>>(
        h1_hl, h1_hl + (long long)ROWS*HID, 1024, 0,
        wf2, wf2 + (long long)512*1024, 1024, 0,
        out, 512, 0, nullptr, 0, 0, 0,
        ffn_b2, 0, dln, 1, ROWS, 512, 1024);

    (void)in_sizes; (void)n_in; (void)out_size;
}